// round 2
// baseline (speedup 1.0000x reference)
#include <cuda_runtime.h>
#include <cuda_bf16.h>
#include <math.h>

// Problem constants
#define B 2
#define N_SEQ 4096
#define DIM 1024
#define HEADS 16
#define DHEAD 64
#define M_ROWS (B * N_SEQ)        // 8192
#define QKV_COLS (3 * DIM)        // 3072

// Scratch (device globals; no dynamic allocation allowed)
__device__ float g_qkv[M_ROWS * QKV_COLS];            // [8192][3072]
__device__ float g_ctxp[8 * 32 * DHEAD * DHEAD];      // [chunk][bh][64][64]
__device__ float g_Sp[8 * 32 * DHEAD];                // [chunk][bh][64]
__device__ float g_ctx[32 * DHEAD * DHEAD];           // [bh][64][64] normalized
__device__ float g_M[B * DIM * DIM];                  // [b][1024][1024]

// ---------------------------------------------------------------------------
// Generic SGEMM: C[M,N] = A[M,K] @ B[K,N], all row-major, strided, batched.
// BM=BN=128, BK=16, 256 threads, 8x8 per thread.
// Grid: (N/128, M/128, batches). All dims divide evenly for our shapes.
// ---------------------------------------------------------------------------
#define BM 128
#define BN 128
#define BK 16
#define TM 8
#define TN 8

__global__ __launch_bounds__(256, 2)
void sgemm_kernel(const float* __restrict__ A, const float* __restrict__ Bm,
                  float* __restrict__ C, int K,
                  int lda, int ldb, int ldc,
                  long aBatch, long bBatch, long cBatch)
{
    A  += (long)blockIdx.z * aBatch;
    Bm += (long)blockIdx.z * bBatch;
    C  += (long)blockIdx.z * cBatch;

    __shared__ float As[BK][BM + 4];   // transposed A tile (As[k][m]), padded
    __shared__ float Bs[BK][BN];

    const int tid = threadIdx.x;
    const int bm = blockIdx.y * BM;
    const int bn = blockIdx.x * BN;

    // A tile load mapping: 128 rows x 4 float4 per row = 512 float4, 2/thread
    const int arow = tid >> 2;          // 0..63
    const int acol4 = tid & 3;          // float4 index within BK=16
    // B tile load mapping: 16 rows x 32 float4 per row = 512 float4, 2/thread
    const int brow = tid >> 5;          // 0..7
    const int bcol4 = tid & 31;

    const int ty = tid >> 4;            // 0..15
    const int tx = tid & 15;            // 0..15

    float acc[TM][TN];
    #pragma unroll
    for (int i = 0; i < TM; i++)
        #pragma unroll
        for (int j = 0; j < TN; j++) acc[i][j] = 0.f;

    for (int k0 = 0; k0 < K; k0 += BK) {
        // Load A tile (transposed into SMEM)
        #pragma unroll
        for (int i = 0; i < 2; ++i) {
            int r = arow + i * 64;
            float4 a = *(const float4*)&A[(long)(bm + r) * lda + k0 + acol4 * 4];
            As[acol4 * 4 + 0][r] = a.x;
            As[acol4 * 4 + 1][r] = a.y;
            As[acol4 * 4 + 2][r] = a.z;
            As[acol4 * 4 + 3][r] = a.w;
        }
        // Load B tile
        #pragma unroll
        for (int i = 0; i < 2; ++i) {
            int r = brow + i * 8;
            *(float4*)&Bs[r][bcol4 * 4] =
                *(const float4*)&Bm[(long)(k0 + r) * ldb + bn + bcol4 * 4];
        }
        __syncthreads();

        #pragma unroll
        for (int kk = 0; kk < BK; ++kk) {
            float ar[TM], br[TN];
            *(float4*)&ar[0] = *(const float4*)&As[kk][ty * TM];
            *(float4*)&ar[4] = *(const float4*)&As[kk][ty * TM + 4];
            *(float4*)&br[0] = *(const float4*)&Bs[kk][tx * TN];
            *(float4*)&br[4] = *(const float4*)&Bs[kk][tx * TN + 4];
            #pragma unroll
            for (int i = 0; i < TM; i++)
                #pragma unroll
                for (int j = 0; j < TN; j++)
                    acc[i][j] += ar[i] * br[j];
        }
        __syncthreads();
    }

    #pragma unroll
    for (int i = 0; i < TM; i++) {
        #pragma unroll
        for (int j = 0; j < TN; j += 4) {
            float4 v = make_float4(acc[i][j], acc[i][j+1], acc[i][j+2], acc[i][j+3]);
            *(float4*)&C[(long)(bm + ty * TM + i) * ldc + bn + tx * TN + j] = v;
        }
    }
}

// ---------------------------------------------------------------------------
// q softmax over d=64 per (m, h), times scale, in place inside g_qkv cols [0,1024)
// One warp per (m,h). grid 16384 x 256 threads (8 warps)
// ---------------------------------------------------------------------------
__global__ void q_softmax_kernel()
{
    int gw = (blockIdx.x * blockDim.x + threadIdx.x) >> 5;
    int lane = threadIdx.x & 31;
    int m = gw >> 4;
    int h = gw & 15;
    float* p = g_qkv + (long)m * QKV_COLS + h * DHEAD;
    float v0 = p[lane];
    float v1 = p[lane + 32];
    float mx = fmaxf(v0, v1);
    #pragma unroll
    for (int o = 16; o > 0; o >>= 1) mx = fmaxf(mx, __shfl_xor_sync(0xFFFFFFFFu, mx, o));
    float e0 = expf(v0 - mx);
    float e1 = expf(v1 - mx);
    float s = e0 + e1;
    #pragma unroll
    for (int o = 16; o > 0; o >>= 1) s += __shfl_xor_sync(0xFFFFFFFFu, s, o);
    float inv = 0.125f / s;   // scale = 64^-0.5 = 0.125
    p[lane] = e0 * inv;
    p[lane + 32] = e1 * inv;
}

// ---------------------------------------------------------------------------
// Partial context: for chunk c (512 seq positions), bh in [0,32):
//   ctxp[d][e] += exp(k[n,d]) * v[n,e];  Sp[d] += exp(k[n,d])
// grid (8 chunks, 32 bh), 256 threads.
// ---------------------------------------------------------------------------
__global__ __launch_bounds__(256, 4)
void ctx_partial_kernel()
{
    const int chunk = blockIdx.x;
    const int bh = blockIdx.y;
    const int b = bh >> 4;
    const int h = bh & 15;

    __shared__ float ek[32][DHEAD];
    __shared__ float sv[32][DHEAD];

    const int tid = threadIdx.x;
    const int d0 = (tid >> 4) * 4;
    const int e0 = (tid & 15) * 4;

    float acc[4][4];
    #pragma unroll
    for (int i = 0; i < 4; i++)
        #pragma unroll
        for (int j = 0; j < 4; j++) acc[i][j] = 0.f;
    float ssum = 0.f;

    const long rowbase = (long)b * N_SEQ;
    const int kcol = DIM + h * DHEAD;
    const int vcol = 2 * DIM + h * DHEAD;

    for (int t = 0; t < 16; ++t) {          // 16 tiles of 32 rows = 512
        int n_base = chunk * 512 + t * 32;
        // load 32x64 tiles: 512 float4, 2 per thread
        #pragma unroll
        for (int i = 0; i < 2; ++i) {
            int idx = tid + i * 256;
            int r = idx >> 4;                // 0..31
            int c4 = idx & 15;
            long m = rowbase + n_base + r;
            float4 kv = *(const float4*)&g_qkv[m * QKV_COLS + kcol + c4 * 4];
            ek[r][c4*4+0] = __expf(kv.x);
            ek[r][c4*4+1] = __expf(kv.y);
            ek[r][c4*4+2] = __expf(kv.z);
            ek[r][c4*4+3] = __expf(kv.w);
            *(float4*)&sv[r][c4*4] = *(const float4*)&g_qkv[m * QKV_COLS + vcol + c4 * 4];
        }
        __syncthreads();

        if (tid < 64) {
            #pragma unroll
            for (int kk = 0; kk < 32; ++kk) ssum += ek[kk][tid];
        }
        #pragma unroll
        for (int kk = 0; kk < 32; ++kk) {
            float ar[4], br[4];
            *(float4*)ar = *(const float4*)&ek[kk][d0];
            *(float4*)br = *(const float4*)&sv[kk][e0];
            #pragma unroll
            for (int i = 0; i < 4; i++)
                #pragma unroll
                for (int j = 0; j < 4; j++)
                    acc[i][j] += ar[i] * br[j];
        }
        __syncthreads();
    }

    float* outp = g_ctxp + ((long)chunk * 32 + bh) * (DHEAD * DHEAD);
    #pragma unroll
    for (int i = 0; i < 4; i++) {
        float4 v = make_float4(acc[i][0], acc[i][1], acc[i][2], acc[i][3]);
        *(float4*)&outp[(d0 + i) * DHEAD + e0] = v;
    }
    if (tid < 64) g_Sp[(chunk * 32 + bh) * DHEAD + tid] = ssum;
}

// ---------------------------------------------------------------------------
// Reduce partials over 8 chunks and normalize by S[d]. grid 32, 256 threads.
// ---------------------------------------------------------------------------
__global__ void ctx_reduce_kernel()
{
    const int bh = blockIdx.x;
    const int tid = threadIdx.x;
    __shared__ float sS[DHEAD];
    if (tid < 64) {
        float s = 0.f;
        #pragma unroll
        for (int c = 0; c < 8; ++c) s += g_Sp[(c * 32 + bh) * DHEAD + tid];
        sS[tid] = 1.f / s;
    }
    __syncthreads();
    for (int i = tid; i < DHEAD * DHEAD; i += 256) {
        float v = 0.f;
        #pragma unroll
        for (int c = 0; c < 8; ++c) v += g_ctxp[((long)c * 32 + bh) * (DHEAD*DHEAD) + i];
        g_ctx[bh * (DHEAD*DHEAD) + i] = v * sS[i >> 6];
    }
}

// ---------------------------------------------------------------------------
// Build M_b = blockdiag(C_{b,h}) @ W_out.
// Block (nt, bh): M[b][h*64+d][nt*64+c] = sum_d2 ctx[bh][d][d2] * W_out[h*64+d2][nt*64+c]
// grid (16, 32), 256 threads.
// ---------------------------------------------------------------------------
__global__ __launch_bounds__(256, 4)
void make_M_kernel(const float* __restrict__ W_out)
{
    const int nt = blockIdx.x;
    const int bh = blockIdx.y;
    const int b = bh >> 4;
    const int h = bh & 15;
    const int tid = threadIdx.x;

    __shared__ float cst[DHEAD][DHEAD + 1];  // cst[d2][d] = ctx[d][d2]
    __shared__ float ws[DHEAD][DHEAD + 4];

    for (int i = tid; i < DHEAD * DHEAD; i += 256) {
        int d = i >> 6, d2 = i & 63;
        cst[d2][d] = g_ctx[bh * (DHEAD*DHEAD) + i];
        ws[d >> 0][d2] = 0.f; // placeholder to keep compiler happy (overwritten below)
    }
    for (int i = tid; i < DHEAD * DHEAD; i += 256) {
        int k2 = i >> 6, c = i & 63;
        ws[k2][c] = W_out[(long)(h * DHEAD + k2) * DIM + nt * DHEAD + c];
    }
    __syncthreads();

    const int dd0 = (tid >> 4) * 4;
    const int c0 = (tid & 15) * 4;
    float acc[4][4];
    #pragma unroll
    for (int i = 0; i < 4; i++)
        #pragma unroll
        for (int j = 0; j < 4; j++) acc[i][j] = 0.f;

    #pragma unroll 8
    for (int k2 = 0; k2 < DHEAD; ++k2) {
        float ar[4], br[4];
        ar[0] = cst[k2][dd0 + 0];
        ar[1] = cst[k2][dd0 + 1];
        ar[2] = cst[k2][dd0 + 2];
        ar[3] = cst[k2][dd0 + 3];
        *(float4*)br = *(const float4*)&ws[k2][c0];
        #pragma unroll
        for (int i = 0; i < 4; i++)
            #pragma unroll
            for (int j = 0; j < 4; j++)
                acc[i][j] += ar[i] * br[j];
    }

    float* mp = g_M + (long)b * DIM * DIM;
    #pragma unroll
    for (int i = 0; i < 4; i++) {
        float4 v = make_float4(acc[i][0], acc[i][1], acc[i][2], acc[i][3]);
        *(float4*)&mp[(long)(h * DHEAD + dd0 + i) * DIM + nt * DHEAD + c0] = v;
    }
}

// ---------------------------------------------------------------------------
// Launch
// ---------------------------------------------------------------------------
extern "C" void kernel_launch(void* const* d_in, const int* in_sizes, int n_in,
                              void* d_out, int out_size)
{
    const float* feats = (const float*)d_in[0];   // [2,4096,1024]
    const float* W_qkv = (const float*)d_in[1];   // [1024,3072]
    const float* W_out = (const float*)d_in[2];   // [1024,1024]
    float* out = (float*)d_out;                   // [2,4096,1024]

    float* qkv;  cudaGetSymbolAddress((void**)&qkv, g_qkv);
    float* Mb;   cudaGetSymbolAddress((void**)&Mb, g_M);

    // 1) qkv = feats @ W_qkv   [8192,1024] x [1024,3072]
    sgemm_kernel<<<dim3(QKV_COLS / BN, M_ROWS / BM, 1), 256>>>(
        feats, W_qkv, qkv, DIM, DIM, QKV_COLS, QKV_COLS, 0, 0, 0);

    // 2) q softmax (in place)
    q_softmax_kernel<<<(M_ROWS * HEADS) / 8, 256>>>();

    // 3) partial contexts  (8 K-chunks x 32 bh)
    ctx_partial_kernel<<<dim3(8, 32), 256>>>();

    // 4) reduce + normalize
    ctx_reduce_kernel<<<32, 256>>>();

    // 5) M_b = blockdiag(ctx) @ W_out
    make_M_kernel<<<dim3(16, 32), 256>>>(W_out);

    // 6) out = q' @ M_b   batched over b:  [4096,1024] x [1024,1024]
    sgemm_kernel<<<dim3(DIM / BN, N_SEQ / BM, B), 256>>>(
        qkv, Mb, out, DIM, QKV_COLS, DIM, DIM,
        (long)N_SEQ * QKV_COLS, (long)DIM * DIM, (long)N_SEQ * DIM);
}

// round 4
// speedup vs baseline: 4.4674x; 4.4674x over previous
#include <cuda_runtime.h>
#include <cuda_fp16.h>
#include <cstdint>
#include <math.h>

// Problem constants
#define B 2
#define N_SEQ 4096
#define DIM 1024
#define HEADS 16
#define DHEAD 64
#define M_ROWS (B * N_SEQ)        // 8192
#define QKV_COLS (3 * DIM)        // 3072

// ---------------------------------------------------------------------------
// Scratch (device globals)
// ---------------------------------------------------------------------------
__device__ float  g_qkv[(size_t)M_ROWS * QKV_COLS];      // fp32 qkv
__device__ __half g_featsh[(size_t)M_ROWS * DIM];        // feats fp16 (K-major)
__device__ __half g_Wt[(size_t)QKV_COLS * DIM];          // W_qkv^T fp16 [3072][1024]
__device__ __half g_qh[(size_t)M_ROWS * DIM];            // q' fp16 [8192][1024]
__device__ __half g_Mh[(size_t)B * DIM * DIM];           // M_b^T fp16 [b][1024][1024]
__device__ float  g_ctxp[8 * 32 * DHEAD * DHEAD];
__device__ float  g_Sp[8 * 32 * DHEAD];
__device__ float  g_ctx[32 * DHEAD * DHEAD];

// ---------------------------------------------------------------------------
// Helpers
// ---------------------------------------------------------------------------
__device__ __forceinline__ uint32_t smem_u32(const void* p) {
    uint32_t a;
    asm("{ .reg .u64 t; cvta.to.shared.u64 t, %1; cvt.u32.u64 %0, t; }" : "=r"(a) : "l"(p));
    return a;
}
#define CP_ASYNC16(smem, g) \
    asm volatile("cp.async.cg.shared.global [%0], [%1], 16;" :: "r"((uint32_t)(smem)), "l"(g) : "memory")
#define CP_COMMIT() asm volatile("cp.async.commit_group;" ::: "memory")
template <int N> __device__ __forceinline__ void cp_wait() {
    asm volatile("cp.async.wait_group %0;" :: "n"(N) : "memory");
}
#define SWZ(x) ((x) ^ (((x) >> 3) & 0x70))

#define LDSM_X4(r0, r1, r2, r3, addr) \
    asm volatile("ldmatrix.sync.aligned.m8n8.x4.shared.b16 {%0,%1,%2,%3}, [%4];" \
                 : "=r"(r0), "=r"(r1), "=r"(r2), "=r"(r3) : "r"(addr))

#define MMA16816(c0, c1, c2, c3, a0, a1, a2, a3, b0, b1) \
    asm volatile("mma.sync.aligned.m16n8k16.row.col.f32.f16.f16.f32 " \
                 "{%0,%1,%2,%3}, {%4,%5,%6,%7}, {%8,%9}, {%0,%1,%2,%3};" \
                 : "+f"(c0), "+f"(c1), "+f"(c2), "+f"(c3) \
                 : "r"(a0), "r"(a1), "r"(a2), "r"(a3), "r"(b0), "r"(b1))

// ---------------------------------------------------------------------------
// HMMA fp16 GEMM: C[M,N] = A[M,K] @ B[N,K]^T, fp32 out.
// A row-major fp16 (lda), B row-major fp16 [N][K] (ldb), C fp32 (ldc).
// Tile 128x128, K-chunk 64 halves (128B rows, SW128), 3-stage cp.async.
// 256 threads = 8 warps in 2(M) x 4(N); warp tile 64x32.
// ---------------------------------------------------------------------------
#define HG_BM 128
#define HG_BN 128
#define HG_BK 64
#define STG_A (HG_BM * 128)            // 16 KB
#define STG_B (HG_BN * 128)            // 16 KB
#define STG_BYTES (STG_A + STG_B)      // 32 KB
#define HG_STAGES 3
#define HG_SMEM (HG_STAGES * STG_BYTES)  // 96 KB

__global__ __launch_bounds__(256, 1)
void hgemm_kernel(const __half* __restrict__ A, const __half* __restrict__ Bh,
                  float* __restrict__ C, int K, int lda, int ldb, int ldc,
                  long aB, long bB, long cB)
{
    A  += (long)blockIdx.z * aB;
    Bh += (long)blockIdx.z * bB;
    C  += (long)blockIdx.z * cB;

    extern __shared__ char smem[];
    const uint32_t sbase = smem_u32(smem);
    const int tid  = threadIdx.x;
    const int wid  = tid >> 5;
    const int lane = tid & 31;
    const int wm = wid & 1;            // 0..1  (64 rows each)
    const int wn = wid >> 1;           // 0..3  (32 cols each)
    const int bm = blockIdx.y * HG_BM;
    const int bn = blockIdx.x * HG_BN;
    const int NC = K >> 6;             // chunks of 64

    // cp.async mapping: 1024 16B ops per operand, 4 per thread each
    const int ldr = tid >> 3;          // 0..31 base row block? (u = tid + i*256: r=u>>3)
    const int ldc16 = tid & 7;

    auto load_chunk = [&](int kc, int st) {
        const uint32_t sa = sbase + st * STG_BYTES;
        const uint32_t sb = sa + STG_A;
        const __half* ap = A + kc * 64;
        const __half* bp = Bh + kc * 64;
        #pragma unroll
        for (int i = 0; i < 4; ++i) {
            int r = ldr + i * 32;
            CP_ASYNC16(sa + SWZ(r * 128 + ldc16 * 16), ap + (long)(bm + r) * lda + ldc16 * 8);
        }
        #pragma unroll
        for (int i = 0; i < 4; ++i) {
            int r = ldr + i * 32;
            CP_ASYNC16(sb + SWZ(r * 128 + ldc16 * 16), bp + (long)(bn + r) * ldb + ldc16 * 8);
        }
    };

    float acc[4][4][4];
    #pragma unroll
    for (int i = 0; i < 4; i++)
        #pragma unroll
        for (int j = 0; j < 4; j++)
            #pragma unroll
            for (int x = 0; x < 4; x++) acc[i][j][x] = 0.f;

    // prologue: stages 0,1
    load_chunk(0, 0); CP_COMMIT();
    load_chunk(1, 1); CP_COMMIT();

    // per-lane ldmatrix row/chunk selectors
    const int lrow = lane & 15;        // row within 16-row tile
    const int lsel = lane >> 4;        // 0: k0-7 chunk, 1: k8-15 chunk

    for (int c = 0; c < NC; ++c) {
        const int st = c % HG_STAGES;
        cp_wait<1>();
        __syncthreads();

        // prefetch c+2 into the free stage
        if (c + 2 < NC) load_chunk(c + 2, (c + 2) % HG_STAGES);
        CP_COMMIT();

        const uint32_t sa = sbase + st * STG_BYTES;
        const uint32_t sb = sa + STG_A;

        #pragma unroll
        for (int ks = 0; ks < 4; ++ks) {
            const int cc = 2 * ks + lsel;          // 16B chunk within 128B row
            uint32_t af[4][4];
            #pragma unroll
            for (int mt = 0; mt < 4; ++mt) {
                int row = wm * 64 + mt * 16 + lrow;
                uint32_t addr = sa + SWZ(row * 128 + cc * 16);
                LDSM_X4(af[mt][0], af[mt][1], af[mt][2], af[mt][3], addr);
            }
            uint32_t bf[2][4];
            #pragma unroll
            for (int np = 0; np < 2; ++np) {
                int row = wn * 32 + np * 16 + lrow;
                uint32_t addr = sb + SWZ(row * 128 + cc * 16);
                LDSM_X4(bf[np][0], bf[np][1], bf[np][2], bf[np][3], addr);
            }
            #pragma unroll
            for (int mt = 0; mt < 4; ++mt) {
                #pragma unroll
                for (int np = 0; np < 2; ++np) {
                    MMA16816(acc[mt][2*np][0], acc[mt][2*np][1], acc[mt][2*np][2], acc[mt][2*np][3],
                             af[mt][0], af[mt][1], af[mt][2], af[mt][3],
                             bf[np][0], bf[np][2]);
                    MMA16816(acc[mt][2*np+1][0], acc[mt][2*np+1][1], acc[mt][2*np+1][2], acc[mt][2*np+1][3],
                             af[mt][0], af[mt][1], af[mt][2], af[mt][3],
                             bf[np][1], bf[np][3]);
                }
            }
        }
        __syncthreads();
    }

    // epilogue: direct fp32 stores
    const int r0 = bm + wm * 64 + (lane >> 2);
    const int c0 = bn + wn * 32 + (lane & 3) * 2;
    #pragma unroll
    for (int mt = 0; mt < 4; ++mt) {
        #pragma unroll
        for (int nt = 0; nt < 4; ++nt) {
            float* p0 = C + (long)(r0 + mt * 16) * ldc + c0 + nt * 8;
            float* p1 = p0 + 8 * ldc;
            *(float2*)p0 = make_float2(acc[mt][nt][0], acc[mt][nt][1]);
            *(float2*)p1 = make_float2(acc[mt][nt][2], acc[mt][nt][3]);
        }
    }
}

// ---------------------------------------------------------------------------
// feats fp32 -> fp16
// ---------------------------------------------------------------------------
__global__ void f2h_kernel(const float* __restrict__ in)
{
    long i = (long)blockIdx.x * 256 + threadIdx.x;   // float4 index
    float4 f = ((const float4*)in)[i];
    ((__half2*)g_featsh)[2 * i]     = __floats2half2_rn(f.x, f.y);
    ((__half2*)g_featsh)[2 * i + 1] = __floats2half2_rn(f.z, f.w);
}

// W_qkv [1024][3072] fp32 -> g_Wt [3072][1024] fp16 (transpose)
__global__ void wtrans_kernel(const float* __restrict__ W)
{
    __shared__ float t[32][33];
    const int n0 = blockIdx.x * 32, k0 = blockIdx.y * 32;
    const int tx = threadIdx.x & 31, ty = threadIdx.x >> 5;  // 32 x 8
    #pragma unroll
    for (int j = 0; j < 4; ++j)
        t[ty + 8 * j][tx] = W[(long)(k0 + ty + 8 * j) * QKV_COLS + n0 + tx];
    __syncthreads();
    #pragma unroll
    for (int j = 0; j < 4; ++j)
        g_Wt[(long)(n0 + ty + 8 * j) * DIM + k0 + tx] = __float2half_rn(t[tx][ty + 8 * j]);
}

// ---------------------------------------------------------------------------
// q softmax over d=64 per (m,h), * scale, in place
// ---------------------------------------------------------------------------
__global__ void q_softmax_kernel()
{
    int gw = (blockIdx.x * blockDim.x + threadIdx.x) >> 5;
    int lane = threadIdx.x & 31;
    int m = gw >> 4;
    int h = gw & 15;
    float* p = g_qkv + (long)m * QKV_COLS + h * DHEAD;
    float v0 = p[lane];
    float v1 = p[lane + 32];
    float mx = fmaxf(v0, v1);
    #pragma unroll
    for (int o = 16; o > 0; o >>= 1) mx = fmaxf(mx, __shfl_xor_sync(0xFFFFFFFFu, mx, o));
    float e0 = expf(v0 - mx);
    float e1 = expf(v1 - mx);
    float s = e0 + e1;
    #pragma unroll
    for (int o = 16; o > 0; o >>= 1) s += __shfl_xor_sync(0xFFFFFFFFu, s, o);
    float inv = 0.125f / s;                  // scale = 64^-0.5
    p[lane] = e0 * inv;
    p[lane + 32] = e1 * inv;
}

// q' cols of g_qkv -> fp16 g_qh [8192][1024]
__global__ void q2h_kernel()
{
    long t = (long)blockIdx.x * 256 + threadIdx.x;
    long row = t >> 8;
    int c4 = (int)(t & 255);
    float4 f = *(const float4*)&g_qkv[row * QKV_COLS + c4 * 4];
    *(__half2*)&g_qh[row * DIM + c4 * 4]     = __floats2half2_rn(f.x, f.y);
    *(__half2*)&g_qh[row * DIM + c4 * 4 + 2] = __floats2half2_rn(f.z, f.w);
}

// ---------------------------------------------------------------------------
// Partial context: ctxp[d][e] += exp(k[n,d]) * v[n,e]; Sp[d] += exp(k[n,d])
// ---------------------------------------------------------------------------
__global__ __launch_bounds__(256, 4)
void ctx_partial_kernel()
{
    const int chunk = blockIdx.x;
    const int bh = blockIdx.y;
    const int b = bh >> 4;
    const int h = bh & 15;

    __shared__ float ek[32][DHEAD];
    __shared__ float sv[32][DHEAD];

    const int tid = threadIdx.x;
    const int d0 = (tid >> 4) * 4;
    const int e0 = (tid & 15) * 4;

    float acc[4][4];
    #pragma unroll
    for (int i = 0; i < 4; i++)
        #pragma unroll
        for (int j = 0; j < 4; j++) acc[i][j] = 0.f;
    float ssum = 0.f;

    const long rowbase = (long)b * N_SEQ;
    const int kcol = DIM + h * DHEAD;
    const int vcol = 2 * DIM + h * DHEAD;

    for (int t = 0; t < 16; ++t) {
        int n_base = chunk * 512 + t * 32;
        #pragma unroll
        for (int i = 0; i < 2; ++i) {
            int idx = tid + i * 256;
            int r = idx >> 4;
            int c4 = idx & 15;
            long m = rowbase + n_base + r;
            float4 kv = *(const float4*)&g_qkv[m * QKV_COLS + kcol + c4 * 4];
            ek[r][c4*4+0] = __expf(kv.x);
            ek[r][c4*4+1] = __expf(kv.y);
            ek[r][c4*4+2] = __expf(kv.z);
            ek[r][c4*4+3] = __expf(kv.w);
            *(float4*)&sv[r][c4*4] = *(const float4*)&g_qkv[m * QKV_COLS + vcol + c4 * 4];
        }
        __syncthreads();

        if (tid < 64) {
            #pragma unroll
            for (int kk = 0; kk < 32; ++kk) ssum += ek[kk][tid];
        }
        #pragma unroll
        for (int kk = 0; kk < 32; ++kk) {
            float ar[4], br[4];
            *(float4*)ar = *(const float4*)&ek[kk][d0];
            *(float4*)br = *(const float4*)&sv[kk][e0];
            #pragma unroll
            for (int i = 0; i < 4; i++)
                #pragma unroll
                for (int j = 0; j < 4; j++)
                    acc[i][j] += ar[i] * br[j];
        }
        __syncthreads();
    }

    float* outp = g_ctxp + ((long)chunk * 32 + bh) * (DHEAD * DHEAD);
    #pragma unroll
    for (int i = 0; i < 4; i++) {
        float4 v = make_float4(acc[i][0], acc[i][1], acc[i][2], acc[i][3]);
        *(float4*)&outp[(d0 + i) * DHEAD + e0] = v;
    }
    if (tid < 64) g_Sp[(chunk * 32 + bh) * DHEAD + tid] = ssum;
}

__global__ void ctx_reduce_kernel()
{
    const int bh = blockIdx.x;
    const int tid = threadIdx.x;
    __shared__ float sS[DHEAD];
    if (tid < 64) {
        float s = 0.f;
        #pragma unroll
        for (int c = 0; c < 8; ++c) s += g_Sp[(c * 32 + bh) * DHEAD + tid];
        sS[tid] = 1.f / s;
    }
    __syncthreads();
    for (int i = tid; i < DHEAD * DHEAD; i += 256) {
        float v = 0.f;
        #pragma unroll
        for (int c = 0; c < 8; ++c) v += g_ctxp[((long)c * 32 + bh) * (DHEAD*DHEAD) + i];
        g_ctx[bh * (DHEAD*DHEAD) + i] = v * sS[i >> 6];
    }
}

// ---------------------------------------------------------------------------
// M_b^T (fp16) = (blockdiag(ctx_b) @ W_out)^T. g_Mh[b][n][k] = M_b[k][n]
// ---------------------------------------------------------------------------
__global__ __launch_bounds__(256, 4)
void make_M_kernel(const float* __restrict__ W_out)
{
    const int nt = blockIdx.x;
    const int bh = blockIdx.y;
    const int b = bh >> 4;
    const int h = bh & 15;
    const int tid = threadIdx.x;

    __shared__ float cst[DHEAD][DHEAD + 1];  // cst[d2][d] = ctx[d][d2]
    __shared__ float ws[DHEAD][DHEAD + 4];

    for (int i = tid; i < DHEAD * DHEAD; i += 256) {
        int d = i >> 6, d2 = i & 63;
        cst[d2][d] = g_ctx[bh * (DHEAD*DHEAD) + i];
    }
    for (int i = tid; i < DHEAD * DHEAD; i += 256) {
        int k2 = i >> 6, c = i & 63;
        ws[k2][c] = W_out[(long)(h * DHEAD + k2) * DIM + nt * DHEAD + c];
    }
    __syncthreads();

    const int dd0 = (tid >> 4) * 4;
    const int c0 = (tid & 15) * 4;
    float acc[4][4];
    #pragma unroll
    for (int i = 0; i < 4; i++)
        #pragma unroll
        for (int j = 0; j < 4; j++) acc[i][j] = 0.f;

    #pragma unroll 8
    for (int k2 = 0; k2 < DHEAD; ++k2) {
        float ar[4], br[4];
        ar[0] = cst[k2][dd0 + 0];
        ar[1] = cst[k2][dd0 + 1];
        ar[2] = cst[k2][dd0 + 2];
        ar[3] = cst[k2][dd0 + 3];
        *(float4*)br = *(const float4*)&ws[k2][c0];
        #pragma unroll
        for (int i = 0; i < 4; i++)
            #pragma unroll
            for (int j = 0; j < 4; j++)
                acc[i][j] += ar[i] * br[j];
    }

    // write transposed fp16: Mh[b][nt*64+c][h*64+d]
    #pragma unroll
    for (int j = 0; j < 4; ++j) {
        long rowb = (long)b * DIM * DIM + (long)(nt * 64 + c0 + j) * DIM + h * 64 + dd0;
        *(__half2*)&g_Mh[rowb]     = __floats2half2_rn(acc[0][j], acc[1][j]);
        *(__half2*)&g_Mh[rowb + 2] = __floats2half2_rn(acc[2][j], acc[3][j]);
    }
}

// ---------------------------------------------------------------------------
// Launch
// ---------------------------------------------------------------------------
extern "C" void kernel_launch(void* const* d_in, const int* in_sizes, int n_in,
                              void* d_out, int out_size)
{
    const float* feats = (const float*)d_in[0];   // [2,4096,1024]
    const float* W_qkv = (const float*)d_in[1];   // [1024,3072]
    const float* W_out = (const float*)d_in[2];   // [1024,1024]
    float* out = (float*)d_out;                   // [2,4096,1024]

    cudaFuncSetAttribute(hgemm_kernel, cudaFuncAttributeMaxDynamicSharedMemorySize, HG_SMEM);

    float*  qkv;    cudaGetSymbolAddress((void**)&qkv, g_qkv);
    __half* featsh; cudaGetSymbolAddress((void**)&featsh, g_featsh);
    __half* Wt;     cudaGetSymbolAddress((void**)&Wt, g_Wt);
    __half* qh;     cudaGetSymbolAddress((void**)&qh, g_qh);
    __half* Mh;     cudaGetSymbolAddress((void**)&Mh, g_Mh);

    // 0) conversions
    f2h_kernel<<<(M_ROWS * DIM / 4) / 256, 256>>>(feats);
    wtrans_kernel<<<dim3(QKV_COLS / 32, DIM / 32), 256>>>(W_qkv);

    // 1) qkv = feats @ W_qkv  (HMMA fp16): A[8192,1024], B=W^T[3072,1024]
    hgemm_kernel<<<dim3(QKV_COLS / HG_BN, M_ROWS / HG_BM, 1), 256, HG_SMEM>>>(
        featsh, Wt, qkv, DIM, DIM, DIM, QKV_COLS, 0, 0, 0);

    // 2) q softmax (fp32 in place), q -> fp16
    q_softmax_kernel<<<(M_ROWS * HEADS) / 8, 256>>>();
    q2h_kernel<<<(M_ROWS * 256) / 256, 256>>>();

    // 3) context partials + reduce
    ctx_partial_kernel<<<dim3(8, 32), 256>>>();
    ctx_reduce_kernel<<<32, 256>>>();

    // 4) M_b^T fp16 = (blockdiag(ctx) @ W_out)^T
    make_M_kernel<<<dim3(16, 32), 256>>>(W_out);

    // 5) out = q' @ M_b (HMMA fp16, batched over b)
    hgemm_kernel<<<dim3(DIM / HG_BN, N_SEQ / HG_BM, B), 256, HG_SMEM>>>(
        qh, Mh, out, DIM, DIM, DIM, DIM,
        (long)N_SEQ * DIM, (long)DIM * DIM, (long)N_SEQ * DIM);
}

// round 5
// speedup vs baseline: 5.2506x; 1.1753x over previous
#include <cuda_runtime.h>
#include <cuda_fp16.h>
#include <cstdint>
#include <math.h>

// Problem constants
#define B 2
#define N_SEQ 4096
#define DIM 1024
#define HEADS 16
#define DHEAD 64
#define M_ROWS (B * N_SEQ)        // 8192
#define QKV_COLS (3 * DIM)        // 3072

// ---------------------------------------------------------------------------
// Scratch (device globals)
// ---------------------------------------------------------------------------
__device__ __half g_featsh[(size_t)M_ROWS * DIM];        // feats fp16
__device__ __half g_Wt[(size_t)QKV_COLS * DIM];          // W_qkv^T fp16 [3072][1024]
__device__ __half g_qh[(size_t)M_ROWS * DIM];            // q' (softmaxed*scale) fp16
__device__ __half g_ekh[(size_t)M_ROWS * DIM];           // exp(k) fp16
__device__ __half g_vh[(size_t)M_ROWS * DIM];            // v fp16
__device__ __half g_Mh[(size_t)B * DIM * DIM];           // M_b^T fp16
__device__ float  g_S[B * DIM];                          // colsum exp(k)
__device__ float  g_ctxp[8 * 32 * DHEAD * DHEAD];
__device__ float  g_ctx[32 * DHEAD * DHEAD];

// ---------------------------------------------------------------------------
// Helpers
// ---------------------------------------------------------------------------
__device__ __forceinline__ uint32_t smem_u32(const void* p) {
    uint32_t a;
    asm("{ .reg .u64 t; cvta.to.shared.u64 t, %1; cvt.u32.u64 %0, t; }" : "=r"(a) : "l"(p));
    return a;
}
#define CP_ASYNC16(smem, g) \
    asm volatile("cp.async.cg.shared.global [%0], [%1], 16;" :: "r"((uint32_t)(smem)), "l"(g) : "memory")
#define CP_COMMIT() asm volatile("cp.async.commit_group;" ::: "memory")
template <int N> __device__ __forceinline__ void cp_wait() {
    asm volatile("cp.async.wait_group %0;" :: "n"(N) : "memory");
}
#define SWZ(x) ((x) ^ (((x) >> 3) & 0x70))

#define LDSM_X4(r0, r1, r2, r3, addr) \
    asm volatile("ldmatrix.sync.aligned.m8n8.x4.shared.b16 {%0,%1,%2,%3}, [%4];" \
                 : "=r"(r0), "=r"(r1), "=r"(r2), "=r"(r3) : "r"(addr))

#define MMA16816(c0, c1, c2, c3, a0, a1, a2, a3, b0, b1) \
    asm volatile("mma.sync.aligned.m16n8k16.row.col.f32.f16.f16.f32 " \
                 "{%0,%1,%2,%3}, {%4,%5,%6,%7}, {%8,%9}, {%0,%1,%2,%3};" \
                 : "+f"(c0), "+f"(c1), "+f"(c2), "+f"(c3) \
                 : "r"(a0), "r"(a1), "r"(a2), "r"(a3), "r"(b0), "r"(b1))

// ---------------------------------------------------------------------------
// HMMA fp16 GEMM: 128x256 tile, K-chunk 64, 4-stage cp.async, 8 warps (2x4),
// warp tile 64x64.
// MODE 0: qkv fused epilogue (softmax-q / exp-k+colsum / v), fp16 outputs.
// MODE 1: plain fp32 C store.
// ---------------------------------------------------------------------------
#define HG_BM 128
#define HG_BN 256
#define STG_A (HG_BM * 128)            // 16 KB
#define STG_B (HG_BN * 128)            // 32 KB
#define STG_BYTES (STG_A + STG_B)      // 48 KB
#define HG_STAGES 4
#define HG_SMEM (HG_STAGES * STG_BYTES)  // 192 KB

template <int MODE>
__global__ __launch_bounds__(256, 1)
void hgemm_kernel(const __half* __restrict__ A, const __half* __restrict__ Bh,
                  float* __restrict__ C, int K, int lda, int ldb, int ldc,
                  long aB, long bB, long cB)
{
    A  += (long)blockIdx.z * aB;
    Bh += (long)blockIdx.z * bB;
    if (MODE == 1) C += (long)blockIdx.z * cB;

    extern __shared__ char smem[];
    const uint32_t sbase = smem_u32(smem);
    const int tid  = threadIdx.x;
    const int wid  = tid >> 5;
    const int lane = tid & 31;
    const int wm = wid & 1;            // 0..1 (64 rows)
    const int wn = wid >> 1;           // 0..3 (64 cols)
    const int bm = blockIdx.y * HG_BM;
    const int bn = blockIdx.x * HG_BN;
    const int NC = K >> 6;

    const int ldr = tid >> 3;          // 0..31
    const int ldc16 = tid & 7;

    auto load_chunk = [&](int kc, int st) {
        const uint32_t sa = sbase + st * STG_BYTES;
        const uint32_t sb = sa + STG_A;
        const __half* ap = A + (long)bm * lda + kc * 64;
        const __half* bp = Bh + (long)bn * ldb + kc * 64;
        #pragma unroll
        for (int i = 0; i < 4; ++i) {
            int r = ldr + i * 32;
            CP_ASYNC16(sa + SWZ(r * 128 + ldc16 * 16), ap + (long)r * lda + ldc16 * 8);
        }
        #pragma unroll
        for (int i = 0; i < 8; ++i) {
            int r = ldr + i * 32;
            CP_ASYNC16(sb + SWZ(r * 128 + ldc16 * 16), bp + (long)r * ldb + ldc16 * 8);
        }
    };

    float acc[4][8][4];
    #pragma unroll
    for (int i = 0; i < 4; i++)
        #pragma unroll
        for (int j = 0; j < 8; j++)
            #pragma unroll
            for (int x = 0; x < 4; x++) acc[i][j][x] = 0.f;

    load_chunk(0, 0); CP_COMMIT();
    load_chunk(1, 1); CP_COMMIT();
    load_chunk(2, 2); CP_COMMIT();

    const int lrow = lane & 15;
    const int lsel = lane >> 4;

    for (int c = 0; c < NC; ++c) {
        const int st = c & 3;
        int allow = NC - 1 - c;
        if (allow >= 2)      cp_wait<2>();
        else if (allow == 1) cp_wait<1>();
        else                 cp_wait<0>();
        __syncthreads();
        if (c + 3 < NC) { load_chunk(c + 3, (c + 3) & 3); CP_COMMIT(); }

        const uint32_t sa = sbase + st * STG_BYTES;
        const uint32_t sb = sa + STG_A;

        #pragma unroll
        for (int ks = 0; ks < 4; ++ks) {
            const int cc = 2 * ks + lsel;
            uint32_t af[4][4];
            #pragma unroll
            for (int mt = 0; mt < 4; ++mt) {
                int row = wm * 64 + mt * 16 + lrow;
                LDSM_X4(af[mt][0], af[mt][1], af[mt][2], af[mt][3], sa + SWZ(row * 128 + cc * 16));
            }
            uint32_t bf[4][4];
            #pragma unroll
            for (int np = 0; np < 4; ++np) {
                int row = wn * 64 + np * 16 + lrow;
                LDSM_X4(bf[np][0], bf[np][1], bf[np][2], bf[np][3], sb + SWZ(row * 128 + cc * 16));
            }
            #pragma unroll
            for (int mt = 0; mt < 4; ++mt) {
                #pragma unroll
                for (int np = 0; np < 4; ++np) {
                    MMA16816(acc[mt][2*np][0], acc[mt][2*np][1], acc[mt][2*np][2], acc[mt][2*np][3],
                             af[mt][0], af[mt][1], af[mt][2], af[mt][3],
                             bf[np][0], bf[np][2]);
                    MMA16816(acc[mt][2*np+1][0], acc[mt][2*np+1][1], acc[mt][2*np+1][2], acc[mt][2*np+1][3],
                             af[mt][0], af[mt][1], af[mt][2], af[mt][3],
                             bf[np][1], bf[np][3]);
                }
            }
        }
    }

    // ------------------------- epilogue -------------------------
    const int r_base = bm + wm * 64;
    const int cq = (lane & 3) * 2;                 // col pair offset in n8 tile

    if (MODE == 1) {
        #pragma unroll
        for (int mt = 0; mt < 4; ++mt) {
            int r0 = r_base + mt * 16 + (lane >> 2);
            #pragma unroll
            for (int nt = 0; nt < 8; ++nt) {
                int col = bn + wn * 64 + nt * 8 + cq;
                *(float2*)&C[(long)r0 * ldc + col]       = make_float2(acc[mt][nt][0], acc[mt][nt][1]);
                *(float2*)&C[(long)(r0 + 8) * ldc + col] = make_float2(acc[mt][nt][2], acc[mt][nt][3]);
            }
        }
    } else {
        const int region = bn >> 10;               // 0=q, 1=k, 2=v
        const int bidb = bm >> 12;                 // batch (bm/4096)
        if (region == 0) {
            // softmax over the warp's 64 cols (= one head) per row, *0.125
            #pragma unroll
            for (int mt = 0; mt < 4; ++mt) {
                #pragma unroll
                for (int hf = 0; hf < 2; ++hf) {
                    int row = r_base + mt * 16 + (lane >> 2) + 8 * hf;
                    float mx = -1e30f;
                    #pragma unroll
                    for (int nt = 0; nt < 8; ++nt)
                        mx = fmaxf(mx, fmaxf(acc[mt][nt][2*hf], acc[mt][nt][2*hf+1]));
                    mx = fmaxf(mx, __shfl_xor_sync(0xFFFFFFFFu, mx, 1));
                    mx = fmaxf(mx, __shfl_xor_sync(0xFFFFFFFFu, mx, 2));
                    float s = 0.f;
                    #pragma unroll
                    for (int nt = 0; nt < 8; ++nt) {
                        float e0 = __expf(acc[mt][nt][2*hf]   - mx);
                        float e1 = __expf(acc[mt][nt][2*hf+1] - mx);
                        acc[mt][nt][2*hf] = e0; acc[mt][nt][2*hf+1] = e1;
                        s += e0 + e1;
                    }
                    s += __shfl_xor_sync(0xFFFFFFFFu, s, 1);
                    s += __shfl_xor_sync(0xFFFFFFFFu, s, 2);
                    float inv = 0.125f / s;
                    #pragma unroll
                    for (int nt = 0; nt < 8; ++nt) {
                        int col = bn + wn * 64 + nt * 8 + cq;
                        *(__half2*)&g_qh[(long)row * DIM + col] =
                            __floats2half2_rn(acc[mt][nt][2*hf] * inv, acc[mt][nt][2*hf+1] * inv);
                    }
                }
            }
        } else if (region == 1) {
            // exp(k) -> fp16, plus per-column sums -> atomicAdd g_S
            const int coff = bn - 1024;
            float cs[8][2];
            #pragma unroll
            for (int nt = 0; nt < 8; ++nt) { cs[nt][0] = 0.f; cs[nt][1] = 0.f; }
            #pragma unroll
            for (int mt = 0; mt < 4; ++mt) {
                int r0 = r_base + mt * 16 + (lane >> 2);
                #pragma unroll
                for (int nt = 0; nt < 8; ++nt) {
                    float e0 = __expf(acc[mt][nt][0]);
                    float e1 = __expf(acc[mt][nt][1]);
                    float e2 = __expf(acc[mt][nt][2]);
                    float e3 = __expf(acc[mt][nt][3]);
                    cs[nt][0] += e0 + e2;
                    cs[nt][1] += e1 + e3;
                    int col = coff + wn * 64 + nt * 8 + cq;
                    *(__half2*)&g_ekh[(long)r0 * DIM + col]       = __floats2half2_rn(e0, e1);
                    *(__half2*)&g_ekh[(long)(r0 + 8) * DIM + col] = __floats2half2_rn(e2, e3);
                }
            }
            #pragma unroll
            for (int nt = 0; nt < 8; ++nt) {
                #pragma unroll
                for (int j = 0; j < 2; ++j) {
                    float c = cs[nt][j];
                    c += __shfl_xor_sync(0xFFFFFFFFu, c, 4);
                    c += __shfl_xor_sync(0xFFFFFFFFu, c, 8);
                    c += __shfl_xor_sync(0xFFFFFFFFu, c, 16);
                    if (lane < 4)
                        atomicAdd(&g_S[bidb * DIM + coff + wn * 64 + nt * 8 + cq + j], c);
                }
            }
        } else {
            const int coff = bn - 2048;
            #pragma unroll
            for (int mt = 0; mt < 4; ++mt) {
                int r0 = r_base + mt * 16 + (lane >> 2);
                #pragma unroll
                for (int nt = 0; nt < 8; ++nt) {
                    int col = coff + wn * 64 + nt * 8 + cq;
                    *(__half2*)&g_vh[(long)r0 * DIM + col]       = __floats2half2_rn(acc[mt][nt][0], acc[mt][nt][1]);
                    *(__half2*)&g_vh[(long)(r0 + 8) * DIM + col] = __floats2half2_rn(acc[mt][nt][2], acc[mt][nt][3]);
                }
            }
        }
    }
}

// ---------------------------------------------------------------------------
// Small kernels
// ---------------------------------------------------------------------------
__global__ void zero_S_kernel() { g_S[blockIdx.x * 256 + threadIdx.x] = 0.f; }

__global__ void f2h_kernel(const float* __restrict__ in)
{
    long i = (long)blockIdx.x * 256 + threadIdx.x;   // float4 index
    float4 f = ((const float4*)in)[i];
    ((__half2*)g_featsh)[2 * i]     = __floats2half2_rn(f.x, f.y);
    ((__half2*)g_featsh)[2 * i + 1] = __floats2half2_rn(f.z, f.w);
}

__global__ void wtrans_kernel(const float* __restrict__ W)
{
    __shared__ float t[32][33];
    const int n0 = blockIdx.x * 32, k0 = blockIdx.y * 32;
    const int tx = threadIdx.x & 31, ty = threadIdx.x >> 5;  // 32 x 8
    #pragma unroll
    for (int j = 0; j < 4; ++j)
        t[ty + 8 * j][tx] = W[(long)(k0 + ty + 8 * j) * QKV_COLS + n0 + tx];
    __syncthreads();
    #pragma unroll
    for (int j = 0; j < 4; ++j)
        g_Wt[(long)(n0 + ty + 8 * j) * DIM + k0 + tx] = __float2half_rn(t[tx][ty + 8 * j]);
}

// ---------------------------------------------------------------------------
// Partial context from fp16 ek/v: ctxp[d][e] += ek[n,d] * v[n,e]
// ---------------------------------------------------------------------------
__global__ __launch_bounds__(256, 4)
void ctx_partial_kernel()
{
    const int chunk = blockIdx.x;
    const int bh = blockIdx.y;
    const int b = bh >> 4;
    const int h = bh & 15;

    __shared__ float ek[32][DHEAD];
    __shared__ float sv[32][DHEAD];

    const int tid = threadIdx.x;
    const int d0 = (tid >> 4) * 4;
    const int e0 = (tid & 15) * 4;
    const int lr = tid >> 3;           // 0..31
    const int lc8 = (tid & 7) * 8;

    float acc[4][4];
    #pragma unroll
    for (int i = 0; i < 4; i++)
        #pragma unroll
        for (int j = 0; j < 4; j++) acc[i][j] = 0.f;

    const long rowbase = (long)b * N_SEQ;
    const int hc = h * DHEAD;

    for (int t = 0; t < 16; ++t) {
        long m = rowbase + chunk * 512 + t * 32 + lr;
        {
            uint4 raw = *(const uint4*)&g_ekh[m * DIM + hc + lc8];
            const __half2* ph = (const __half2*)&raw;
            #pragma unroll
            for (int u = 0; u < 4; ++u) {
                float2 f = __half22float2(ph[u]);
                ek[lr][lc8 + 2*u] = f.x; ek[lr][lc8 + 2*u + 1] = f.y;
            }
        }
        {
            uint4 raw = *(const uint4*)&g_vh[m * DIM + hc + lc8];
            const __half2* ph = (const __half2*)&raw;
            #pragma unroll
            for (int u = 0; u < 4; ++u) {
                float2 f = __half22float2(ph[u]);
                sv[lr][lc8 + 2*u] = f.x; sv[lr][lc8 + 2*u + 1] = f.y;
            }
        }
        __syncthreads();
        #pragma unroll
        for (int kk = 0; kk < 32; ++kk) {
            float ar[4], br[4];
            *(float4*)ar = *(const float4*)&ek[kk][d0];
            *(float4*)br = *(const float4*)&sv[kk][e0];
            #pragma unroll
            for (int i = 0; i < 4; i++)
                #pragma unroll
                for (int j = 0; j < 4; j++)
                    acc[i][j] += ar[i] * br[j];
        }
        __syncthreads();
    }

    float* outp = g_ctxp + ((long)chunk * 32 + bh) * (DHEAD * DHEAD);
    #pragma unroll
    for (int i = 0; i < 4; i++)
        *(float4*)&outp[(d0 + i) * DHEAD + e0] =
            make_float4(acc[i][0], acc[i][1], acc[i][2], acc[i][3]);
}

// reduce 8 chunk partials. grid (32 bh, 4 quarters), 256 threads, 4 floats each.
__global__ void ctx_reduce_kernel()
{
    const int bh = blockIdx.x;
    const int idx = blockIdx.y * 1024 + threadIdx.x * 4;
    float4 v = make_float4(0.f, 0.f, 0.f, 0.f);
    #pragma unroll
    for (int c = 0; c < 8; ++c) {
        float4 p = *(const float4*)&g_ctxp[((long)c * 32 + bh) * (DHEAD*DHEAD) + idx];
        v.x += p.x; v.y += p.y; v.z += p.z; v.w += p.w;
    }
    *(float4*)&g_ctx[bh * (DHEAD*DHEAD) + idx] = v;
}

// ---------------------------------------------------------------------------
// M_b^T (fp16) = (blockdiag(ctx_b / S) @ W_out)^T
// ---------------------------------------------------------------------------
__global__ __launch_bounds__(256, 4)
void make_M_kernel(const float* __restrict__ W_out)
{
    const int nt = blockIdx.x;
    const int bh = blockIdx.y;
    const int b = bh >> 4;
    const int h = bh & 15;
    const int tid = threadIdx.x;

    __shared__ float cst[DHEAD][DHEAD + 1];  // cst[d2][d] = ctx[d][d2]
    __shared__ float ws[DHEAD][DHEAD + 4];
    __shared__ float invs[DHEAD];

    if (tid < 64) invs[tid] = 1.f / g_S[b * DIM + h * DHEAD + tid];
    for (int i = tid; i < DHEAD * DHEAD; i += 256) {
        int d = i >> 6, d2 = i & 63;
        cst[d2][d] = g_ctx[bh * (DHEAD*DHEAD) + i];
    }
    for (int i = tid; i < DHEAD * DHEAD; i += 256) {
        int k2 = i >> 6, c = i & 63;
        ws[k2][c] = W_out[(long)(h * DHEAD + k2) * DIM + nt * DHEAD + c];
    }
    __syncthreads();

    const int dd0 = (tid >> 4) * 4;
    const int c0 = (tid & 15) * 4;
    float acc[4][4];
    #pragma unroll
    for (int i = 0; i < 4; i++)
        #pragma unroll
        for (int j = 0; j < 4; j++) acc[i][j] = 0.f;

    #pragma unroll 8
    for (int k2 = 0; k2 < DHEAD; ++k2) {
        float ar[4], br[4];
        ar[0] = cst[k2][dd0 + 0];
        ar[1] = cst[k2][dd0 + 1];
        ar[2] = cst[k2][dd0 + 2];
        ar[3] = cst[k2][dd0 + 3];
        *(float4*)br = *(const float4*)&ws[k2][c0];
        #pragma unroll
        for (int i = 0; i < 4; i++)
            #pragma unroll
            for (int j = 0; j < 4; j++)
                acc[i][j] += ar[i] * br[j];
    }

    // normalize rows by S, write transposed fp16: Mh[b][nt*64+c][h*64+d]
    #pragma unroll
    for (int j = 0; j < 4; ++j) {
        long rowb = (long)b * DIM * DIM + (long)(nt * 64 + c0 + j) * DIM + h * 64 + dd0;
        *(__half2*)&g_Mh[rowb]     = __floats2half2_rn(acc[0][j] * invs[dd0+0], acc[1][j] * invs[dd0+1]);
        *(__half2*)&g_Mh[rowb + 2] = __floats2half2_rn(acc[2][j] * invs[dd0+2], acc[3][j] * invs[dd0+3]);
    }
}

// ---------------------------------------------------------------------------
// Launch
// ---------------------------------------------------------------------------
extern "C" void kernel_launch(void* const* d_in, const int* in_sizes, int n_in,
                              void* d_out, int out_size)
{
    const float* feats = (const float*)d_in[0];   // [2,4096,1024]
    const float* W_qkv = (const float*)d_in[1];   // [1024,3072]
    const float* W_out = (const float*)d_in[2];   // [1024,1024]
    float* out = (float*)d_out;                   // [2,4096,1024]

    cudaFuncSetAttribute(hgemm_kernel<0>, cudaFuncAttributeMaxDynamicSharedMemorySize, HG_SMEM);
    cudaFuncSetAttribute(hgemm_kernel<1>, cudaFuncAttributeMaxDynamicSharedMemorySize, HG_SMEM);

    __half* featsh; cudaGetSymbolAddress((void**)&featsh, g_featsh);
    __half* Wt;     cudaGetSymbolAddress((void**)&Wt, g_Wt);
    __half* qh;     cudaGetSymbolAddress((void**)&qh, g_qh);
    __half* Mh;     cudaGetSymbolAddress((void**)&Mh, g_Mh);

    // 0) conversions + S reset
    zero_S_kernel<<<(B * DIM) / 256, 256>>>();
    f2h_kernel<<<(M_ROWS * DIM / 4) / 256, 256>>>(feats);
    wtrans_kernel<<<dim3(QKV_COLS / 32, DIM / 32), 256>>>(W_qkv);

    // 1) fused qkv GEMM: writes g_qh (softmaxed q'), g_ekh (exp k) + g_S, g_vh
    hgemm_kernel<0><<<dim3(QKV_COLS / HG_BN, M_ROWS / HG_BM, 1), 256, HG_SMEM>>>(
        featsh, Wt, nullptr, DIM, DIM, DIM, 0, 0, 0, 0);

    // 2) context partials + reduce
    ctx_partial_kernel<<<dim3(8, 32), 256>>>();
    ctx_reduce_kernel<<<dim3(32, 4), 256>>>();

    // 3) M_b^T fp16 = (blockdiag(ctx/S) @ W_out)^T
    make_M_kernel<<<dim3(16, 32), 256>>>(W_out);

    // 4) out = q' @ M_b (batched over b)
    hgemm_kernel<1><<<dim3(DIM / HG_BN, N_SEQ / HG_BM, B), 256, HG_SMEM>>>(
        qh, Mh, out, DIM, DIM, DIM, DIM,
        (long)N_SEQ * DIM, (long)DIM * DIM, (long)N_SEQ * DIM);
}

// round 6
// speedup vs baseline: 5.6776x; 1.0813x over previous
#include <cuda_runtime.h>
#include <cuda_fp16.h>
#include <cstdint>
#include <math.h>

// Problem constants
#define B 2
#define N_SEQ 4096
#define DIM 1024
#define HEADS 16
#define DHEAD 64
#define M_ROWS (B * N_SEQ)        // 8192
#define QKV_COLS (3 * DIM)        // 3072
#define NCHUNK 32                 // ctx n-chunks

// ---------------------------------------------------------------------------
// Scratch (device globals)
// ---------------------------------------------------------------------------
__device__ __half g_featsh[(size_t)M_ROWS * DIM];        // feats fp16
__device__ __half g_Wt[(size_t)QKV_COLS * DIM];          // W_qkv^T fp16 [3072][1024]
__device__ __half g_qh[(size_t)M_ROWS * DIM];            // q' (softmaxed*scale) fp16
__device__ __half g_ekh[(size_t)M_ROWS * DIM];           // exp(k) fp16
__device__ __half g_vh[(size_t)M_ROWS * DIM];            // v fp16
__device__ __half g_Mh[(size_t)B * DIM * DIM];           // M_b^T fp16
__device__ float  g_S[B * DIM];                          // colsum exp(k)
__device__ float  g_ctxp[NCHUNK * 32 * DHEAD * DHEAD];
__device__ float  g_ctx[32 * DHEAD * DHEAD];

// ---------------------------------------------------------------------------
// Helpers
// ---------------------------------------------------------------------------
__device__ __forceinline__ uint32_t smem_u32(const void* p) {
    uint32_t a;
    asm("{ .reg .u64 t; cvta.to.shared.u64 t, %1; cvt.u32.u64 %0, t; }" : "=r"(a) : "l"(p));
    return a;
}
#define CP_ASYNC16(smem, g) \
    asm volatile("cp.async.cg.shared.global [%0], [%1], 16;" :: "r"((uint32_t)(smem)), "l"(g) : "memory")
#define CP_COMMIT() asm volatile("cp.async.commit_group;" ::: "memory")
template <int N> __device__ __forceinline__ void cp_wait() {
    asm volatile("cp.async.wait_group %0;" :: "n"(N) : "memory");
}
#define SWZ(x) ((x) ^ (((x) >> 3) & 0x70))

#define LDSM_X4(r0, r1, r2, r3, addr) \
    asm volatile("ldmatrix.sync.aligned.m8n8.x4.shared.b16 {%0,%1,%2,%3}, [%4];" \
                 : "=r"(r0), "=r"(r1), "=r"(r2), "=r"(r3) : "r"(addr))

#define MMA16816(c0, c1, c2, c3, a0, a1, a2, a3, b0, b1) \
    asm volatile("mma.sync.aligned.m16n8k16.row.col.f32.f16.f16.f32 " \
                 "{%0,%1,%2,%3}, {%4,%5,%6,%7}, {%8,%9}, {%0,%1,%2,%3};" \
                 : "+f"(c0), "+f"(c1), "+f"(c2), "+f"(c3) \
                 : "r"(a0), "r"(a1), "r"(a2), "r"(a3), "r"(b0), "r"(b1))

// ---------------------------------------------------------------------------
// HMMA fp16 GEMM: 128x128 tile, K-chunk 64, 3-stage cp.async, 96KB smem,
// 2 CTAs/SM. 8 warps in 4(M) x 2(N); warp tile 32x64 (full head per warp).
// MODE 0: qkv fused epilogue (softmax-q / exp-k+colsum / v), fp16 outputs.
// MODE 1: plain fp32 C store.
// ---------------------------------------------------------------------------
#define HG_BM 128
#define HG_BN 128
#define STG_A (HG_BM * 128)            // 16 KB
#define STG_B (HG_BN * 128)            // 16 KB
#define STG_BYTES (STG_A + STG_B)      // 32 KB
#define HG_STAGES 3
#define HG_SMEM (HG_STAGES * STG_BYTES)  // 96 KB

template <int MODE>
__global__ __launch_bounds__(256, 2)
void hgemm_kernel(const __half* __restrict__ A, const __half* __restrict__ Bh,
                  float* __restrict__ C, int K, int lda, int ldb, int ldc,
                  long aB, long bB, long cB)
{
    A  += (long)blockIdx.z * aB;
    Bh += (long)blockIdx.z * bB;
    if (MODE == 1) C += (long)blockIdx.z * cB;

    extern __shared__ char smem[];
    const uint32_t sbase = smem_u32(smem);
    const int tid  = threadIdx.x;
    const int wid  = tid >> 5;
    const int lane = tid & 31;
    const int wm = wid >> 1;           // 0..3 (32 rows each)
    const int wn = wid & 1;            // 0..1 (64 cols each)
    const int bm = blockIdx.y * HG_BM;
    const int bn = blockIdx.x * HG_BN;
    const int NC = K >> 6;

    const int ldr = tid >> 3;          // 0..31
    const int ldc16 = tid & 7;

    auto load_chunk = [&](int kc, int st) {
        const uint32_t sa = sbase + st * STG_BYTES;
        const uint32_t sb = sa + STG_A;
        const __half* ap = A + (long)bm * lda + kc * 64;
        const __half* bp = Bh + (long)bn * ldb + kc * 64;
        #pragma unroll
        for (int i = 0; i < 4; ++i) {
            int r = ldr + i * 32;
            CP_ASYNC16(sa + SWZ(r * 128 + ldc16 * 16), ap + (long)r * lda + ldc16 * 8);
        }
        #pragma unroll
        for (int i = 0; i < 4; ++i) {
            int r = ldr + i * 32;
            CP_ASYNC16(sb + SWZ(r * 128 + ldc16 * 16), bp + (long)r * ldb + ldc16 * 8);
        }
    };

    float acc[2][8][4];
    #pragma unroll
    for (int i = 0; i < 2; i++)
        #pragma unroll
        for (int j = 0; j < 8; j++)
            #pragma unroll
            for (int x = 0; x < 4; x++) acc[i][j][x] = 0.f;

    load_chunk(0, 0); CP_COMMIT();
    load_chunk(1, 1); CP_COMMIT();

    const int lrow = lane & 15;
    const int lsel = lane >> 4;

    // Precomputed swizzle pieces: addr = stage_base + row*128 + ((cc ^ (lrow&7))*16)
    // (row*128 has bits >=7; (lrow&7) are bits 7-9 of row*128 >> 3 -> xor into bits 4-6)
    uint32_t a_row[2], b_row[4], ksel[4];
    #pragma unroll
    for (int mt = 0; mt < 2; ++mt) a_row[mt] = (uint32_t)(wm * 32 + mt * 16 + lrow) * 128;
    #pragma unroll
    for (int np = 0; np < 4; ++np) b_row[np] = (uint32_t)(wn * 64 + np * 16 + lrow) * 128;
    #pragma unroll
    for (int ks = 0; ks < 4; ++ks) ksel[ks] = (uint32_t)(((2 * ks + lsel) ^ (lrow & 7)) * 16);

    for (int c = 0; c < NC; ++c) {
        const int st = c % HG_STAGES;
        cp_wait<1>();
        __syncthreads();
        if (c + 2 < NC) load_chunk(c + 2, (c + 2) % HG_STAGES);
        CP_COMMIT();

        const uint32_t sa = sbase + st * STG_BYTES;
        const uint32_t sb = sa + STG_A;

        #pragma unroll
        for (int ks = 0; ks < 4; ++ks) {
            uint32_t af[2][4];
            #pragma unroll
            for (int mt = 0; mt < 2; ++mt)
                LDSM_X4(af[mt][0], af[mt][1], af[mt][2], af[mt][3], sa + a_row[mt] + ksel[ks]);
            uint32_t bf[4][4];
            #pragma unroll
            for (int np = 0; np < 4; ++np)
                LDSM_X4(bf[np][0], bf[np][1], bf[np][2], bf[np][3], sb + b_row[np] + ksel[ks]);
            #pragma unroll
            for (int mt = 0; mt < 2; ++mt) {
                #pragma unroll
                for (int np = 0; np < 4; ++np) {
                    MMA16816(acc[mt][2*np][0], acc[mt][2*np][1], acc[mt][2*np][2], acc[mt][2*np][3],
                             af[mt][0], af[mt][1], af[mt][2], af[mt][3],
                             bf[np][0], bf[np][2]);
                    MMA16816(acc[mt][2*np+1][0], acc[mt][2*np+1][1], acc[mt][2*np+1][2], acc[mt][2*np+1][3],
                             af[mt][0], af[mt][1], af[mt][2], af[mt][3],
                             bf[np][1], bf[np][3]);
                }
            }
        }
        __syncthreads();
    }

    // ------------------------- epilogue -------------------------
    const int r_base = bm + wm * 32;
    const int cq = (lane & 3) * 2;

    if (MODE == 1) {
        #pragma unroll
        for (int mt = 0; mt < 2; ++mt) {
            int r0 = r_base + mt * 16 + (lane >> 2);
            #pragma unroll
            for (int nt = 0; nt < 8; ++nt) {
                int col = bn + wn * 64 + nt * 8 + cq;
                *(float2*)&C[(long)r0 * ldc + col]       = make_float2(acc[mt][nt][0], acc[mt][nt][1]);
                *(float2*)&C[(long)(r0 + 8) * ldc + col] = make_float2(acc[mt][nt][2], acc[mt][nt][3]);
            }
        }
    } else {
        const int region = bn >> 10;               // 0=q, 1=k, 2=v
        const int bidb = bm >> 12;                 // batch
        if (region == 0) {
            // softmax over the warp's 64 cols (= one head) per row, *0.125
            #pragma unroll
            for (int mt = 0; mt < 2; ++mt) {
                #pragma unroll
                for (int hf = 0; hf < 2; ++hf) {
                    int row = r_base + mt * 16 + (lane >> 2) + 8 * hf;
                    float mx = -1e30f;
                    #pragma unroll
                    for (int nt = 0; nt < 8; ++nt)
                        mx = fmaxf(mx, fmaxf(acc[mt][nt][2*hf], acc[mt][nt][2*hf+1]));
                    mx = fmaxf(mx, __shfl_xor_sync(0xFFFFFFFFu, mx, 1));
                    mx = fmaxf(mx, __shfl_xor_sync(0xFFFFFFFFu, mx, 2));
                    float s = 0.f;
                    #pragma unroll
                    for (int nt = 0; nt < 8; ++nt) {
                        float e0 = __expf(acc[mt][nt][2*hf]   - mx);
                        float e1 = __expf(acc[mt][nt][2*hf+1] - mx);
                        acc[mt][nt][2*hf] = e0; acc[mt][nt][2*hf+1] = e1;
                        s += e0 + e1;
                    }
                    s += __shfl_xor_sync(0xFFFFFFFFu, s, 1);
                    s += __shfl_xor_sync(0xFFFFFFFFu, s, 2);
                    float inv = 0.125f / s;
                    #pragma unroll
                    for (int nt = 0; nt < 8; ++nt) {
                        int col = bn + wn * 64 + nt * 8 + cq;
                        *(__half2*)&g_qh[(long)row * DIM + col] =
                            __floats2half2_rn(acc[mt][nt][2*hf] * inv, acc[mt][nt][2*hf+1] * inv);
                    }
                }
            }
        } else if (region == 1) {
            const int coff = bn - 1024;
            float cs[8][2];
            #pragma unroll
            for (int nt = 0; nt < 8; ++nt) { cs[nt][0] = 0.f; cs[nt][1] = 0.f; }
            #pragma unroll
            for (int mt = 0; mt < 2; ++mt) {
                int r0 = r_base + mt * 16 + (lane >> 2);
                #pragma unroll
                for (int nt = 0; nt < 8; ++nt) {
                    float e0 = __expf(acc[mt][nt][0]);
                    float e1 = __expf(acc[mt][nt][1]);
                    float e2 = __expf(acc[mt][nt][2]);
                    float e3 = __expf(acc[mt][nt][3]);
                    cs[nt][0] += e0 + e2;
                    cs[nt][1] += e1 + e3;
                    int col = coff + wn * 64 + nt * 8 + cq;
                    *(__half2*)&g_ekh[(long)r0 * DIM + col]       = __floats2half2_rn(e0, e1);
                    *(__half2*)&g_ekh[(long)(r0 + 8) * DIM + col] = __floats2half2_rn(e2, e3);
                }
            }
            #pragma unroll
            for (int nt = 0; nt < 8; ++nt) {
                #pragma unroll
                for (int j = 0; j < 2; ++j) {
                    float cc = cs[nt][j];
                    cc += __shfl_xor_sync(0xFFFFFFFFu, cc, 4);
                    cc += __shfl_xor_sync(0xFFFFFFFFu, cc, 8);
                    cc += __shfl_xor_sync(0xFFFFFFFFu, cc, 16);
                    if (lane < 4)
                        atomicAdd(&g_S[bidb * DIM + coff + wn * 64 + nt * 8 + cq + j], cc);
                }
            }
        } else {
            const int coff = bn - 2048;
            #pragma unroll
            for (int mt = 0; mt < 2; ++mt) {
                int r0 = r_base + mt * 16 + (lane >> 2);
                #pragma unroll
                for (int nt = 0; nt < 8; ++nt) {
                    int col = coff + wn * 64 + nt * 8 + cq;
                    *(__half2*)&g_vh[(long)r0 * DIM + col]       = __floats2half2_rn(acc[mt][nt][0], acc[mt][nt][1]);
                    *(__half2*)&g_vh[(long)(r0 + 8) * DIM + col] = __floats2half2_rn(acc[mt][nt][2], acc[mt][nt][3]);
                }
            }
        }
    }
}

// ---------------------------------------------------------------------------
// Small kernels
// ---------------------------------------------------------------------------
__global__ void zero_S_kernel() { g_S[blockIdx.x * 256 + threadIdx.x] = 0.f; }

__global__ void f2h_kernel(const float* __restrict__ in)
{
    long i = (long)blockIdx.x * 256 + threadIdx.x;
    float4 f = ((const float4*)in)[i];
    ((__half2*)g_featsh)[2 * i]     = __floats2half2_rn(f.x, f.y);
    ((__half2*)g_featsh)[2 * i + 1] = __floats2half2_rn(f.z, f.w);
}

__global__ void wtrans_kernel(const float* __restrict__ W)
{
    __shared__ float t[32][33];
    const int n0 = blockIdx.x * 32, k0 = blockIdx.y * 32;
    const int tx = threadIdx.x & 31, ty = threadIdx.x >> 5;
    #pragma unroll
    for (int j = 0; j < 4; ++j)
        t[ty + 8 * j][tx] = W[(long)(k0 + ty + 8 * j) * QKV_COLS + n0 + tx];
    __syncthreads();
    #pragma unroll
    for (int j = 0; j < 4; ++j)
        g_Wt[(long)(n0 + ty + 8 * j) * DIM + k0 + tx] = __float2half_rn(t[tx][ty + 8 * j]);
}

// ---------------------------------------------------------------------------
// Partial context: ctxp[d][e] += ek[n,d]*v[n,e] over 128-row chunk
// grid (NCHUNK, 32 bh)
// ---------------------------------------------------------------------------
__global__ __launch_bounds__(256, 4)
void ctx_partial_kernel()
{
    const int chunk = blockIdx.x;
    const int bh = blockIdx.y;
    const int b = bh >> 4;
    const int h = bh & 15;

    __shared__ float ek[32][DHEAD];
    __shared__ float sv[32][DHEAD];

    const int tid = threadIdx.x;
    const int d0 = (tid >> 4) * 4;
    const int e0 = (tid & 15) * 4;
    const int lr = tid >> 3;
    const int lc8 = (tid & 7) * 8;

    float acc[4][4];
    #pragma unroll
    for (int i = 0; i < 4; i++)
        #pragma unroll
        for (int j = 0; j < 4; j++) acc[i][j] = 0.f;

    const long rowbase = (long)b * N_SEQ;
    const int hc = h * DHEAD;

    for (int t = 0; t < 4; ++t) {               // 4 tiles of 32 rows = 128
        long m = rowbase + chunk * 128 + t * 32 + lr;
        {
            uint4 raw = *(const uint4*)&g_ekh[m * DIM + hc + lc8];
            const __half2* ph = (const __half2*)&raw;
            #pragma unroll
            for (int u = 0; u < 4; ++u) {
                float2 f = __half22float2(ph[u]);
                ek[lr][lc8 + 2*u] = f.x; ek[lr][lc8 + 2*u + 1] = f.y;
            }
        }
        {
            uint4 raw = *(const uint4*)&g_vh[m * DIM + hc + lc8];
            const __half2* ph = (const __half2*)&raw;
            #pragma unroll
            for (int u = 0; u < 4; ++u) {
                float2 f = __half22float2(ph[u]);
                sv[lr][lc8 + 2*u] = f.x; sv[lr][lc8 + 2*u + 1] = f.y;
            }
        }
        __syncthreads();
        #pragma unroll
        for (int kk = 0; kk < 32; ++kk) {
            float ar[4], br[4];
            *(float4*)ar = *(const float4*)&ek[kk][d0];
            *(float4*)br = *(const float4*)&sv[kk][e0];
            #pragma unroll
            for (int i = 0; i < 4; i++)
                #pragma unroll
                for (int j = 0; j < 4; j++)
                    acc[i][j] += ar[i] * br[j];
        }
        __syncthreads();
    }

    float* outp = g_ctxp + ((long)chunk * 32 + bh) * (DHEAD * DHEAD);
    #pragma unroll
    for (int i = 0; i < 4; i++)
        *(float4*)&outp[(d0 + i) * DHEAD + e0] =
            make_float4(acc[i][0], acc[i][1], acc[i][2], acc[i][3]);
}

// reduce NCHUNK partials. grid (32 bh, 4), 256 threads x float4.
__global__ void ctx_reduce_kernel()
{
    const int bh = blockIdx.x;
    const int idx = blockIdx.y * 1024 + threadIdx.x * 4;
    float4 v = make_float4(0.f, 0.f, 0.f, 0.f);
    #pragma unroll
    for (int c = 0; c < NCHUNK; ++c) {
        float4 p = *(const float4*)&g_ctxp[((long)c * 32 + bh) * (DHEAD*DHEAD) + idx];
        v.x += p.x; v.y += p.y; v.z += p.z; v.w += p.w;
    }
    *(float4*)&g_ctx[bh * (DHEAD*DHEAD) + idx] = v;
}

// ---------------------------------------------------------------------------
// M_b^T (fp16) = (blockdiag(ctx_b / S) @ W_out)^T
// ---------------------------------------------------------------------------
__global__ __launch_bounds__(256, 4)
void make_M_kernel(const float* __restrict__ W_out)
{
    const int nt = blockIdx.x;
    const int bh = blockIdx.y;
    const int b = bh >> 4;
    const int h = bh & 15;
    const int tid = threadIdx.x;

    __shared__ float cst[DHEAD][DHEAD + 1];
    __shared__ float ws[DHEAD][DHEAD + 4];
    __shared__ float invs[DHEAD];

    if (tid < 64) invs[tid] = 1.f / g_S[b * DIM + h * DHEAD + tid];
    for (int i = tid; i < DHEAD * DHEAD; i += 256) {
        int d = i >> 6, d2 = i & 63;
        cst[d2][d] = g_ctx[bh * (DHEAD*DHEAD) + i];
    }
    for (int i = tid; i < DHEAD * DHEAD; i += 256) {
        int k2 = i >> 6, c = i & 63;
        ws[k2][c] = W_out[(long)(h * DHEAD + k2) * DIM + nt * DHEAD + c];
    }
    __syncthreads();

    const int dd0 = (tid >> 4) * 4;
    const int c0 = (tid & 15) * 4;
    float acc[4][4];
    #pragma unroll
    for (int i = 0; i < 4; i++)
        #pragma unroll
        for (int j = 0; j < 4; j++) acc[i][j] = 0.f;

    #pragma unroll 8
    for (int k2 = 0; k2 < DHEAD; ++k2) {
        float ar[4], br[4];
        ar[0] = cst[k2][dd0 + 0];
        ar[1] = cst[k2][dd0 + 1];
        ar[2] = cst[k2][dd0 + 2];
        ar[3] = cst[k2][dd0 + 3];
        *(float4*)br = *(const float4*)&ws[k2][c0];
        #pragma unroll
        for (int i = 0; i < 4; i++)
            #pragma unroll
            for (int j = 0; j < 4; j++)
                acc[i][j] += ar[i] * br[j];
    }

    #pragma unroll
    for (int j = 0; j < 4; ++j) {
        long rowb = (long)b * DIM * DIM + (long)(nt * 64 + c0 + j) * DIM + h * 64 + dd0;
        *(__half2*)&g_Mh[rowb]     = __floats2half2_rn(acc[0][j] * invs[dd0+0], acc[1][j] * invs[dd0+1]);
        *(__half2*)&g_Mh[rowb + 2] = __floats2half2_rn(acc[2][j] * invs[dd0+2], acc[3][j] * invs[dd0+3]);
    }
}

// ---------------------------------------------------------------------------
// Launch
// ---------------------------------------------------------------------------
extern "C" void kernel_launch(void* const* d_in, const int* in_sizes, int n_in,
                              void* d_out, int out_size)
{
    const float* feats = (const float*)d_in[0];
    const float* W_qkv = (const float*)d_in[1];
    const float* W_out = (const float*)d_in[2];
    float* out = (float*)d_out;

    cudaFuncSetAttribute(hgemm_kernel<0>, cudaFuncAttributeMaxDynamicSharedMemorySize, HG_SMEM);
    cudaFuncSetAttribute(hgemm_kernel<1>, cudaFuncAttributeMaxDynamicSharedMemorySize, HG_SMEM);

    __half* featsh; cudaGetSymbolAddress((void**)&featsh, g_featsh);
    __half* Wt;     cudaGetSymbolAddress((void**)&Wt, g_Wt);
    __half* qh;     cudaGetSymbolAddress((void**)&qh, g_qh);
    __half* Mh;     cudaGetSymbolAddress((void**)&Mh, g_Mh);

    zero_S_kernel<<<(B * DIM) / 256, 256>>>();
    f2h_kernel<<<(M_ROWS * DIM / 4) / 256, 256>>>(feats);
    wtrans_kernel<<<dim3(QKV_COLS / 32, DIM / 32), 256>>>(W_qkv);

    // 1) fused qkv GEMM
    hgemm_kernel<0><<<dim3(QKV_COLS / HG_BN, M_ROWS / HG_BM, 1), 256, HG_SMEM>>>(
        featsh, Wt, nullptr, DIM, DIM, DIM, 0, 0, 0, 0);

    // 2) context partials + reduce
    ctx_partial_kernel<<<dim3(NCHUNK, 32), 256>>>();
    ctx_reduce_kernel<<<dim3(32, 4), 256>>>();

    // 3) M_b^T fp16
    make_M_kernel<<<dim3(16, 32), 256>>>(W_out);

    // 4) out = q' @ M_b
    hgemm_kernel<1><<<dim3(DIM / HG_BN, N_SEQ / HG_BM, B), 256, HG_SMEM>>>(
        qh, Mh, out, DIM, DIM, DIM, DIM,
        (long)N_SEQ * DIM, (long)DIM * DIM, (long)N_SEQ * DIM);
}

// round 7
// speedup vs baseline: 5.7333x; 1.0098x over previous
#include <cuda_runtime.h>
#include <cuda_fp16.h>
#include <cstdint>
#include <math.h>

// Problem constants
#define B 2
#define N_SEQ 4096
#define DIM 1024
#define HEADS 16
#define DHEAD 64
#define M_ROWS (B * N_SEQ)        // 8192
#define QKV_COLS (3 * DIM)        // 3072
#define NCHUNK 32                 // ctx n-chunks

// ---------------------------------------------------------------------------
// Scratch (device globals)
// ---------------------------------------------------------------------------
__device__ __half g_featsh[(size_t)M_ROWS * DIM];        // feats fp16
__device__ __half g_Wt[(size_t)QKV_COLS * DIM];          // W_qkv^T fp16 [3072][1024]
__device__ __half g_qh[(size_t)M_ROWS * DIM];            // q' (softmaxed*scale) fp16
__device__ __half g_ekh[(size_t)M_ROWS * DIM];           // exp(k) fp16
__device__ __half g_vh[(size_t)M_ROWS * DIM];            // v fp16
__device__ __half g_Mh[(size_t)B * DIM * DIM];           // M_b^T fp16
__device__ float  g_S[B * DIM];                          // colsum exp(k)
__device__ float  g_ctxp[NCHUNK * 32 * DHEAD * DHEAD];
__device__ float  g_ctx[32 * DHEAD * DHEAD];

// ---------------------------------------------------------------------------
// Helpers
// ---------------------------------------------------------------------------
__device__ __forceinline__ uint32_t smem_u32(const void* p) {
    uint32_t a;
    asm("{ .reg .u64 t; cvta.to.shared.u64 t, %1; cvt.u32.u64 %0, t; }" : "=r"(a) : "l"(p));
    return a;
}
#define CP_ASYNC16(smem, g) \
    asm volatile("cp.async.cg.shared.global [%0], [%1], 16;" :: "r"((uint32_t)(smem)), "l"(g) : "memory")
#define CP_COMMIT() asm volatile("cp.async.commit_group;" ::: "memory")
template <int N> __device__ __forceinline__ void cp_wait() {
    asm volatile("cp.async.wait_group %0;" :: "n"(N) : "memory");
}

#define LDSM_X4(r0, r1, r2, r3, addr) \
    asm volatile("ldmatrix.sync.aligned.m8n8.x4.shared.b16 {%0,%1,%2,%3}, [%4];" \
                 : "=r"(r0), "=r"(r1), "=r"(r2), "=r"(r3) : "r"(addr))

#define MMA16816(c0, c1, c2, c3, a0, a1, a2, a3, b0, b1) \
    asm volatile("mma.sync.aligned.m16n8k16.row.col.f32.f16.f16.f32 " \
                 "{%0,%1,%2,%3}, {%4,%5,%6,%7}, {%8,%9}, {%0,%1,%2,%3};" \
                 : "+f"(c0), "+f"(c1), "+f"(c2), "+f"(c3) \
                 : "r"(a0), "r"(a1), "r"(a2), "r"(a3), "r"(b0), "r"(b1))

// ---------------------------------------------------------------------------
// HMMA fp16 GEMM: 128x128 CTA tile, 4 warps (128 thr), warp tile 64x64.
// K-chunk 64, 3-stage cp.async (96 KB), 2 CTAs/SM, 256-reg budget.
// MODE 0: qkv fused epilogue (softmax-q / exp-k+colsum / v), fp16 outputs.
// MODE 1: plain fp32 C store.
// ---------------------------------------------------------------------------
#define HG_BM 128
#define HG_BN 128
#define STG_A (HG_BM * 128)            // 16 KB
#define STG_B (HG_BN * 128)            // 16 KB
#define STG_BYTES (STG_A + STG_B)      // 32 KB
#define HG_STAGES 3
#define HG_SMEM (HG_STAGES * STG_BYTES)  // 96 KB

template <int MODE>
__global__ __launch_bounds__(128, 2)
void hgemm_kernel(const __half* __restrict__ A, const __half* __restrict__ Bh,
                  float* __restrict__ C, int K, int lda, int ldb, int ldc,
                  long aB, long bB, long cB)
{
    A  += (long)blockIdx.z * aB;
    Bh += (long)blockIdx.z * bB;
    if (MODE == 1) C += (long)blockIdx.z * cB;

    extern __shared__ char smem[];
    const uint32_t sbase = smem_u32(smem);
    const int tid  = threadIdx.x;
    const int wid  = tid >> 5;
    const int lane = tid & 31;
    const int wm = wid >> 1;           // 0..1 (64 rows each)
    const int wn = wid & 1;            // 0..1 (64 cols each)
    const int bm = blockIdx.y * HG_BM;
    const int bn = blockIdx.x * HG_BN;
    const int NC = K >> 6;

    // ---- cp.async mapping: 128 thr, 8 ops each per operand ----
    // slot t+128i: row = (t>>3)+16i, col16 = t&7 ; swizzle xor is loop-invariant
    const int r0   = tid >> 3;          // 0..15
    const int c16  = tid & 7;
    const uint32_t offLd = (uint32_t)(r0 * 128 + ((c16 ^ (r0 & 7)) * 16));  // +i*2048
    const __half* apg = A + (long)(bm + r0) * lda + c16 * 8;
    const __half* bpg = Bh + (long)(bn + r0) * ldb + c16 * 8;
    const long strideA = (long)16 * lda;
    const long strideB = (long)16 * ldb;

    auto load_chunk = [&](int kc, int st) {
        const uint32_t sa = sbase + st * STG_BYTES + offLd;
        const uint32_t sb = sa + STG_A;
        const __half* ap = apg + kc * 64;
        const __half* bp = bpg + kc * 64;
        #pragma unroll
        for (int i = 0; i < 8; ++i) {
            CP_ASYNC16(sa + i * 2048, ap);
            ap += strideA;
        }
        #pragma unroll
        for (int i = 0; i < 8; ++i) {
            CP_ASYNC16(sb + i * 2048, bp);
            bp += strideB;
        }
    };

    float acc[4][8][4];
    #pragma unroll
    for (int i = 0; i < 4; i++)
        #pragma unroll
        for (int j = 0; j < 8; j++)
            #pragma unroll
            for (int x = 0; x < 4; x++) acc[i][j][x] = 0.f;

    load_chunk(0, 0); CP_COMMIT();
    load_chunk(1, 1); CP_COMMIT();

    const int lrow = lane & 15;
    const int lsel = lane >> 4;

    // ldsm addresses: addr = stage_base + row*128 + ((cc ^ (lrow&7))*16)
    uint32_t a_row[4], b_row[4], ksel[4];
    #pragma unroll
    for (int mt = 0; mt < 4; ++mt) a_row[mt] = (uint32_t)(wm * 64 + mt * 16 + lrow) * 128;
    #pragma unroll
    for (int np = 0; np < 4; ++np) b_row[np] = (uint32_t)(wn * 64 + np * 16 + lrow) * 128;
    #pragma unroll
    for (int ks = 0; ks < 4; ++ks) ksel[ks] = (uint32_t)(((2 * ks + lsel) ^ (lrow & 7)) * 16);

    for (int c = 0; c < NC; ++c) {
        const int st = c % HG_STAGES;
        cp_wait<1>();
        __syncthreads();
        if (c + 2 < NC) load_chunk(c + 2, (c + 2) % HG_STAGES);
        CP_COMMIT();

        const uint32_t sa = sbase + st * STG_BYTES;
        const uint32_t sb = sa + STG_A;

        #pragma unroll
        for (int ks = 0; ks < 4; ++ks) {
            uint32_t af[4][4];
            #pragma unroll
            for (int mt = 0; mt < 4; ++mt)
                LDSM_X4(af[mt][0], af[mt][1], af[mt][2], af[mt][3], sa + a_row[mt] + ksel[ks]);
            uint32_t bf[4][4];
            #pragma unroll
            for (int np = 0; np < 4; ++np)
                LDSM_X4(bf[np][0], bf[np][1], bf[np][2], bf[np][3], sb + b_row[np] + ksel[ks]);
            #pragma unroll
            for (int mt = 0; mt < 4; ++mt) {
                #pragma unroll
                for (int np = 0; np < 4; ++np) {
                    MMA16816(acc[mt][2*np][0], acc[mt][2*np][1], acc[mt][2*np][2], acc[mt][2*np][3],
                             af[mt][0], af[mt][1], af[mt][2], af[mt][3],
                             bf[np][0], bf[np][2]);
                    MMA16816(acc[mt][2*np+1][0], acc[mt][2*np+1][1], acc[mt][2*np+1][2], acc[mt][2*np+1][3],
                             af[mt][0], af[mt][1], af[mt][2], af[mt][3],
                             bf[np][1], bf[np][3]);
                }
            }
        }
    }

    // ------------------------- epilogue -------------------------
    const int r_base = bm + wm * 64;
    const int cq = (lane & 3) * 2;

    if (MODE == 1) {
        #pragma unroll
        for (int mt = 0; mt < 4; ++mt) {
            int r0e = r_base + mt * 16 + (lane >> 2);
            #pragma unroll
            for (int nt = 0; nt < 8; ++nt) {
                int col = bn + wn * 64 + nt * 8 + cq;
                *(float2*)&C[(long)r0e * ldc + col]       = make_float2(acc[mt][nt][0], acc[mt][nt][1]);
                *(float2*)&C[(long)(r0e + 8) * ldc + col] = make_float2(acc[mt][nt][2], acc[mt][nt][3]);
            }
        }
    } else {
        const int region = bn >> 10;               // 0=q, 1=k, 2=v
        const int bidb = bm >> 12;                 // batch
        if (region == 0) {
            // softmax over the warp's 64 cols (= one head) per row, *0.125
            #pragma unroll
            for (int mt = 0; mt < 4; ++mt) {
                #pragma unroll
                for (int hf = 0; hf < 2; ++hf) {
                    int row = r_base + mt * 16 + (lane >> 2) + 8 * hf;
                    float mx = -1e30f;
                    #pragma unroll
                    for (int nt = 0; nt < 8; ++nt)
                        mx = fmaxf(mx, fmaxf(acc[mt][nt][2*hf], acc[mt][nt][2*hf+1]));
                    mx = fmaxf(mx, __shfl_xor_sync(0xFFFFFFFFu, mx, 1));
                    mx = fmaxf(mx, __shfl_xor_sync(0xFFFFFFFFu, mx, 2));
                    float s = 0.f;
                    #pragma unroll
                    for (int nt = 0; nt < 8; ++nt) {
                        float e0 = __expf(acc[mt][nt][2*hf]   - mx);
                        float e1 = __expf(acc[mt][nt][2*hf+1] - mx);
                        acc[mt][nt][2*hf] = e0; acc[mt][nt][2*hf+1] = e1;
                        s += e0 + e1;
                    }
                    s += __shfl_xor_sync(0xFFFFFFFFu, s, 1);
                    s += __shfl_xor_sync(0xFFFFFFFFu, s, 2);
                    float inv = 0.125f / s;
                    #pragma unroll
                    for (int nt = 0; nt < 8; ++nt) {
                        int col = bn + wn * 64 + nt * 8 + cq;
                        *(__half2*)&g_qh[(long)row * DIM + col] =
                            __floats2half2_rn(acc[mt][nt][2*hf] * inv, acc[mt][nt][2*hf+1] * inv);
                    }
                }
            }
        } else if (region == 1) {
            const int coff = bn - 1024;
            float cs[8][2];
            #pragma unroll
            for (int nt = 0; nt < 8; ++nt) { cs[nt][0] = 0.f; cs[nt][1] = 0.f; }
            #pragma unroll
            for (int mt = 0; mt < 4; ++mt) {
                int r0e = r_base + mt * 16 + (lane >> 2);
                #pragma unroll
                for (int nt = 0; nt < 8; ++nt) {
                    float e0 = __expf(acc[mt][nt][0]);
                    float e1 = __expf(acc[mt][nt][1]);
                    float e2 = __expf(acc[mt][nt][2]);
                    float e3 = __expf(acc[mt][nt][3]);
                    cs[nt][0] += e0 + e2;
                    cs[nt][1] += e1 + e3;
                    int col = coff + wn * 64 + nt * 8 + cq;
                    *(__half2*)&g_ekh[(long)r0e * DIM + col]       = __floats2half2_rn(e0, e1);
                    *(__half2*)&g_ekh[(long)(r0e + 8) * DIM + col] = __floats2half2_rn(e2, e3);
                }
            }
            #pragma unroll
            for (int nt = 0; nt < 8; ++nt) {
                #pragma unroll
                for (int j = 0; j < 2; ++j) {
                    float cc = cs[nt][j];
                    cc += __shfl_xor_sync(0xFFFFFFFFu, cc, 4);
                    cc += __shfl_xor_sync(0xFFFFFFFFu, cc, 8);
                    cc += __shfl_xor_sync(0xFFFFFFFFu, cc, 16);
                    if (lane < 4)
                        atomicAdd(&g_S[bidb * DIM + coff + wn * 64 + nt * 8 + cq + j], cc);
                }
            }
        } else {
            const int coff = bn - 2048;
            #pragma unroll
            for (int mt = 0; mt < 4; ++mt) {
                int r0e = r_base + mt * 16 + (lane >> 2);
                #pragma unroll
                for (int nt = 0; nt < 8; ++nt) {
                    int col = coff + wn * 64 + nt * 8 + cq;
                    *(__half2*)&g_vh[(long)r0e * DIM + col]       = __floats2half2_rn(acc[mt][nt][0], acc[mt][nt][1]);
                    *(__half2*)&g_vh[(long)(r0e + 8) * DIM + col] = __floats2half2_rn(acc[mt][nt][2], acc[mt][nt][3]);
                }
            }
        }
    }
}

// ---------------------------------------------------------------------------
// Small kernels
// ---------------------------------------------------------------------------
__global__ void zero_S_kernel() { g_S[blockIdx.x * 256 + threadIdx.x] = 0.f; }

__global__ void f2h_kernel(const float* __restrict__ in)
{
    long i = (long)blockIdx.x * 256 + threadIdx.x;
    float4 f = ((const float4*)in)[i];
    ((__half2*)g_featsh)[2 * i]     = __floats2half2_rn(f.x, f.y);
    ((__half2*)g_featsh)[2 * i + 1] = __floats2half2_rn(f.z, f.w);
}

__global__ void wtrans_kernel(const float* __restrict__ W)
{
    __shared__ float t[32][33];
    const int n0 = blockIdx.x * 32, k0 = blockIdx.y * 32;
    const int tx = threadIdx.x & 31, ty = threadIdx.x >> 5;
    #pragma unroll
    for (int j = 0; j < 4; ++j)
        t[ty + 8 * j][tx] = W[(long)(k0 + ty + 8 * j) * QKV_COLS + n0 + tx];
    __syncthreads();
    #pragma unroll
    for (int j = 0; j < 4; ++j)
        g_Wt[(long)(n0 + ty + 8 * j) * DIM + k0 + tx] = __float2half_rn(t[tx][ty + 8 * j]);
}

// ---------------------------------------------------------------------------
// Partial context: ctxp[d][e] += ek[n,d]*v[n,e] over 128-row chunk
// grid (NCHUNK, 32 bh)
// ---------------------------------------------------------------------------
__global__ __launch_bounds__(256, 4)
void ctx_partial_kernel()
{
    const int chunk = blockIdx.x;
    const int bh = blockIdx.y;
    const int b = bh >> 4;
    const int h = bh & 15;

    __shared__ float ek[32][DHEAD];
    __shared__ float sv[32][DHEAD];

    const int tid = threadIdx.x;
    const int d0 = (tid >> 4) * 4;
    const int e0 = (tid & 15) * 4;
    const int lr = tid >> 3;
    const int lc8 = (tid & 7) * 8;

    float acc[4][4];
    #pragma unroll
    for (int i = 0; i < 4; i++)
        #pragma unroll
        for (int j = 0; j < 4; j++) acc[i][j] = 0.f;

    const long rowbase = (long)b * N_SEQ;
    const int hc = h * DHEAD;

    for (int t = 0; t < 4; ++t) {
        long m = rowbase + chunk * 128 + t * 32 + lr;
        {
            uint4 raw = *(const uint4*)&g_ekh[m * DIM + hc + lc8];
            const __half2* ph = (const __half2*)&raw;
            #pragma unroll
            for (int u = 0; u < 4; ++u) {
                float2 f = __half22float2(ph[u]);
                ek[lr][lc8 + 2*u] = f.x; ek[lr][lc8 + 2*u + 1] = f.y;
            }
        }
        {
            uint4 raw = *(const uint4*)&g_vh[m * DIM + hc + lc8];
            const __half2* ph = (const __half2*)&raw;
            #pragma unroll
            for (int u = 0; u < 4; ++u) {
                float2 f = __half22float2(ph[u]);
                sv[lr][lc8 + 2*u] = f.x; sv[lr][lc8 + 2*u + 1] = f.y;
            }
        }
        __syncthreads();
        #pragma unroll
        for (int kk = 0; kk < 32; ++kk) {
            float ar[4], br[4];
            *(float4*)ar = *(const float4*)&ek[kk][d0];
            *(float4*)br = *(const float4*)&sv[kk][e0];
            #pragma unroll
            for (int i = 0; i < 4; i++)
                #pragma unroll
                for (int j = 0; j < 4; j++)
                    acc[i][j] += ar[i] * br[j];
        }
        __syncthreads();
    }

    float* outp = g_ctxp + ((long)chunk * 32 + bh) * (DHEAD * DHEAD);
    #pragma unroll
    for (int i = 0; i < 4; i++)
        *(float4*)&outp[(d0 + i) * DHEAD + e0] =
            make_float4(acc[i][0], acc[i][1], acc[i][2], acc[i][3]);
}

// reduce NCHUNK partials. grid (32 bh, 4), 256 threads x float4.
__global__ void ctx_reduce_kernel()
{
    const int bh = blockIdx.x;
    const int idx = blockIdx.y * 1024 + threadIdx.x * 4;
    float4 v = make_float4(0.f, 0.f, 0.f, 0.f);
    #pragma unroll
    for (int c = 0; c < NCHUNK; ++c) {
        float4 p = *(const float4*)&g_ctxp[((long)c * 32 + bh) * (DHEAD*DHEAD) + idx];
        v.x += p.x; v.y += p.y; v.z += p.z; v.w += p.w;
    }
    *(float4*)&g_ctx[bh * (DHEAD*DHEAD) + idx] = v;
}

// ---------------------------------------------------------------------------
// M_b^T (fp16) = (blockdiag(ctx_b / S) @ W_out)^T
// ---------------------------------------------------------------------------
__global__ __launch_bounds__(256, 4)
void make_M_kernel(const float* __restrict__ W_out)
{
    const int nt = blockIdx.x;
    const int bh = blockIdx.y;
    const int b = bh >> 4;
    const int h = bh & 15;
    const int tid = threadIdx.x;

    __shared__ float cst[DHEAD][DHEAD + 1];
    __shared__ float ws[DHEAD][DHEAD + 4];
    __shared__ float invs[DHEAD];

    if (tid < 64) invs[tid] = 1.f / g_S[b * DIM + h * DHEAD + tid];
    for (int i = tid; i < DHEAD * DHEAD; i += 256) {
        int d = i >> 6, d2 = i & 63;
        cst[d2][d] = g_ctx[bh * (DHEAD*DHEAD) + i];
    }
    for (int i = tid; i < DHEAD * DHEAD; i += 256) {
        int k2 = i >> 6, c = i & 63;
        ws[k2][c] = W_out[(long)(h * DHEAD + k2) * DIM + nt * DHEAD + c];
    }
    __syncthreads();

    const int dd0 = (tid >> 4) * 4;
    const int c0 = (tid & 15) * 4;
    float acc[4][4];
    #pragma unroll
    for (int i = 0; i < 4; i++)
        #pragma unroll
        for (int j = 0; j < 4; j++) acc[i][j] = 0.f;

    #pragma unroll 8
    for (int k2 = 0; k2 < DHEAD; ++k2) {
        float ar[4], br[4];
        ar[0] = cst[k2][dd0 + 0];
        ar[1] = cst[k2][dd0 + 1];
        ar[2] = cst[k2][dd0 + 2];
        ar[3] = cst[k2][dd0 + 3];
        *(float4*)br = *(const float4*)&ws[k2][c0];
        #pragma unroll
        for (int i = 0; i < 4; i++)
            #pragma unroll
            for (int j = 0; j < 4; j++)
                acc[i][j] += ar[i] * br[j];
    }

    #pragma unroll
    for (int j = 0; j < 4; ++j) {
        long rowb = (long)b * DIM * DIM + (long)(nt * 64 + c0 + j) * DIM + h * 64 + dd0;
        *(__half2*)&g_Mh[rowb]     = __floats2half2_rn(acc[0][j] * invs[dd0+0], acc[1][j] * invs[dd0+1]);
        *(__half2*)&g_Mh[rowb + 2] = __floats2half2_rn(acc[2][j] * invs[dd0+2], acc[3][j] * invs[dd0+3]);
    }
}

// ---------------------------------------------------------------------------
// Launch
// ---------------------------------------------------------------------------
extern "C" void kernel_launch(void* const* d_in, const int* in_sizes, int n_in,
                              void* d_out, int out_size)
{
    const float* feats = (const float*)d_in[0];
    const float* W_qkv = (const float*)d_in[1];
    const float* W_out = (const float*)d_in[2];
    float* out = (float*)d_out;

    cudaFuncSetAttribute(hgemm_kernel<0>, cudaFuncAttributeMaxDynamicSharedMemorySize, HG_SMEM);
    cudaFuncSetAttribute(hgemm_kernel<1>, cudaFuncAttributeMaxDynamicSharedMemorySize, HG_SMEM);

    __half* featsh; cudaGetSymbolAddress((void**)&featsh, g_featsh);
    __half* Wt;     cudaGetSymbolAddress((void**)&Wt, g_Wt);
    __half* qh;     cudaGetSymbolAddress((void**)&qh, g_qh);
    __half* Mh;     cudaGetSymbolAddress((void**)&Mh, g_Mh);

    zero_S_kernel<<<(B * DIM) / 256, 256>>>();
    f2h_kernel<<<(M_ROWS * DIM / 4) / 256, 256>>>(feats);
    wtrans_kernel<<<dim3(QKV_COLS / 32, DIM / 32), 256>>>(W_qkv);

    // 1) fused qkv GEMM
    hgemm_kernel<0><<<dim3(QKV_COLS / HG_BN, M_ROWS / HG_BM, 1), 128, HG_SMEM>>>(
        featsh, Wt, nullptr, DIM, DIM, DIM, 0, 0, 0, 0);

    // 2) context partials + reduce
    ctx_partial_kernel<<<dim3(NCHUNK, 32), 256>>>();
    ctx_reduce_kernel<<<dim3(32, 4), 256>>>();

    // 3) M_b^T fp16
    make_M_kernel<<<dim3(16, 32), 256>>>(W_out);

    // 4) out = q' @ M_b
    hgemm_kernel<1><<<dim3(DIM / HG_BN, N_SEQ / HG_BM, B), 128, HG_SMEM>>>(
        qh, Mh, out, DIM, DIM, DIM, DIM,
        (long)N_SEQ * DIM, (long)DIM * DIM, (long)N_SEQ * DIM);
}

// round 8
// speedup vs baseline: 5.7486x; 1.0027x over previous
#include <cuda_runtime.h>
#include <cuda_fp16.h>
#include <cstdint>
#include <math.h>

// Problem constants
#define B 2
#define N_SEQ 4096
#define DIM 1024
#define HEADS 16
#define DHEAD 64
#define M_ROWS (B * N_SEQ)        // 8192
#define QKV_COLS (3 * DIM)        // 3072
#define NCHUNK 32                 // ctx n-chunks

// ---------------------------------------------------------------------------
// Scratch (device globals)
// ---------------------------------------------------------------------------
__device__ __half g_featsh[(size_t)M_ROWS * DIM];        // feats fp16
__device__ __half g_Wt[(size_t)QKV_COLS * DIM];          // W_qkv^T fp16 [3072][1024]
__device__ __half g_qh[(size_t)M_ROWS * DIM];            // q' (softmaxed*scale) fp16
__device__ __half g_ekh[(size_t)M_ROWS * DIM];           // exp(k) fp16
__device__ __half g_vh[(size_t)M_ROWS * DIM];            // v fp16
__device__ __half g_Mh[(size_t)B * DIM * DIM];           // M_b^T fp16
__device__ float  g_S[B * DIM];                          // colsum exp(k)
__device__ float  g_ctxp[NCHUNK * 32 * DHEAD * DHEAD];
__device__ float  g_ctx[32 * DHEAD * DHEAD];

// ---------------------------------------------------------------------------
// Helpers
// ---------------------------------------------------------------------------
__device__ __forceinline__ uint32_t smem_u32(const void* p) {
    uint32_t a;
    asm("{ .reg .u64 t; cvta.to.shared.u64 t, %1; cvt.u32.u64 %0, t; }" : "=r"(a) : "l"(p));
    return a;
}
#define CP_ASYNC16(smem, g) \
    asm volatile("cp.async.cg.shared.global [%0], [%1], 16;" :: "r"((uint32_t)(smem)), "l"(g) : "memory")
#define CP_COMMIT() asm volatile("cp.async.commit_group;" ::: "memory")
template <int N> __device__ __forceinline__ void cp_wait() {
    asm volatile("cp.async.wait_group %0;" :: "n"(N) : "memory");
}

#define LDSM_X4(r0, r1, r2, r3, addr) \
    asm volatile("ldmatrix.sync.aligned.m8n8.x4.shared.b16 {%0,%1,%2,%3}, [%4];" \
                 : "=r"(r0), "=r"(r1), "=r"(r2), "=r"(r3) : "r"(addr))

#define MMA16816(c0, c1, c2, c3, a0, a1, a2, a3, b0, b1) \
    asm volatile("mma.sync.aligned.m16n8k16.row.col.f32.f16.f16.f32 " \
                 "{%0,%1,%2,%3}, {%4,%5,%6,%7}, {%8,%9}, {%0,%1,%2,%3};" \
                 : "+f"(c0), "+f"(c1), "+f"(c2), "+f"(c3) \
                 : "r"(a0), "r"(a1), "r"(a2), "r"(a3), "r"(b0), "r"(b1))

// ---------------------------------------------------------------------------
// HMMA fp16 GEMM: 128x128 CTA tile, 4 warps (128 thr), warp tile 64x64.
// K-chunk 64, 3-stage cp.async (96 KB), 2 CTAs/SM.
// Fragment double-buffering: LDSM for ks+1 issued before MMAs of ks.
// MODE 0: qkv fused epilogue (softmax-q / exp-k+colsum / v), fp16 outputs.
// MODE 1: plain fp32 C store.
// ---------------------------------------------------------------------------
#define HG_BM 128
#define HG_BN 128
#define STG_A (HG_BM * 128)            // 16 KB
#define STG_B (HG_BN * 128)            // 16 KB
#define STG_BYTES (STG_A + STG_B)      // 32 KB
#define HG_STAGES 3
#define HG_SMEM (HG_STAGES * STG_BYTES)  // 96 KB

template <int MODE>
__global__ __launch_bounds__(128, 2)
void hgemm_kernel(const __half* __restrict__ A, const __half* __restrict__ Bh,
                  float* __restrict__ C, int K, int lda, int ldb, int ldc,
                  long aB, long bB, long cB)
{
    A  += (long)blockIdx.z * aB;
    Bh += (long)blockIdx.z * bB;
    if (MODE == 1) C += (long)blockIdx.z * cB;

    extern __shared__ char smem[];
    const uint32_t sbase = smem_u32(smem);
    const int tid  = threadIdx.x;
    const int wid  = tid >> 5;
    const int lane = tid & 31;
    const int wm = wid >> 1;           // 0..1 (64 rows each)
    const int wn = wid & 1;            // 0..1 (64 cols each)
    const int bm = blockIdx.y * HG_BM;
    const int bn = blockIdx.x * HG_BN;
    const int NC = K >> 6;

    // ---- cp.async mapping: 128 thr, 8 ops each per operand ----
    const int r0   = tid >> 3;          // 0..15
    const int c16  = tid & 7;
    const uint32_t offLd = (uint32_t)(r0 * 128 + ((c16 ^ (r0 & 7)) * 16));  // +i*2048
    const __half* apg = A + (long)(bm + r0) * lda + c16 * 8;
    const __half* bpg = Bh + (long)(bn + r0) * ldb + c16 * 8;
    const long strideA = (long)16 * lda;
    const long strideB = (long)16 * ldb;

    auto load_chunk = [&](int kc, int st) {
        const uint32_t sa = sbase + st * STG_BYTES + offLd;
        const uint32_t sb = sa + STG_A;
        const __half* ap = apg + kc * 64;
        const __half* bp = bpg + kc * 64;
        #pragma unroll
        for (int i = 0; i < 8; ++i) {
            CP_ASYNC16(sa + i * 2048, ap);
            ap += strideA;
        }
        #pragma unroll
        for (int i = 0; i < 8; ++i) {
            CP_ASYNC16(sb + i * 2048, bp);
            bp += strideB;
        }
    };

    float acc[4][8][4];
    #pragma unroll
    for (int i = 0; i < 4; i++)
        #pragma unroll
        for (int j = 0; j < 8; j++)
            #pragma unroll
            for (int x = 0; x < 4; x++) acc[i][j][x] = 0.f;

    load_chunk(0, 0); CP_COMMIT();
    load_chunk(1, 1); CP_COMMIT();

    const int lrow = lane & 15;
    const int lsel = lane >> 4;

    // ldsm addresses: addr = stage_base + row*128 + ((cc ^ (lrow&7))*16)
    uint32_t a_row[4], b_row[4], ksel[4];
    #pragma unroll
    for (int mt = 0; mt < 4; ++mt) a_row[mt] = (uint32_t)(wm * 64 + mt * 16 + lrow) * 128;
    #pragma unroll
    for (int np = 0; np < 4; ++np) b_row[np] = (uint32_t)(wn * 64 + np * 16 + lrow) * 128;
    #pragma unroll
    for (int ks = 0; ks < 4; ++ks) ksel[ks] = (uint32_t)(((2 * ks + lsel) ^ (lrow & 7)) * 16);

    // double-buffered fragments
    uint32_t af[2][4][4], bf[2][4][4];

    for (int c = 0; c < NC; ++c) {
        const int st = c % HG_STAGES;
        cp_wait<1>();
        __syncthreads();
        if (c + 2 < NC) load_chunk(c + 2, (c + 2) % HG_STAGES);
        CP_COMMIT();

        const uint32_t sa = sbase + st * STG_BYTES;
        const uint32_t sb = sa + STG_A;

        // load fragments for ks = 0 into buffer 0
        #pragma unroll
        for (int mt = 0; mt < 4; ++mt)
            LDSM_X4(af[0][mt][0], af[0][mt][1], af[0][mt][2], af[0][mt][3], sa + a_row[mt] + ksel[0]);
        #pragma unroll
        for (int np = 0; np < 4; ++np)
            LDSM_X4(bf[0][np][0], bf[0][np][1], bf[0][np][2], bf[0][np][3], sb + b_row[np] + ksel[0]);

        #pragma unroll
        for (int ks = 0; ks < 4; ++ks) {
            const int cur = ks & 1;
            const int nxt = cur ^ 1;
            if (ks < 3) {
                // prefetch fragments for ks+1 (hidden under MMAs below)
                #pragma unroll
                for (int mt = 0; mt < 4; ++mt)
                    LDSM_X4(af[nxt][mt][0], af[nxt][mt][1], af[nxt][mt][2], af[nxt][mt][3],
                            sa + a_row[mt] + ksel[ks + 1]);
                #pragma unroll
                for (int np = 0; np < 4; ++np)
                    LDSM_X4(bf[nxt][np][0], bf[nxt][np][1], bf[nxt][np][2], bf[nxt][np][3],
                            sb + b_row[np] + ksel[ks + 1]);
            }
            #pragma unroll
            for (int mt = 0; mt < 4; ++mt) {
                #pragma unroll
                for (int np = 0; np < 4; ++np) {
                    MMA16816(acc[mt][2*np][0], acc[mt][2*np][1], acc[mt][2*np][2], acc[mt][2*np][3],
                             af[cur][mt][0], af[cur][mt][1], af[cur][mt][2], af[cur][mt][3],
                             bf[cur][np][0], bf[cur][np][2]);
                    MMA16816(acc[mt][2*np+1][0], acc[mt][2*np+1][1], acc[mt][2*np+1][2], acc[mt][2*np+1][3],
                             af[cur][mt][0], af[cur][mt][1], af[cur][mt][2], af[cur][mt][3],
                             bf[cur][np][1], bf[cur][np][3]);
                }
            }
        }
    }

    // ------------------------- epilogue -------------------------
    const int r_base = bm + wm * 64;
    const int cq = (lane & 3) * 2;

    if (MODE == 1) {
        #pragma unroll
        for (int mt = 0; mt < 4; ++mt) {
            int r0e = r_base + mt * 16 + (lane >> 2);
            #pragma unroll
            for (int nt = 0; nt < 8; ++nt) {
                int col = bn + wn * 64 + nt * 8 + cq;
                *(float2*)&C[(long)r0e * ldc + col]       = make_float2(acc[mt][nt][0], acc[mt][nt][1]);
                *(float2*)&C[(long)(r0e + 8) * ldc + col] = make_float2(acc[mt][nt][2], acc[mt][nt][3]);
            }
        }
    } else {
        const int region = bn >> 10;               // 0=q, 1=k, 2=v
        const int bidb = bm >> 12;                 // batch
        if (region == 0) {
            // softmax over the warp's 64 cols (= one head) per row, *0.125
            #pragma unroll
            for (int mt = 0; mt < 4; ++mt) {
                #pragma unroll
                for (int hf = 0; hf < 2; ++hf) {
                    int row = r_base + mt * 16 + (lane >> 2) + 8 * hf;
                    float mx = -1e30f;
                    #pragma unroll
                    for (int nt = 0; nt < 8; ++nt)
                        mx = fmaxf(mx, fmaxf(acc[mt][nt][2*hf], acc[mt][nt][2*hf+1]));
                    mx = fmaxf(mx, __shfl_xor_sync(0xFFFFFFFFu, mx, 1));
                    mx = fmaxf(mx, __shfl_xor_sync(0xFFFFFFFFu, mx, 2));
                    float s = 0.f;
                    #pragma unroll
                    for (int nt = 0; nt < 8; ++nt) {
                        float e0 = __expf(acc[mt][nt][2*hf]   - mx);
                        float e1 = __expf(acc[mt][nt][2*hf+1] - mx);
                        acc[mt][nt][2*hf] = e0; acc[mt][nt][2*hf+1] = e1;
                        s += e0 + e1;
                    }
                    s += __shfl_xor_sync(0xFFFFFFFFu, s, 1);
                    s += __shfl_xor_sync(0xFFFFFFFFu, s, 2);
                    float inv = 0.125f / s;
                    #pragma unroll
                    for (int nt = 0; nt < 8; ++nt) {
                        int col = bn + wn * 64 + nt * 8 + cq;
                        *(__half2*)&g_qh[(long)row * DIM + col] =
                            __floats2half2_rn(acc[mt][nt][2*hf] * inv, acc[mt][nt][2*hf+1] * inv);
                    }
                }
            }
        } else if (region == 1) {
            const int coff = bn - 1024;
            float cs[8][2];
            #pragma unroll
            for (int nt = 0; nt < 8; ++nt) { cs[nt][0] = 0.f; cs[nt][1] = 0.f; }
            #pragma unroll
            for (int mt = 0; mt < 4; ++mt) {
                int r0e = r_base + mt * 16 + (lane >> 2);
                #pragma unroll
                for (int nt = 0; nt < 8; ++nt) {
                    float e0 = __expf(acc[mt][nt][0]);
                    float e1 = __expf(acc[mt][nt][1]);
                    float e2 = __expf(acc[mt][nt][2]);
                    float e3 = __expf(acc[mt][nt][3]);
                    cs[nt][0] += e0 + e2;
                    cs[nt][1] += e1 + e3;
                    int col = coff + wn * 64 + nt * 8 + cq;
                    *(__half2*)&g_ekh[(long)r0e * DIM + col]       = __floats2half2_rn(e0, e1);
                    *(__half2*)&g_ekh[(long)(r0e + 8) * DIM + col] = __floats2half2_rn(e2, e3);
                }
            }
            #pragma unroll
            for (int nt = 0; nt < 8; ++nt) {
                #pragma unroll
                for (int j = 0; j < 2; ++j) {
                    float cc = cs[nt][j];
                    cc += __shfl_xor_sync(0xFFFFFFFFu, cc, 4);
                    cc += __shfl_xor_sync(0xFFFFFFFFu, cc, 8);
                    cc += __shfl_xor_sync(0xFFFFFFFFu, cc, 16);
                    if (lane < 4)
                        atomicAdd(&g_S[bidb * DIM + coff + wn * 64 + nt * 8 + cq + j], cc);
                }
            }
        } else {
            const int coff = bn - 2048;
            #pragma unroll
            for (int mt = 0; mt < 4; ++mt) {
                int r0e = r_base + mt * 16 + (lane >> 2);
                #pragma unroll
                for (int nt = 0; nt < 8; ++nt) {
                    int col = coff + wn * 64 + nt * 8 + cq;
                    *(__half2*)&g_vh[(long)r0e * DIM + col]       = __floats2half2_rn(acc[mt][nt][0], acc[mt][nt][1]);
                    *(__half2*)&g_vh[(long)(r0e + 8) * DIM + col] = __floats2half2_rn(acc[mt][nt][2], acc[mt][nt][3]);
                }
            }
        }
    }
}

// ---------------------------------------------------------------------------
// Small kernels
// ---------------------------------------------------------------------------
__global__ void zero_S_kernel() { g_S[blockIdx.x * 256 + threadIdx.x] = 0.f; }

__global__ void f2h_kernel(const float* __restrict__ in)
{
    long i = (long)blockIdx.x * 256 + threadIdx.x;
    float4 f = ((const float4*)in)[i];
    ((__half2*)g_featsh)[2 * i]     = __floats2half2_rn(f.x, f.y);
    ((__half2*)g_featsh)[2 * i + 1] = __floats2half2_rn(f.z, f.w);
}

__global__ void wtrans_kernel(const float* __restrict__ W)
{
    __shared__ float t[32][33];
    const int n0 = blockIdx.x * 32, k0 = blockIdx.y * 32;
    const int tx = threadIdx.x & 31, ty = threadIdx.x >> 5;
    #pragma unroll
    for (int j = 0; j < 4; ++j)
        t[ty + 8 * j][tx] = W[(long)(k0 + ty + 8 * j) * QKV_COLS + n0 + tx];
    __syncthreads();
    #pragma unroll
    for (int j = 0; j < 4; ++j)
        g_Wt[(long)(n0 + ty + 8 * j) * DIM + k0 + tx] = __float2half_rn(t[tx][ty + 8 * j]);
}

// ---------------------------------------------------------------------------
// Partial context: ctxp[d][e] += ek[n,d]*v[n,e] over 128-row chunk
// grid (NCHUNK, 32 bh)
// ---------------------------------------------------------------------------
__global__ __launch_bounds__(256, 4)
void ctx_partial_kernel()
{
    const int chunk = blockIdx.x;
    const int bh = blockIdx.y;
    const int b = bh >> 4;
    const int h = bh & 15;

    __shared__ float ek[32][DHEAD];
    __shared__ float sv[32][DHEAD];

    const int tid = threadIdx.x;
    const int d0 = (tid >> 4) * 4;
    const int e0 = (tid & 15) * 4;
    const int lr = tid >> 3;
    const int lc8 = (tid & 7) * 8;

    float acc[4][4];
    #pragma unroll
    for (int i = 0; i < 4; i++)
        #pragma unroll
        for (int j = 0; j < 4; j++) acc[i][j] = 0.f;

    const long rowbase = (long)b * N_SEQ;
    const int hc = h * DHEAD;

    for (int t = 0; t < 4; ++t) {
        long m = rowbase + chunk * 128 + t * 32 + lr;
        {
            uint4 raw = *(const uint4*)&g_ekh[m * DIM + hc + lc8];
            const __half2* ph = (const __half2*)&raw;
            #pragma unroll
            for (int u = 0; u < 4; ++u) {
                float2 f = __half22float2(ph[u]);
                ek[lr][lc8 + 2*u] = f.x; ek[lr][lc8 + 2*u + 1] = f.y;
            }
        }
        {
            uint4 raw = *(const uint4*)&g_vh[m * DIM + hc + lc8];
            const __half2* ph = (const __half2*)&raw;
            #pragma unroll
            for (int u = 0; u < 4; ++u) {
                float2 f = __half22float2(ph[u]);
                sv[lr][lc8 + 2*u] = f.x; sv[lr][lc8 + 2*u + 1] = f.y;
            }
        }
        __syncthreads();
        #pragma unroll
        for (int kk = 0; kk < 32; ++kk) {
            float ar[4], br[4];
            *(float4*)ar = *(const float4*)&ek[kk][d0];
            *(float4*)br = *(const float4*)&sv[kk][e0];
            #pragma unroll
            for (int i = 0; i < 4; i++)
                #pragma unroll
                for (int j = 0; j < 4; j++)
                    acc[i][j] += ar[i] * br[j];
        }
        __syncthreads();
    }

    float* outp = g_ctxp + ((long)chunk * 32 + bh) * (DHEAD * DHEAD);
    #pragma unroll
    for (int i = 0; i < 4; i++)
        *(float4*)&outp[(d0 + i) * DHEAD + e0] =
            make_float4(acc[i][0], acc[i][1], acc[i][2], acc[i][3]);
}

// reduce NCHUNK partials. grid (32 bh, 4), 256 threads x float4.
__global__ void ctx_reduce_kernel()
{
    const int bh = blockIdx.x;
    const int idx = blockIdx.y * 1024 + threadIdx.x * 4;
    float4 v = make_float4(0.f, 0.f, 0.f, 0.f);
    #pragma unroll
    for (int c = 0; c < NCHUNK; ++c) {
        float4 p = *(const float4*)&g_ctxp[((long)c * 32 + bh) * (DHEAD*DHEAD) + idx];
        v.x += p.x; v.y += p.y; v.z += p.z; v.w += p.w;
    }
    *(float4*)&g_ctx[bh * (DHEAD*DHEAD) + idx] = v;
}

// ---------------------------------------------------------------------------
// M_b^T (fp16) = (blockdiag(ctx_b / S) @ W_out)^T
// ---------------------------------------------------------------------------
__global__ __launch_bounds__(256, 4)
void make_M_kernel(const float* __restrict__ W_out)
{
    const int nt = blockIdx.x;
    const int bh = blockIdx.y;
    const int b = bh >> 4;
    const int h = bh & 15;
    const int tid = threadIdx.x;

    __shared__ float cst[DHEAD][DHEAD + 1];
    __shared__ float ws[DHEAD][DHEAD + 4];
    __shared__ float invs[DHEAD];

    if (tid < 64) invs[tid] = 1.f / g_S[b * DIM + h * DHEAD + tid];
    for (int i = tid; i < DHEAD * DHEAD; i += 256) {
        int d = i >> 6, d2 = i & 63;
        cst[d2][d] = g_ctx[bh * (DHEAD*DHEAD) + i];
    }
    for (int i = tid; i < DHEAD * DHEAD; i += 256) {
        int k2 = i >> 6, c = i & 63;
        ws[k2][c] = W_out[(long)(h * DHEAD + k2) * DIM + nt * DHEAD + c];
    }
    __syncthreads();

    const int dd0 = (tid >> 4) * 4;
    const int c0 = (tid & 15) * 4;
    float acc[4][4];
    #pragma unroll
    for (int i = 0; i < 4; i++)
        #pragma unroll
        for (int j = 0; j < 4; j++) acc[i][j] = 0.f;

    #pragma unroll 8
    for (int k2 = 0; k2 < DHEAD; ++k2) {
        float ar[4], br[4];
        ar[0] = cst[k2][dd0 + 0];
        ar[1] = cst[k2][dd0 + 1];
        ar[2] = cst[k2][dd0 + 2];
        ar[3] = cst[k2][dd0 + 3];
        *(float4*)br = *(const float4*)&ws[k2][c0];
        #pragma unroll
        for (int i = 0; i < 4; i++)
            #pragma unroll
            for (int j = 0; j < 4; j++)
                acc[i][j] += ar[i] * br[j];
    }

    #pragma unroll
    for (int j = 0; j < 4; ++j) {
        long rowb = (long)b * DIM * DIM + (long)(nt * 64 + c0 + j) * DIM + h * 64 + dd0;
        *(__half2*)&g_Mh[rowb]     = __floats2half2_rn(acc[0][j] * invs[dd0+0], acc[1][j] * invs[dd0+1]);
        *(__half2*)&g_Mh[rowb + 2] = __floats2half2_rn(acc[2][j] * invs[dd0+2], acc[3][j] * invs[dd0+3]);
    }
}

// ---------------------------------------------------------------------------
// Launch
// ---------------------------------------------------------------------------
extern "C" void kernel_launch(void* const* d_in, const int* in_sizes, int n_in,
                              void* d_out, int out_size)
{
    const float* feats = (const float*)d_in[0];
    const float* W_qkv = (const float*)d_in[1];
    const float* W_out = (const float*)d_in[2];
    float* out = (float*)d_out;

    cudaFuncSetAttribute(hgemm_kernel<0>, cudaFuncAttributeMaxDynamicSharedMemorySize, HG_SMEM);
    cudaFuncSetAttribute(hgemm_kernel<1>, cudaFuncAttributeMaxDynamicSharedMemorySize, HG_SMEM);

    __half* featsh; cudaGetSymbolAddress((void**)&featsh, g_featsh);
    __half* Wt;     cudaGetSymbolAddress((void**)&Wt, g_Wt);
    __half* qh;     cudaGetSymbolAddress((void**)&qh, g_qh);
    __half* Mh;     cudaGetSymbolAddress((void**)&Mh, g_Mh);

    zero_S_kernel<<<(B * DIM) / 256, 256>>>();
    f2h_kernel<<<(M_ROWS * DIM / 4) / 256, 256>>>(feats);
    wtrans_kernel<<<dim3(QKV_COLS / 32, DIM / 32), 256>>>(W_qkv);

    // 1) fused qkv GEMM
    hgemm_kernel<0><<<dim3(QKV_COLS / HG_BN, M_ROWS / HG_BM, 1), 128, HG_SMEM>>>(
        featsh, Wt, nullptr, DIM, DIM, DIM, 0, 0, 0, 0);

    // 2) context partials + reduce
    ctx_partial_kernel<<<dim3(NCHUNK, 32), 256>>>();
    ctx_reduce_kernel<<<dim3(32, 4), 256>>>();

    // 3) M_b^T fp16
    make_M_kernel<<<dim3(16, 32), 256>>>(W_out);

    // 4) out = q' @ M_b
    hgemm_kernel<1><<<dim3(DIM / HG_BN, N_SEQ / HG_BM, B), 128, HG_SMEM>>>(
        qh, Mh, out, DIM, DIM, DIM, DIM,
        (long)N_SEQ * DIM, (long)DIM * DIM, (long)N_SEQ * DIM);
}

// round 9
// speedup vs baseline: 6.3758x; 1.1091x over previous
#include <cuda_runtime.h>
#include <cuda_fp16.h>
#include <cstdint>
#include <math.h>

// Problem constants
#define B 2
#define N_SEQ 4096
#define DIM 1024
#define HEADS 16
#define DHEAD 64
#define M_ROWS (B * N_SEQ)        // 8192
#define QKV_COLS (3 * DIM)        // 3072
#define NCHUNK 32                 // ctx n-chunks (128 rows each)

// ---------------------------------------------------------------------------
// Scratch (device globals)
// ---------------------------------------------------------------------------
__device__ __half g_featsh[(size_t)M_ROWS * DIM];        // feats fp16
__device__ __half g_Wt[(size_t)QKV_COLS * DIM];          // W_qkv^T fp16 [3072][1024]
__device__ __half g_qh[(size_t)M_ROWS * DIM];            // q' (softmaxed*scale) fp16
__device__ __half g_ekh[(size_t)M_ROWS * DIM];           // exp(k) fp16
__device__ __half g_vh[(size_t)M_ROWS * DIM];            // v fp16
__device__ __half g_Mh[(size_t)B * DIM * DIM];           // M_b^T fp16
__device__ float  g_S[B * DIM];                          // colsum exp(k)
__device__ float  g_ctxp[NCHUNK * 32 * DHEAD * DHEAD];
__device__ float  g_ctx[32 * DHEAD * DHEAD];

// ---------------------------------------------------------------------------
// Helpers
// ---------------------------------------------------------------------------
__device__ __forceinline__ uint32_t smem_u32(const void* p) {
    uint32_t a;
    asm("{ .reg .u64 t; cvta.to.shared.u64 t, %1; cvt.u32.u64 %0, t; }" : "=r"(a) : "l"(p));
    return a;
}
#define CP_ASYNC16(smem, g) \
    asm volatile("cp.async.cg.shared.global [%0], [%1], 16;" :: "r"((uint32_t)(smem)), "l"(g) : "memory")
#define CP_COMMIT() asm volatile("cp.async.commit_group;" ::: "memory")
template <int N> __device__ __forceinline__ void cp_wait() {
    asm volatile("cp.async.wait_group %0;" :: "n"(N) : "memory");
}
#define SWZ(x) ((x) ^ (((x) >> 3) & 0x70))

#define LDSM_X4(r0, r1, r2, r3, addr) \
    asm volatile("ldmatrix.sync.aligned.m8n8.x4.shared.b16 {%0,%1,%2,%3}, [%4];" \
                 : "=r"(r0), "=r"(r1), "=r"(r2), "=r"(r3) : "r"(addr))

#define LDSM_X4T(r0, r1, r2, r3, addr) \
    asm volatile("ldmatrix.sync.aligned.m8n8.x4.trans.shared.b16 {%0,%1,%2,%3}, [%4];" \
                 : "=r"(r0), "=r"(r1), "=r"(r2), "=r"(r3) : "r"(addr))

#define MMA16816(c0, c1, c2, c3, a0, a1, a2, a3, b0, b1) \
    asm volatile("mma.sync.aligned.m16n8k16.row.col.f32.f16.f16.f32 " \
                 "{%0,%1,%2,%3}, {%4,%5,%6,%7}, {%8,%9}, {%0,%1,%2,%3};" \
                 : "+f"(c0), "+f"(c1), "+f"(c2), "+f"(c3) \
                 : "r"(a0), "r"(a1), "r"(a2), "r"(a3), "r"(b0), "r"(b1))

// ---------------------------------------------------------------------------
// HMMA fp16 GEMM: 128x128 CTA tile, 4 warps, warp tile 64x64, K-chunk 64,
// 3-stage cp.async (96 KB), 2 CTAs/SM, fragment double-buffering.
// MODE 0: qkv fused epilogue (softmax-q / exp-k+colsum / v), fp16 outputs.
// MODE 1: plain fp32 C store.
// ---------------------------------------------------------------------------
#define HG_BM 128
#define HG_BN 128
#define STG_A (HG_BM * 128)            // 16 KB
#define STG_B (HG_BN * 128)            // 16 KB
#define STG_BYTES (STG_A + STG_B)      // 32 KB
#define HG_STAGES 3
#define HG_SMEM (HG_STAGES * STG_BYTES)  // 96 KB

template <int MODE>
__global__ __launch_bounds__(128, 2)
void hgemm_kernel(const __half* __restrict__ A, const __half* __restrict__ Bh,
                  float* __restrict__ C, int K, int lda, int ldb, int ldc,
                  long aB, long bB, long cB)
{
    A  += (long)blockIdx.z * aB;
    Bh += (long)blockIdx.z * bB;
    if (MODE == 1) C += (long)blockIdx.z * cB;

    extern __shared__ char smem[];
    const uint32_t sbase = smem_u32(smem);
    const int tid  = threadIdx.x;
    const int wid  = tid >> 5;
    const int lane = tid & 31;
    const int wm = wid >> 1;           // 0..1 (64 rows)
    const int wn = wid & 1;            // 0..1 (64 cols)
    const int bm = blockIdx.y * HG_BM;
    const int bn = blockIdx.x * HG_BN;
    const int NC = K >> 6;

    const int r0   = tid >> 3;          // 0..15
    const int c16  = tid & 7;
    const uint32_t offLd = (uint32_t)(r0 * 128 + ((c16 ^ (r0 & 7)) * 16));
    const __half* apg = A + (long)(bm + r0) * lda + c16 * 8;
    const __half* bpg = Bh + (long)(bn + r0) * ldb + c16 * 8;
    const long strideA = (long)16 * lda;
    const long strideB = (long)16 * ldb;

    auto load_chunk = [&](int kc, int st) {
        const uint32_t sa = sbase + st * STG_BYTES + offLd;
        const uint32_t sb = sa + STG_A;
        const __half* ap = apg + kc * 64;
        const __half* bp = bpg + kc * 64;
        #pragma unroll
        for (int i = 0; i < 8; ++i) { CP_ASYNC16(sa + i * 2048, ap); ap += strideA; }
        #pragma unroll
        for (int i = 0; i < 8; ++i) { CP_ASYNC16(sb + i * 2048, bp); bp += strideB; }
    };

    float acc[4][8][4];
    #pragma unroll
    for (int i = 0; i < 4; i++)
        #pragma unroll
        for (int j = 0; j < 8; j++)
            #pragma unroll
            for (int x = 0; x < 4; x++) acc[i][j][x] = 0.f;

    load_chunk(0, 0); CP_COMMIT();
    load_chunk(1, 1); CP_COMMIT();

    const int lrow = lane & 15;
    const int lsel = lane >> 4;

    uint32_t a_row[4], b_row[4], ksel[4];
    #pragma unroll
    for (int mt = 0; mt < 4; ++mt) a_row[mt] = (uint32_t)(wm * 64 + mt * 16 + lrow) * 128;
    #pragma unroll
    for (int np = 0; np < 4; ++np) b_row[np] = (uint32_t)(wn * 64 + np * 16 + lrow) * 128;
    #pragma unroll
    for (int ks = 0; ks < 4; ++ks) ksel[ks] = (uint32_t)(((2 * ks + lsel) ^ (lrow & 7)) * 16);

    uint32_t af[2][4][4], bf[2][4][4];

    int st = 0, stl = 2;               // compute stage, load stage (c+2)
    for (int c = 0; c < NC; ++c) {
        cp_wait<1>();
        __syncthreads();
        if (c + 2 < NC) load_chunk(c + 2, stl);
        CP_COMMIT();

        const uint32_t sa = sbase + st * STG_BYTES;
        const uint32_t sb = sa + STG_A;

        #pragma unroll
        for (int mt = 0; mt < 4; ++mt)
            LDSM_X4(af[0][mt][0], af[0][mt][1], af[0][mt][2], af[0][mt][3], sa + a_row[mt] + ksel[0]);
        #pragma unroll
        for (int np = 0; np < 4; ++np)
            LDSM_X4(bf[0][np][0], bf[0][np][1], bf[0][np][2], bf[0][np][3], sb + b_row[np] + ksel[0]);

        #pragma unroll
        for (int ks = 0; ks < 4; ++ks) {
            const int cur = ks & 1;
            const int nxt = cur ^ 1;
            if (ks < 3) {
                #pragma unroll
                for (int mt = 0; mt < 4; ++mt)
                    LDSM_X4(af[nxt][mt][0], af[nxt][mt][1], af[nxt][mt][2], af[nxt][mt][3],
                            sa + a_row[mt] + ksel[ks + 1]);
                #pragma unroll
                for (int np = 0; np < 4; ++np)
                    LDSM_X4(bf[nxt][np][0], bf[nxt][np][1], bf[nxt][np][2], bf[nxt][np][3],
                            sb + b_row[np] + ksel[ks + 1]);
            }
            #pragma unroll
            for (int mt = 0; mt < 4; ++mt) {
                #pragma unroll
                for (int np = 0; np < 4; ++np) {
                    MMA16816(acc[mt][2*np][0], acc[mt][2*np][1], acc[mt][2*np][2], acc[mt][2*np][3],
                             af[cur][mt][0], af[cur][mt][1], af[cur][mt][2], af[cur][mt][3],
                             bf[cur][np][0], bf[cur][np][2]);
                    MMA16816(acc[mt][2*np+1][0], acc[mt][2*np+1][1], acc[mt][2*np+1][2], acc[mt][2*np+1][3],
                             af[cur][mt][0], af[cur][mt][1], af[cur][mt][2], af[cur][mt][3],
                             bf[cur][np][1], bf[cur][np][3]);
                }
            }
        }
        if (++st == HG_STAGES) st = 0;
        if (++stl == HG_STAGES) stl = 0;
    }

    // ------------------------- epilogue -------------------------
    const int r_base = bm + wm * 64;
    const int cq = (lane & 3) * 2;

    if (MODE == 1) {
        #pragma unroll
        for (int mt = 0; mt < 4; ++mt) {
            int r0e = r_base + mt * 16 + (lane >> 2);
            #pragma unroll
            for (int nt = 0; nt < 8; ++nt) {
                int col = bn + wn * 64 + nt * 8 + cq;
                *(float2*)&C[(long)r0e * ldc + col]       = make_float2(acc[mt][nt][0], acc[mt][nt][1]);
                *(float2*)&C[(long)(r0e + 8) * ldc + col] = make_float2(acc[mt][nt][2], acc[mt][nt][3]);
            }
        }
    } else {
        const int region = bn >> 10;               // 0=q, 1=k, 2=v
        const int bidb = bm >> 12;
        if (region == 0) {
            #pragma unroll
            for (int mt = 0; mt < 4; ++mt) {
                #pragma unroll
                for (int hf = 0; hf < 2; ++hf) {
                    int row = r_base + mt * 16 + (lane >> 2) + 8 * hf;
                    float mx = -1e30f;
                    #pragma unroll
                    for (int nt = 0; nt < 8; ++nt)
                        mx = fmaxf(mx, fmaxf(acc[mt][nt][2*hf], acc[mt][nt][2*hf+1]));
                    mx = fmaxf(mx, __shfl_xor_sync(0xFFFFFFFFu, mx, 1));
                    mx = fmaxf(mx, __shfl_xor_sync(0xFFFFFFFFu, mx, 2));
                    float s = 0.f;
                    #pragma unroll
                    for (int nt = 0; nt < 8; ++nt) {
                        float e0 = __expf(acc[mt][nt][2*hf]   - mx);
                        float e1 = __expf(acc[mt][nt][2*hf+1] - mx);
                        acc[mt][nt][2*hf] = e0; acc[mt][nt][2*hf+1] = e1;
                        s += e0 + e1;
                    }
                    s += __shfl_xor_sync(0xFFFFFFFFu, s, 1);
                    s += __shfl_xor_sync(0xFFFFFFFFu, s, 2);
                    float inv = 0.125f / s;
                    #pragma unroll
                    for (int nt = 0; nt < 8; ++nt) {
                        int col = bn + wn * 64 + nt * 8 + cq;
                        *(__half2*)&g_qh[(long)row * DIM + col] =
                            __floats2half2_rn(acc[mt][nt][2*hf] * inv, acc[mt][nt][2*hf+1] * inv);
                    }
                }
            }
        } else if (region == 1) {
            const int coff = bn - 1024;
            float cs[8][2];
            #pragma unroll
            for (int nt = 0; nt < 8; ++nt) { cs[nt][0] = 0.f; cs[nt][1] = 0.f; }
            #pragma unroll
            for (int mt = 0; mt < 4; ++mt) {
                int r0e = r_base + mt * 16 + (lane >> 2);
                #pragma unroll
                for (int nt = 0; nt < 8; ++nt) {
                    float e0 = __expf(acc[mt][nt][0]);
                    float e1 = __expf(acc[mt][nt][1]);
                    float e2 = __expf(acc[mt][nt][2]);
                    float e3 = __expf(acc[mt][nt][3]);
                    cs[nt][0] += e0 + e2;
                    cs[nt][1] += e1 + e3;
                    int col = coff + wn * 64 + nt * 8 + cq;
                    *(__half2*)&g_ekh[(long)r0e * DIM + col]       = __floats2half2_rn(e0, e1);
                    *(__half2*)&g_ekh[(long)(r0e + 8) * DIM + col] = __floats2half2_rn(e2, e3);
                }
            }
            #pragma unroll
            for (int nt = 0; nt < 8; ++nt) {
                #pragma unroll
                for (int j = 0; j < 2; ++j) {
                    float cc = cs[nt][j];
                    cc += __shfl_xor_sync(0xFFFFFFFFu, cc, 4);
                    cc += __shfl_xor_sync(0xFFFFFFFFu, cc, 8);
                    cc += __shfl_xor_sync(0xFFFFFFFFu, cc, 16);
                    if (lane < 4)
                        atomicAdd(&g_S[bidb * DIM + coff + wn * 64 + nt * 8 + cq + j], cc);
                }
            }
        } else {
            const int coff = bn - 2048;
            #pragma unroll
            for (int mt = 0; mt < 4; ++mt) {
                int r0e = r_base + mt * 16 + (lane >> 2);
                #pragma unroll
                for (int nt = 0; nt < 8; ++nt) {
                    int col = coff + wn * 64 + nt * 8 + cq;
                    *(__half2*)&g_vh[(long)r0e * DIM + col]       = __floats2half2_rn(acc[mt][nt][0], acc[mt][nt][1]);
                    *(__half2*)&g_vh[(long)(r0e + 8) * DIM + col] = __floats2half2_rn(acc[mt][nt][2], acc[mt][nt][3]);
                }
            }
        }
    }
}

// ---------------------------------------------------------------------------
// Small kernels
// ---------------------------------------------------------------------------
__global__ void f2h_kernel(const float* __restrict__ in)
{
    long i = (long)blockIdx.x * 256 + threadIdx.x;
    float4 f = ((const float4*)in)[i];
    ((__half2*)g_featsh)[2 * i]     = __floats2half2_rn(f.x, f.y);
    ((__half2*)g_featsh)[2 * i + 1] = __floats2half2_rn(f.z, f.w);
}

// W transpose + fold in S zeroing (runs before hgemm<0> in stream order)
__global__ void wtrans_kernel(const float* __restrict__ W)
{
    if (blockIdx.x < 8 && blockIdx.y == 0)
        g_S[blockIdx.x * 256 + threadIdx.x] = 0.f;

    __shared__ float t[32][33];
    const int n0 = blockIdx.x * 32, k0 = blockIdx.y * 32;
    const int tx = threadIdx.x & 31, ty = threadIdx.x >> 5;
    #pragma unroll
    for (int j = 0; j < 4; ++j)
        t[ty + 8 * j][tx] = W[(long)(k0 + ty + 8 * j) * QKV_COLS + n0 + tx];
    __syncthreads();
    #pragma unroll
    for (int j = 0; j < 4; ++j)
        g_Wt[(long)(n0 + ty + 8 * j) * DIM + k0 + tx] = __float2half_rn(t[tx][ty + 8 * j]);
}

// ---------------------------------------------------------------------------
// HMMA partial context: ctxp[d][e] += sum_n ek[n,d]*v[n,e] over 128-row chunk.
// grid (NCHUNK, 32 bh), 128 threads (4 warps; warp w owns e-range w*16..+16).
// Both operands via ldmatrix.x4.trans (reduction over rows).
// ---------------------------------------------------------------------------
__global__ __launch_bounds__(128, 4)
void ctx_partial_kernel()
{
    const int chunk = blockIdx.x;
    const int bh = blockIdx.y;
    const int b = bh >> 4;
    const int h = bh & 15;

    __shared__ __align__(16) char cs_mem[2 * 128 * 128];   // ek tile + v tile (swizzled)
    const uint32_t ek_base = smem_u32(cs_mem);
    const uint32_t v_base  = ek_base + 128 * 128;

    const int tid = threadIdx.x;
    const int wid = tid >> 5;
    const int lane = tid & 31;

    // ---- load tiles (cp.async): row r=tid>>3 (+16i), col16 = tid&7 ----
    const int r = tid >> 3;
    const int c16 = tid & 7;
    const uint32_t offLd = (uint32_t)(r * 128 + ((c16 ^ (r & 7)) * 16));
    const long gbase = ((long)b * N_SEQ + chunk * 128 + r) * DIM + h * DHEAD + c16 * 8;
    #pragma unroll
    for (int i = 0; i < 8; ++i)
        CP_ASYNC16(ek_base + offLd + i * 2048, g_ekh + gbase + (long)16 * i * DIM);
    #pragma unroll
    for (int i = 0; i < 8; ++i)
        CP_ASYNC16(v_base + offLd + i * 2048, g_vh + gbase + (long)16 * i * DIM);
    CP_COMMIT();
    cp_wait<0>();
    __syncthreads();

    // ---- trans-ldmatrix lane mapping ----
    // g0: src row l7,    col+0 ; g1: src row l7,    col+8
    // g2: src row l7+8,  col+0 ; g3: src row l7+8,  col+8
    const int l7 = lane & 7;
    const int row16 = l7 + ((lane & 16) >> 1);       // source n-row within 16-block
    const int coloff = (lane & 8);                   // 0 or 8 (elements)

    uint32_t aadr[4];                                // ek: d-blocks mt*16
    #pragma unroll
    for (int mt = 0; mt < 4; ++mt)
        aadr[mt] = ek_base + SWZ((uint32_t)(row16 * 128 + (mt * 16 + coloff) * 2));
    uint32_t badr = v_base + SWZ((uint32_t)(row16 * 128 + (wid * 16 + coloff) * 2));

    float acc[4][2][4];
    #pragma unroll
    for (int i = 0; i < 4; i++)
        #pragma unroll
        for (int j = 0; j < 2; j++)
            #pragma unroll
            for (int x = 0; x < 4; x++) acc[i][j][x] = 0.f;

    #pragma unroll
    for (int ks = 0; ks < 8; ++ks) {                 // 8 x 16 n-rows
        const uint32_t koff = (uint32_t)(ks * 2048); // 16 rows * 128B
        uint32_t bfr[4];
        LDSM_X4T(bfr[0], bfr[1], bfr[2], bfr[3], badr + koff);
        #pragma unroll
        for (int mt = 0; mt < 4; ++mt) {
            uint32_t afr[4];
            LDSM_X4T(afr[0], afr[1], afr[2], afr[3], aadr[mt] + koff);
            MMA16816(acc[mt][0][0], acc[mt][0][1], acc[mt][0][2], acc[mt][0][3],
                     afr[0], afr[1], afr[2], afr[3], bfr[0], bfr[2]);
            MMA16816(acc[mt][1][0], acc[mt][1][1], acc[mt][1][2], acc[mt][1][3],
                     afr[0], afr[1], afr[2], afr[3], bfr[1], bfr[3]);
        }
    }

    // ---- store partial [64d][64e] ----
    float* outp = g_ctxp + ((long)chunk * 32 + bh) * (DHEAD * DHEAD);
    const int e0 = wid * 16 + (lane & 3) * 2;
    #pragma unroll
    for (int mt = 0; mt < 4; ++mt) {
        int d0 = mt * 16 + (lane >> 2);
        #pragma unroll
        for (int nt = 0; nt < 2; ++nt) {
            *(float2*)&outp[(d0)     * DHEAD + e0 + nt * 8] = make_float2(acc[mt][nt][0], acc[mt][nt][1]);
            *(float2*)&outp[(d0 + 8) * DHEAD + e0 + nt * 8] = make_float2(acc[mt][nt][2], acc[mt][nt][3]);
        }
    }
}

// reduce NCHUNK partials. grid (32 bh, 4), 256 threads x float4.
__global__ void ctx_reduce_kernel()
{
    const int bh = blockIdx.x;
    const int idx = blockIdx.y * 1024 + threadIdx.x * 4;
    float4 v = make_float4(0.f, 0.f, 0.f, 0.f);
    #pragma unroll
    for (int c = 0; c < NCHUNK; ++c) {
        float4 p = *(const float4*)&g_ctxp[((long)c * 32 + bh) * (DHEAD*DHEAD) + idx];
        v.x += p.x; v.y += p.y; v.z += p.z; v.w += p.w;
    }
    *(float4*)&g_ctx[bh * (DHEAD*DHEAD) + idx] = v;
}

// ---------------------------------------------------------------------------
// M_b^T (fp16) = (blockdiag(ctx_b / S) @ W_out)^T
// ---------------------------------------------------------------------------
__global__ __launch_bounds__(256, 4)
void make_M_kernel(const float* __restrict__ W_out)
{
    const int nt = blockIdx.x;
    const int bh = blockIdx.y;
    const int b = bh >> 4;
    const int h = bh & 15;
    const int tid = threadIdx.x;

    __shared__ float cst[DHEAD][DHEAD + 1];
    __shared__ float ws[DHEAD][DHEAD + 4];
    __shared__ float invs[DHEAD];

    if (tid < 64) invs[tid] = 1.f / g_S[b * DIM + h * DHEAD + tid];
    for (int i = tid; i < DHEAD * DHEAD; i += 256) {
        int d = i >> 6, d2 = i & 63;
        cst[d2][d] = g_ctx[bh * (DHEAD*DHEAD) + i];
    }
    for (int i = tid; i < DHEAD * DHEAD; i += 256) {
        int k2 = i >> 6, c = i & 63;
        ws[k2][c] = W_out[(long)(h * DHEAD + k2) * DIM + nt * DHEAD + c];
    }
    __syncthreads();

    const int dd0 = (tid >> 4) * 4;
    const int c0 = (tid & 15) * 4;
    float acc[4][4];
    #pragma unroll
    for (int i = 0; i < 4; i++)
        #pragma unroll
        for (int j = 0; j < 4; j++) acc[i][j] = 0.f;

    #pragma unroll 8
    for (int k2 = 0; k2 < DHEAD; ++k2) {
        float ar[4], br[4];
        ar[0] = cst[k2][dd0 + 0];
        ar[1] = cst[k2][dd0 + 1];
        ar[2] = cst[k2][dd0 + 2];
        ar[3] = cst[k2][dd0 + 3];
        *(float4*)br = *(const float4*)&ws[k2][c0];
        #pragma unroll
        for (int i = 0; i < 4; i++)
            #pragma unroll
            for (int j = 0; j < 4; j++)
                acc[i][j] += ar[i] * br[j];
    }

    #pragma unroll
    for (int j = 0; j < 4; ++j) {
        long rowb = (long)b * DIM * DIM + (long)(nt * 64 + c0 + j) * DIM + h * 64 + dd0;
        *(__half2*)&g_Mh[rowb]     = __floats2half2_rn(acc[0][j] * invs[dd0+0], acc[1][j] * invs[dd0+1]);
        *(__half2*)&g_Mh[rowb + 2] = __floats2half2_rn(acc[2][j] * invs[dd0+2], acc[3][j] * invs[dd0+3]);
    }
}

// ---------------------------------------------------------------------------
// Launch
// ---------------------------------------------------------------------------
extern "C" void kernel_launch(void* const* d_in, const int* in_sizes, int n_in,
                              void* d_out, int out_size)
{
    const float* feats = (const float*)d_in[0];
    const float* W_qkv = (const float*)d_in[1];
    const float* W_out = (const float*)d_in[2];
    float* out = (float*)d_out;

    cudaFuncSetAttribute(hgemm_kernel<0>, cudaFuncAttributeMaxDynamicSharedMemorySize, HG_SMEM);
    cudaFuncSetAttribute(hgemm_kernel<1>, cudaFuncAttributeMaxDynamicSharedMemorySize, HG_SMEM);

    __half* featsh; cudaGetSymbolAddress((void**)&featsh, g_featsh);
    __half* Wt;     cudaGetSymbolAddress((void**)&Wt, g_Wt);
    __half* qh;     cudaGetSymbolAddress((void**)&qh, g_qh);
    __half* Mh;     cudaGetSymbolAddress((void**)&Mh, g_Mh);

    f2h_kernel<<<(M_ROWS * DIM / 4) / 256, 256>>>(feats);
    wtrans_kernel<<<dim3(QKV_COLS / 32, DIM / 32), 256>>>(W_qkv);

    // 1) fused qkv GEMM
    hgemm_kernel<0><<<dim3(QKV_COLS / HG_BN, M_ROWS / HG_BM, 1), 128, HG_SMEM>>>(
        featsh, Wt, nullptr, DIM, DIM, DIM, 0, 0, 0, 0);

    // 2) context partials (HMMA) + reduce
    ctx_partial_kernel<<<dim3(NCHUNK, 32), 128>>>();
    ctx_reduce_kernel<<<dim3(32, 4), 256>>>();

    // 3) M_b^T fp16
    make_M_kernel<<<dim3(16, 32), 256>>>(W_out);

    // 4) out = q' @ M_b
    hgemm_kernel<1><<<dim3(DIM / HG_BN, N_SEQ / HG_BM, B), 128, HG_SMEM>>>(
        qh, Mh, out, DIM, DIM, DIM, DIM,
        (long)N_SEQ * DIM, (long)DIM * DIM, (long)N_SEQ * DIM);
}

// round 10
// speedup vs baseline: 6.4617x; 1.0135x over previous
#include <cuda_runtime.h>
#include <cuda_fp16.h>
#include <cstdint>
#include <math.h>

// Problem constants
#define B 2
#define N_SEQ 4096
#define DIM 1024
#define HEADS 16
#define DHEAD 64
#define M_ROWS (B * N_SEQ)        // 8192
#define QKV_COLS (3 * DIM)        // 3072
#define MCHUNKS 64                // M_ROWS / 128

// ---------------------------------------------------------------------------
// Scratch (device globals)
// ---------------------------------------------------------------------------
__device__ __half g_featsh[(size_t)M_ROWS * DIM];        // feats fp16
__device__ __half g_Wt[(size_t)QKV_COLS * DIM];          // permuted W_qkv^T fp16
__device__ __half g_qh[(size_t)M_ROWS * DIM];            // q' (softmaxed*scale) fp16
__device__ __half g_Mh[(size_t)B * DIM * DIM];           // M_b^T fp16
__device__ float  g_S[B * DIM];                          // colsum exp(k)
__device__ float  g_ctxp[(size_t)MCHUNKS * HEADS * DHEAD * DHEAD];  // per-chunk partials
__device__ float  g_ctx[32 * DHEAD * DHEAD];

// ---------------------------------------------------------------------------
// Helpers
// ---------------------------------------------------------------------------
__device__ __forceinline__ uint32_t smem_u32(const void* p) {
    uint32_t a;
    asm("{ .reg .u64 t; cvta.to.shared.u64 t, %1; cvt.u32.u64 %0, t; }" : "=r"(a) : "l"(p));
    return a;
}
#define CP_ASYNC16(smem, g) \
    asm volatile("cp.async.cg.shared.global [%0], [%1], 16;" :: "r"((uint32_t)(smem)), "l"(g) : "memory")
#define CP_COMMIT() asm volatile("cp.async.commit_group;" ::: "memory")
template <int N> __device__ __forceinline__ void cp_wait() {
    asm volatile("cp.async.wait_group %0;" :: "n"(N) : "memory");
}
#define SWZ(x) ((x) ^ (((x) >> 3) & 0x70))

#define LDSM_X4(r0, r1, r2, r3, addr) \
    asm volatile("ldmatrix.sync.aligned.m8n8.x4.shared.b16 {%0,%1,%2,%3}, [%4];" \
                 : "=r"(r0), "=r"(r1), "=r"(r2), "=r"(r3) : "r"(addr))

#define LDSM_X4T(r0, r1, r2, r3, addr) \
    asm volatile("ldmatrix.sync.aligned.m8n8.x4.trans.shared.b16 {%0,%1,%2,%3}, [%4];" \
                 : "=r"(r0), "=r"(r1), "=r"(r2), "=r"(r3) : "r"(addr))

#define MMA16816(c0, c1, c2, c3, a0, a1, a2, a3, b0, b1) \
    asm volatile("mma.sync.aligned.m16n8k16.row.col.f32.f16.f16.f32 " \
                 "{%0,%1,%2,%3}, {%4,%5,%6,%7}, {%8,%9}, {%0,%1,%2,%3};" \
                 : "+f"(c0), "+f"(c1), "+f"(c2), "+f"(c3) \
                 : "r"(a0), "r"(a1), "r"(a2), "r"(a3), "r"(b0), "r"(b1))

// ---------------------------------------------------------------------------
// HMMA fp16 GEMM: 128x128 CTA tile, 4 warps, warp tile 64x64, K-chunk 64,
// 3-stage cp.async (96 KB), 2 CTAs/SM, fragment double-buffering.
// MODE 0 (qkv): W columns permuted as [q | (k_h,v_h) per head].
//   bn <  1024 : q epilogue (softmax*scale -> g_qh fp16)
//   bn >= 1024 : head tile [exp(k_h) | v_h]; in-epilogue ctx partial via HMMA
//                -> g_ctxp, colsums -> g_S.
// MODE 1: plain fp32 C store.
// ---------------------------------------------------------------------------
#define HG_BM 128
#define HG_BN 128
#define STG_A (HG_BM * 128)            // 16 KB
#define STG_B (HG_BN * 128)            // 16 KB
#define STG_BYTES (STG_A + STG_B)      // 32 KB
#define HG_STAGES 3
#define HG_SMEM (HG_STAGES * STG_BYTES)  // 96 KB

template <int MODE>
__global__ __launch_bounds__(128, 2)
void hgemm_kernel(const __half* __restrict__ A, const __half* __restrict__ Bh,
                  float* __restrict__ C, int K, int lda, int ldb, int ldc,
                  long aB, long bB, long cB)
{
    A  += (long)blockIdx.z * aB;
    Bh += (long)blockIdx.z * bB;
    if (MODE == 1) C += (long)blockIdx.z * cB;

    extern __shared__ char smem[];
    const uint32_t sbase = smem_u32(smem);
    const int tid  = threadIdx.x;
    const int wid  = tid >> 5;
    const int lane = tid & 31;
    const int wm = wid >> 1;           // 0..1 (64 rows)
    const int wn = wid & 1;            // 0..1 (64 cols)
    const int bm = blockIdx.y * HG_BM;
    const int bn = blockIdx.x * HG_BN;
    const int NC = K >> 6;

    const int r0   = tid >> 3;          // 0..15
    const int c16  = tid & 7;
    const uint32_t offLd = (uint32_t)(r0 * 128 + ((c16 ^ (r0 & 7)) * 16));
    const __half* apg = A + (long)(bm + r0) * lda + c16 * 8;
    const __half* bpg = Bh + (long)(bn + r0) * ldb + c16 * 8;
    const long strideA = (long)16 * lda;
    const long strideB = (long)16 * ldb;

    auto load_chunk = [&](int kc, int st) {
        const uint32_t sa = sbase + st * STG_BYTES + offLd;
        const uint32_t sb = sa + STG_A;
        const __half* ap = apg + kc * 64;
        const __half* bp = bpg + kc * 64;
        #pragma unroll
        for (int i = 0; i < 8; ++i) { CP_ASYNC16(sa + i * 2048, ap); ap += strideA; }
        #pragma unroll
        for (int i = 0; i < 8; ++i) { CP_ASYNC16(sb + i * 2048, bp); bp += strideB; }
    };

    float acc[4][8][4];
    #pragma unroll
    for (int i = 0; i < 4; i++)
        #pragma unroll
        for (int j = 0; j < 8; j++)
            #pragma unroll
            for (int x = 0; x < 4; x++) acc[i][j][x] = 0.f;

    load_chunk(0, 0); CP_COMMIT();
    load_chunk(1, 1); CP_COMMIT();

    const int lrow = lane & 15;
    const int lsel = lane >> 4;

    uint32_t a_row[4], b_row[4], ksel[4];
    #pragma unroll
    for (int mt = 0; mt < 4; ++mt) a_row[mt] = (uint32_t)(wm * 64 + mt * 16 + lrow) * 128;
    #pragma unroll
    for (int np = 0; np < 4; ++np) b_row[np] = (uint32_t)(wn * 64 + np * 16 + lrow) * 128;
    #pragma unroll
    for (int ks = 0; ks < 4; ++ks) ksel[ks] = (uint32_t)(((2 * ks + lsel) ^ (lrow & 7)) * 16);

    uint32_t af[2][4][4], bf[2][4][4];

    int st = 0, stl = 2;
    for (int c = 0; c < NC; ++c) {
        cp_wait<1>();
        __syncthreads();
        if (c + 2 < NC) load_chunk(c + 2, stl);
        CP_COMMIT();

        const uint32_t sa = sbase + st * STG_BYTES;
        const uint32_t sb = sa + STG_A;

        #pragma unroll
        for (int mt = 0; mt < 4; ++mt)
            LDSM_X4(af[0][mt][0], af[0][mt][1], af[0][mt][2], af[0][mt][3], sa + a_row[mt] + ksel[0]);
        #pragma unroll
        for (int np = 0; np < 4; ++np)
            LDSM_X4(bf[0][np][0], bf[0][np][1], bf[0][np][2], bf[0][np][3], sb + b_row[np] + ksel[0]);

        #pragma unroll
        for (int ks = 0; ks < 4; ++ks) {
            const int cur = ks & 1;
            const int nxt = cur ^ 1;
            if (ks < 3) {
                #pragma unroll
                for (int mt = 0; mt < 4; ++mt)
                    LDSM_X4(af[nxt][mt][0], af[nxt][mt][1], af[nxt][mt][2], af[nxt][mt][3],
                            sa + a_row[mt] + ksel[ks + 1]);
                #pragma unroll
                for (int np = 0; np < 4; ++np)
                    LDSM_X4(bf[nxt][np][0], bf[nxt][np][1], bf[nxt][np][2], bf[nxt][np][3],
                            sb + b_row[np] + ksel[ks + 1]);
            }
            #pragma unroll
            for (int mt = 0; mt < 4; ++mt) {
                #pragma unroll
                for (int np = 0; np < 4; ++np) {
                    MMA16816(acc[mt][2*np][0], acc[mt][2*np][1], acc[mt][2*np][2], acc[mt][2*np][3],
                             af[cur][mt][0], af[cur][mt][1], af[cur][mt][2], af[cur][mt][3],
                             bf[cur][np][0], bf[cur][np][2]);
                    MMA16816(acc[mt][2*np+1][0], acc[mt][2*np+1][1], acc[mt][2*np+1][2], acc[mt][2*np+1][3],
                             af[cur][mt][0], af[cur][mt][1], af[cur][mt][2], af[cur][mt][3],
                             bf[cur][np][1], bf[cur][np][3]);
                }
            }
        }
        if (++st == HG_STAGES) st = 0;
        if (++stl == HG_STAGES) stl = 0;
    }

    // ------------------------- epilogue -------------------------
    const int r_base = bm + wm * 64;
    const int cq = (lane & 3) * 2;

    if (MODE == 1) {
        #pragma unroll
        for (int mt = 0; mt < 4; ++mt) {
            int r0e = r_base + mt * 16 + (lane >> 2);
            #pragma unroll
            for (int nt = 0; nt < 8; ++nt) {
                int col = bn + wn * 64 + nt * 8 + cq;
                *(float2*)&C[(long)r0e * ldc + col]       = make_float2(acc[mt][nt][0], acc[mt][nt][1]);
                *(float2*)&C[(long)(r0e + 8) * ldc + col] = make_float2(acc[mt][nt][2], acc[mt][nt][3]);
            }
        }
    } else if (bn < 1024) {
        // ---- q region: softmax over the warp's 64 cols (= one head) ----
        #pragma unroll
        for (int mt = 0; mt < 4; ++mt) {
            #pragma unroll
            for (int hf = 0; hf < 2; ++hf) {
                int row = r_base + mt * 16 + (lane >> 2) + 8 * hf;
                float mx = -1e30f;
                #pragma unroll
                for (int nt = 0; nt < 8; ++nt)
                    mx = fmaxf(mx, fmaxf(acc[mt][nt][2*hf], acc[mt][nt][2*hf+1]));
                mx = fmaxf(mx, __shfl_xor_sync(0xFFFFFFFFu, mx, 1));
                mx = fmaxf(mx, __shfl_xor_sync(0xFFFFFFFFu, mx, 2));
                float s = 0.f;
                #pragma unroll
                for (int nt = 0; nt < 8; ++nt) {
                    float e0 = __expf(acc[mt][nt][2*hf]   - mx);
                    float e1 = __expf(acc[mt][nt][2*hf+1] - mx);
                    acc[mt][nt][2*hf] = e0; acc[mt][nt][2*hf+1] = e1;
                    s += e0 + e1;
                }
                s += __shfl_xor_sync(0xFFFFFFFFu, s, 1);
                s += __shfl_xor_sync(0xFFFFFFFFu, s, 2);
                float inv = 0.125f / s;
                #pragma unroll
                for (int nt = 0; nt < 8; ++nt) {
                    int col = bn + wn * 64 + nt * 8 + cq;
                    *(__half2*)&g_qh[(long)row * DIM + col] =
                        __floats2half2_rn(acc[mt][nt][2*hf] * inv, acc[mt][nt][2*hf+1] * inv);
                }
            }
        }
    } else {
        // ---- kv region: this CTA holds [exp(k_h) | v_h] for one head ----
        const int h = (bn - 1024) >> 7;
        const int bidb = bm >> 12;
        const uint32_t kTu = sbase;               // 128 x 64 fp16 (128B rows)
        const uint32_t vTu = sbase + 16384;

        __syncthreads();   // all warps done reading stage smem

        if (wn == 0) {
            // exp(k) -> kT smem, colsums -> g_S
            float cs[8][2];
            #pragma unroll
            for (int nt = 0; nt < 8; ++nt) { cs[nt][0] = 0.f; cs[nt][1] = 0.f; }
            #pragma unroll
            for (int mt = 0; mt < 4; ++mt) {
                int rr = wm * 64 + mt * 16 + (lane >> 2);
                #pragma unroll
                for (int nt = 0; nt < 8; ++nt) {
                    float e0 = __expf(acc[mt][nt][0]);
                    float e1 = __expf(acc[mt][nt][1]);
                    float e2 = __expf(acc[mt][nt][2]);
                    float e3 = __expf(acc[mt][nt][3]);
                    cs[nt][0] += e0 + e2;
                    cs[nt][1] += e1 + e3;
                    int cb = (nt * 8 + cq) * 2;     // byte col
                    *(__half2*)(smem + SWZ((uint32_t)(rr * 128 + cb)))       = __floats2half2_rn(e0, e1);
                    *(__half2*)(smem + SWZ((uint32_t)((rr + 8) * 128 + cb))) = __floats2half2_rn(e2, e3);
                }
            }
            #pragma unroll
            for (int nt = 0; nt < 8; ++nt) {
                #pragma unroll
                for (int j = 0; j < 2; ++j) {
                    float cc = cs[nt][j];
                    cc += __shfl_xor_sync(0xFFFFFFFFu, cc, 4);
                    cc += __shfl_xor_sync(0xFFFFFFFFu, cc, 8);
                    cc += __shfl_xor_sync(0xFFFFFFFFu, cc, 16);
                    if (lane < 4)
                        atomicAdd(&g_S[bidb * DIM + h * DHEAD + nt * 8 + cq + j], cc);
                }
            }
        } else {
            // v -> vT smem
            #pragma unroll
            for (int mt = 0; mt < 4; ++mt) {
                int rr = wm * 64 + mt * 16 + (lane >> 2);
                #pragma unroll
                for (int nt = 0; nt < 8; ++nt) {
                    int cb = (nt * 8 + cq) * 2;
                    *(__half2*)(smem + 16384 + SWZ((uint32_t)(rr * 128 + cb)))       = __floats2half2_rn(acc[mt][nt][0], acc[mt][nt][1]);
                    *(__half2*)(smem + 16384 + SWZ((uint32_t)((rr + 8) * 128 + cb))) = __floats2half2_rn(acc[mt][nt][2], acc[mt][nt][3]);
                }
            }
        }
        __syncthreads();

        // ctx partial: ekT(128x64)^T @ vT(128x64) -> [64d x 64e], warp wid owns e wid*16..+16
        const int l7 = lane & 7;
        const int row16 = l7 + ((lane & 16) >> 1);
        const int coloff = lane & 8;

        uint32_t aadr[4];
        #pragma unroll
        for (int mt = 0; mt < 4; ++mt)
            aadr[mt] = kTu + SWZ((uint32_t)(row16 * 128 + (mt * 16 + coloff) * 2));
        uint32_t badr = vTu + SWZ((uint32_t)(row16 * 128 + (wid * 16 + coloff) * 2));

        float c2[4][2][4];
        #pragma unroll
        for (int i = 0; i < 4; i++)
            #pragma unroll
            for (int j = 0; j < 2; j++)
                #pragma unroll
                for (int x = 0; x < 4; x++) c2[i][j][x] = 0.f;

        #pragma unroll
        for (int ks = 0; ks < 8; ++ks) {
            const uint32_t koff = (uint32_t)(ks * 2048);
            uint32_t bfr[4];
            LDSM_X4T(bfr[0], bfr[1], bfr[2], bfr[3], badr + koff);
            #pragma unroll
            for (int mt = 0; mt < 4; ++mt) {
                uint32_t afr[4];
                LDSM_X4T(afr[0], afr[1], afr[2], afr[3], aadr[mt] + koff);
                MMA16816(c2[mt][0][0], c2[mt][0][1], c2[mt][0][2], c2[mt][0][3],
                         afr[0], afr[1], afr[2], afr[3], bfr[0], bfr[2]);
                MMA16816(c2[mt][1][0], c2[mt][1][1], c2[mt][1][2], c2[mt][1][3],
                         afr[0], afr[1], afr[2], afr[3], bfr[1], bfr[3]);
            }
        }

        float* outp = g_ctxp + ((long)(bm >> 7) * HEADS + h) * (DHEAD * DHEAD);
        const int e0 = wid * 16 + cq;
        #pragma unroll
        for (int mt = 0; mt < 4; ++mt) {
            int d0 = mt * 16 + (lane >> 2);
            #pragma unroll
            for (int nt = 0; nt < 2; ++nt) {
                *(float2*)&outp[(d0)     * DHEAD + e0 + nt * 8] = make_float2(c2[mt][nt][0], c2[mt][nt][1]);
                *(float2*)&outp[(d0 + 8) * DHEAD + e0 + nt * 8] = make_float2(c2[mt][nt][2], c2[mt][nt][3]);
            }
        }
    }
}

// ---------------------------------------------------------------------------
// Small kernels
// ---------------------------------------------------------------------------
__global__ void f2h_kernel(const float* __restrict__ in)
{
    long i = (long)blockIdx.x * 256 + threadIdx.x;
    float4 f = ((const float4*)in)[i];
    ((__half2*)g_featsh)[2 * i]     = __floats2half2_rn(f.x, f.y);
    ((__half2*)g_featsh)[2 * i + 1] = __floats2half2_rn(f.z, f.w);
}

// W transpose with head-interleaved permutation + S zeroing.
// Wt row for output column n:
//   n < 1024          -> n                         (q)
//   1024 <= n < 2048  -> 1024 + h*128 + d          (k_h)
//   n >= 2048         -> 1024 + h*128 + 64 + d     (v_h)
__global__ void wtrans_kernel(const float* __restrict__ W)
{
    if (blockIdx.x < 8 && blockIdx.y == 0)
        g_S[blockIdx.x * 256 + threadIdx.x] = 0.f;

    __shared__ float t[32][33];
    const int n0 = blockIdx.x * 32, k0 = blockIdx.y * 32;
    const int tx = threadIdx.x & 31, ty = threadIdx.x >> 5;
    #pragma unroll
    for (int j = 0; j < 4; ++j)
        t[ty + 8 * j][tx] = W[(long)(k0 + ty + 8 * j) * QKV_COLS + n0 + tx];
    __syncthreads();
    #pragma unroll
    for (int j = 0; j < 4; ++j) {
        int n = n0 + ty + 8 * j;
        int row;
        if (n < 1024)       row = n;
        else if (n < 2048)  row = 1024 + ((n - 1024) >> 6) * 128 + ((n - 1024) & 63);
        else                row = 1024 + ((n - 2048) >> 6) * 128 + 64 + ((n - 2048) & 63);
        g_Wt[(long)row * DIM + k0 + tx] = __float2half_rn(t[tx][ty + 8 * j]);
    }
}

// reduce 32 m-chunks per (b,h). grid (32 bh, 4), 256 threads x float4.
__global__ void ctx_reduce_kernel()
{
    const int bh = blockIdx.x;
    const int b = bh >> 4, h = bh & 15;
    const int idx = blockIdx.y * 1024 + threadIdx.x * 4;
    float4 v = make_float4(0.f, 0.f, 0.f, 0.f);
    #pragma unroll
    for (int c = 0; c < 32; ++c) {
        const float* p = g_ctxp + ((long)(b * 32 + c) * HEADS + h) * (DHEAD * DHEAD) + idx;
        float4 q = *(const float4*)p;
        v.x += q.x; v.y += q.y; v.z += q.z; v.w += q.w;
    }
    *(float4*)&g_ctx[bh * (DHEAD * DHEAD) + idx] = v;
}

// ---------------------------------------------------------------------------
// M_b^T (fp16) = (blockdiag(ctx_b / S) @ W_out)^T
// ---------------------------------------------------------------------------
__global__ __launch_bounds__(256, 4)
void make_M_kernel(const float* __restrict__ W_out)
{
    const int nt = blockIdx.x;
    const int bh = blockIdx.y;
    const int b = bh >> 4;
    const int h = bh & 15;
    const int tid = threadIdx.x;

    __shared__ float cst[DHEAD][DHEAD + 1];
    __shared__ float ws[DHEAD][DHEAD + 4];
    __shared__ float invs[DHEAD];

    if (tid < 64) invs[tid] = 1.f / g_S[b * DIM + h * DHEAD + tid];
    for (int i = tid; i < DHEAD * DHEAD; i += 256) {
        int d = i >> 6, d2 = i & 63;
        cst[d2][d] = g_ctx[bh * (DHEAD*DHEAD) + i];
    }
    for (int i = tid; i < DHEAD * DHEAD; i += 256) {
        int k2 = i >> 6, c = i & 63;
        ws[k2][c] = W_out[(long)(h * DHEAD + k2) * DIM + nt * DHEAD + c];
    }
    __syncthreads();

    const int dd0 = (tid >> 4) * 4;
    const int c0 = (tid & 15) * 4;
    float acc[4][4];
    #pragma unroll
    for (int i = 0; i < 4; i++)
        #pragma unroll
        for (int j = 0; j < 4; j++) acc[i][j] = 0.f;

    #pragma unroll 8
    for (int k2 = 0; k2 < DHEAD; ++k2) {
        float ar[4], br[4];
        ar[0] = cst[k2][dd0 + 0];
        ar[1] = cst[k2][dd0 + 1];
        ar[2] = cst[k2][dd0 + 2];
        ar[3] = cst[k2][dd0 + 3];
        *(float4*)br = *(const float4*)&ws[k2][c0];
        #pragma unroll
        for (int i = 0; i < 4; i++)
            #pragma unroll
            for (int j = 0; j < 4; j++)
                acc[i][j] += ar[i] * br[j];
    }

    #pragma unroll
    for (int j = 0; j < 4; ++j) {
        long rowb = (long)b * DIM * DIM + (long)(nt * 64 + c0 + j) * DIM + h * 64 + dd0;
        *(__half2*)&g_Mh[rowb]     = __floats2half2_rn(acc[0][j] * invs[dd0+0], acc[1][j] * invs[dd0+1]);
        *(__half2*)&g_Mh[rowb + 2] = __floats2half2_rn(acc[2][j] * invs[dd0+2], acc[3][j] * invs[dd0+3]);
    }
}

// ---------------------------------------------------------------------------
// Launch
// ---------------------------------------------------------------------------
extern "C" void kernel_launch(void* const* d_in, const int* in_sizes, int n_in,
                              void* d_out, int out_size)
{
    const float* feats = (const float*)d_in[0];
    const float* W_qkv = (const float*)d_in[1];
    const float* W_out = (const float*)d_in[2];
    float* out = (float*)d_out;

    cudaFuncSetAttribute(hgemm_kernel<0>, cudaFuncAttributeMaxDynamicSharedMemorySize, HG_SMEM);
    cudaFuncSetAttribute(hgemm_kernel<1>, cudaFuncAttributeMaxDynamicSharedMemorySize, HG_SMEM);

    __half* featsh; cudaGetSymbolAddress((void**)&featsh, g_featsh);
    __half* Wt;     cudaGetSymbolAddress((void**)&Wt, g_Wt);
    __half* qh;     cudaGetSymbolAddress((void**)&qh, g_qh);
    __half* Mh;     cudaGetSymbolAddress((void**)&Mh, g_Mh);

    f2h_kernel<<<(M_ROWS * DIM / 4) / 256, 256>>>(feats);
    wtrans_kernel<<<dim3(QKV_COLS / 32, DIM / 32), 256>>>(W_qkv);

    // 1) fused qkv GEMM (q softmax + in-epilogue ctx partials + colsums)
    hgemm_kernel<0><<<dim3(QKV_COLS / HG_BN, M_ROWS / HG_BM, 1), 128, HG_SMEM>>>(
        featsh, Wt, nullptr, DIM, DIM, DIM, 0, 0, 0, 0);

    // 2) ctx reduce
    ctx_reduce_kernel<<<dim3(32, 4), 256>>>();

    // 3) M_b^T fp16
    make_M_kernel<<<dim3(16, 32), 256>>>(W_out);

    // 4) out = q' @ M_b
    hgemm_kernel<1><<<dim3(DIM / HG_BN, N_SEQ / HG_BM, B), 128, HG_SMEM>>>(
        qh, Mh, out, DIM, DIM, DIM, DIM,
        (long)N_SEQ * DIM, (long)DIM * DIM, (long)N_SEQ * DIM);
}

// round 11
// speedup vs baseline: 6.5102x; 1.0075x over previous
#include <cuda_runtime.h>
#include <cuda_fp16.h>
#include <cstdint>
#include <math.h>

// Problem constants
#define B 2
#define N_SEQ 4096
#define DIM 1024
#define HEADS 16
#define DHEAD 64
#define M_ROWS (B * N_SEQ)        // 8192
#define QKV_COLS (3 * DIM)        // 3072

// ---------------------------------------------------------------------------
// Scratch (device globals)
// ---------------------------------------------------------------------------
__device__ __half g_featsh[(size_t)M_ROWS * DIM];        // feats fp16
__device__ __half g_Wt[(size_t)QKV_COLS * DIM];          // permuted W_qkv^T fp16
__device__ __half g_qh[(size_t)M_ROWS * DIM];            // q' (softmaxed*scale) fp16
__device__ __half g_Mh[(size_t)B * DIM * DIM];           // M_b^T fp16
__device__ float  g_S[B * DIM];                          // colsum exp(k)
__device__ float  g_ctx[B * HEADS * DHEAD * DHEAD];      // ctx accumulators (atomic)

// ---------------------------------------------------------------------------
// Helpers
// ---------------------------------------------------------------------------
__device__ __forceinline__ uint32_t smem_u32(const void* p) {
    uint32_t a;
    asm("{ .reg .u64 t; cvta.to.shared.u64 t, %1; cvt.u32.u64 %0, t; }" : "=r"(a) : "l"(p));
    return a;
}
#define CP_ASYNC16(smem, g) \
    asm volatile("cp.async.cg.shared.global [%0], [%1], 16;" :: "r"((uint32_t)(smem)), "l"(g) : "memory")
#define CP_COMMIT() asm volatile("cp.async.commit_group;" ::: "memory")
template <int N> __device__ __forceinline__ void cp_wait() {
    asm volatile("cp.async.wait_group %0;" :: "n"(N) : "memory");
}
#define SWZ(x) ((x) ^ (((x) >> 3) & 0x70))

#define LDSM_X4(r0, r1, r2, r3, addr) \
    asm volatile("ldmatrix.sync.aligned.m8n8.x4.shared.b16 {%0,%1,%2,%3}, [%4];" \
                 : "=r"(r0), "=r"(r1), "=r"(r2), "=r"(r3) : "r"(addr))

#define LDSM_X4T(r0, r1, r2, r3, addr) \
    asm volatile("ldmatrix.sync.aligned.m8n8.x4.trans.shared.b16 {%0,%1,%2,%3}, [%4];" \
                 : "=r"(r0), "=r"(r1), "=r"(r2), "=r"(r3) : "r"(addr))

#define MMA16816(c0, c1, c2, c3, a0, a1, a2, a3, b0, b1) \
    asm volatile("mma.sync.aligned.m16n8k16.row.col.f32.f16.f16.f32 " \
                 "{%0,%1,%2,%3}, {%4,%5,%6,%7}, {%8,%9}, {%0,%1,%2,%3};" \
                 : "+f"(c0), "+f"(c1), "+f"(c2), "+f"(c3) \
                 : "r"(a0), "r"(a1), "r"(a2), "r"(a3), "r"(b0), "r"(b1))

// ---------------------------------------------------------------------------
// HMMA fp16 GEMM: 128x128 CTA tile, 4 warps, warp tile 64x64, K-chunk 64,
// 3-stage cp.async (96 KB), 2 CTAs/SM, fragment double-buffering.
// MODE 0 (qkv): W columns permuted as [q | (k_h,v_h) per head].
//   bn <  1024 : q epilogue (softmax*scale -> g_qh fp16)
//   bn >= 1024 : head tile [exp(k_h) | v_h]; in-epilogue ctx partial via HMMA
//                -> atomicAdd into g_ctx, colsums -> g_S.
// MODE 1: plain fp32 C store.
// ---------------------------------------------------------------------------
#define HG_BM 128
#define HG_BN 128
#define STG_A (HG_BM * 128)            // 16 KB
#define STG_B (HG_BN * 128)            // 16 KB
#define STG_BYTES (STG_A + STG_B)      // 32 KB
#define HG_STAGES 3
#define HG_SMEM (HG_STAGES * STG_BYTES)  // 96 KB

template <int MODE>
__global__ __launch_bounds__(128, 2)
void hgemm_kernel(const __half* __restrict__ A, const __half* __restrict__ Bh,
                  float* __restrict__ C, int K, int lda, int ldb, int ldc,
                  long aB, long bB, long cB)
{
    A  += (long)blockIdx.z * aB;
    Bh += (long)blockIdx.z * bB;
    if (MODE == 1) C += (long)blockIdx.z * cB;

    extern __shared__ char smem[];
    const uint32_t sbase = smem_u32(smem);
    const int tid  = threadIdx.x;
    const int wid  = tid >> 5;
    const int lane = tid & 31;
    const int wm = wid >> 1;           // 0..1 (64 rows)
    const int wn = wid & 1;            // 0..1 (64 cols)
    const int bm = blockIdx.y * HG_BM;
    const int bn = blockIdx.x * HG_BN;
    const int NC = K >> 6;

    const int r0   = tid >> 3;          // 0..15
    const int c16  = tid & 7;
    const uint32_t offLd = (uint32_t)(r0 * 128 + ((c16 ^ (r0 & 7)) * 16));
    const __half* apg = A + (long)(bm + r0) * lda + c16 * 8;
    const __half* bpg = Bh + (long)(bn + r0) * ldb + c16 * 8;
    const long strideA = (long)16 * lda;
    const long strideB = (long)16 * ldb;

    auto load_chunk = [&](int kc, int st) {
        const uint32_t sa = sbase + st * STG_BYTES + offLd;
        const uint32_t sb = sa + STG_A;
        const __half* ap = apg + kc * 64;
        const __half* bp = bpg + kc * 64;
        #pragma unroll
        for (int i = 0; i < 8; ++i) { CP_ASYNC16(sa + i * 2048, ap); ap += strideA; }
        #pragma unroll
        for (int i = 0; i < 8; ++i) { CP_ASYNC16(sb + i * 2048, bp); bp += strideB; }
    };

    float acc[4][8][4];
    #pragma unroll
    for (int i = 0; i < 4; i++)
        #pragma unroll
        for (int j = 0; j < 8; j++)
            #pragma unroll
            for (int x = 0; x < 4; x++) acc[i][j][x] = 0.f;

    load_chunk(0, 0); CP_COMMIT();
    load_chunk(1, 1); CP_COMMIT();

    const int lrow = lane & 15;
    const int lsel = lane >> 4;

    uint32_t a_row[4], b_row[4], ksel[4];
    #pragma unroll
    for (int mt = 0; mt < 4; ++mt) a_row[mt] = (uint32_t)(wm * 64 + mt * 16 + lrow) * 128;
    #pragma unroll
    for (int np = 0; np < 4; ++np) b_row[np] = (uint32_t)(wn * 64 + np * 16 + lrow) * 128;
    #pragma unroll
    for (int ks = 0; ks < 4; ++ks) ksel[ks] = (uint32_t)(((2 * ks + lsel) ^ (lrow & 7)) * 16);

    uint32_t af[2][4][4], bf[2][4][4];

    int st = 0, stl = 2;
    for (int c = 0; c < NC; ++c) {
        cp_wait<1>();
        __syncthreads();
        if (c + 2 < NC) load_chunk(c + 2, stl);
        CP_COMMIT();

        const uint32_t sa = sbase + st * STG_BYTES;
        const uint32_t sb = sa + STG_A;

        #pragma unroll
        for (int mt = 0; mt < 4; ++mt)
            LDSM_X4(af[0][mt][0], af[0][mt][1], af[0][mt][2], af[0][mt][3], sa + a_row[mt] + ksel[0]);
        #pragma unroll
        for (int np = 0; np < 4; ++np)
            LDSM_X4(bf[0][np][0], bf[0][np][1], bf[0][np][2], bf[0][np][3], sb + b_row[np] + ksel[0]);

        #pragma unroll
        for (int ks = 0; ks < 4; ++ks) {
            const int cur = ks & 1;
            const int nxt = cur ^ 1;
            if (ks < 3) {
                #pragma unroll
                for (int mt = 0; mt < 4; ++mt)
                    LDSM_X4(af[nxt][mt][0], af[nxt][mt][1], af[nxt][mt][2], af[nxt][mt][3],
                            sa + a_row[mt] + ksel[ks + 1]);
                #pragma unroll
                for (int np = 0; np < 4; ++np)
                    LDSM_X4(bf[nxt][np][0], bf[nxt][np][1], bf[nxt][np][2], bf[nxt][np][3],
                            sb + b_row[np] + ksel[ks + 1]);
            }
            #pragma unroll
            for (int mt = 0; mt < 4; ++mt) {
                #pragma unroll
                for (int np = 0; np < 4; ++np) {
                    MMA16816(acc[mt][2*np][0], acc[mt][2*np][1], acc[mt][2*np][2], acc[mt][2*np][3],
                             af[cur][mt][0], af[cur][mt][1], af[cur][mt][2], af[cur][mt][3],
                             bf[cur][np][0], bf[cur][np][2]);
                    MMA16816(acc[mt][2*np+1][0], acc[mt][2*np+1][1], acc[mt][2*np+1][2], acc[mt][2*np+1][3],
                             af[cur][mt][0], af[cur][mt][1], af[cur][mt][2], af[cur][mt][3],
                             bf[cur][np][1], bf[cur][np][3]);
                }
            }
        }
        if (++st == HG_STAGES) st = 0;
        if (++stl == HG_STAGES) stl = 0;
    }

    // ------------------------- epilogue -------------------------
    const int r_base = bm + wm * 64;
    const int cq = (lane & 3) * 2;

    if (MODE == 1) {
        #pragma unroll
        for (int mt = 0; mt < 4; ++mt) {
            int r0e = r_base + mt * 16 + (lane >> 2);
            #pragma unroll
            for (int nt = 0; nt < 8; ++nt) {
                int col = bn + wn * 64 + nt * 8 + cq;
                *(float2*)&C[(long)r0e * ldc + col]       = make_float2(acc[mt][nt][0], acc[mt][nt][1]);
                *(float2*)&C[(long)(r0e + 8) * ldc + col] = make_float2(acc[mt][nt][2], acc[mt][nt][3]);
            }
        }
    } else if (bn < 1024) {
        // ---- q region: softmax over the warp's 64 cols (= one head) ----
        #pragma unroll
        for (int mt = 0; mt < 4; ++mt) {
            #pragma unroll
            for (int hf = 0; hf < 2; ++hf) {
                int row = r_base + mt * 16 + (lane >> 2) + 8 * hf;
                float mx = -1e30f;
                #pragma unroll
                for (int nt = 0; nt < 8; ++nt)
                    mx = fmaxf(mx, fmaxf(acc[mt][nt][2*hf], acc[mt][nt][2*hf+1]));
                mx = fmaxf(mx, __shfl_xor_sync(0xFFFFFFFFu, mx, 1));
                mx = fmaxf(mx, __shfl_xor_sync(0xFFFFFFFFu, mx, 2));
                float s = 0.f;
                #pragma unroll
                for (int nt = 0; nt < 8; ++nt) {
                    float e0 = __expf(acc[mt][nt][2*hf]   - mx);
                    float e1 = __expf(acc[mt][nt][2*hf+1] - mx);
                    acc[mt][nt][2*hf] = e0; acc[mt][nt][2*hf+1] = e1;
                    s += e0 + e1;
                }
                s += __shfl_xor_sync(0xFFFFFFFFu, s, 1);
                s += __shfl_xor_sync(0xFFFFFFFFu, s, 2);
                float inv = 0.125f / s;
                #pragma unroll
                for (int nt = 0; nt < 8; ++nt) {
                    int col = bn + wn * 64 + nt * 8 + cq;
                    *(__half2*)&g_qh[(long)row * DIM + col] =
                        __floats2half2_rn(acc[mt][nt][2*hf] * inv, acc[mt][nt][2*hf+1] * inv);
                }
            }
        }
    } else {
        // ---- kv region: this CTA holds [exp(k_h) | v_h] for one head ----
        const int h = (bn - 1024) >> 7;
        const int bidb = bm >> 12;
        const uint32_t kTu = sbase;               // 128 x 64 fp16 (128B rows)
        const uint32_t vTu = sbase + 16384;

        __syncthreads();   // all warps done reading stage smem

        if (wn == 0) {
            // exp(k) -> kT smem, colsums -> g_S
            float cs[8][2];
            #pragma unroll
            for (int nt = 0; nt < 8; ++nt) { cs[nt][0] = 0.f; cs[nt][1] = 0.f; }
            #pragma unroll
            for (int mt = 0; mt < 4; ++mt) {
                int rr = wm * 64 + mt * 16 + (lane >> 2);
                #pragma unroll
                for (int nt = 0; nt < 8; ++nt) {
                    float e0 = __expf(acc[mt][nt][0]);
                    float e1 = __expf(acc[mt][nt][1]);
                    float e2 = __expf(acc[mt][nt][2]);
                    float e3 = __expf(acc[mt][nt][3]);
                    cs[nt][0] += e0 + e2;
                    cs[nt][1] += e1 + e3;
                    int cb = (nt * 8 + cq) * 2;     // byte col
                    *(__half2*)(smem + SWZ((uint32_t)(rr * 128 + cb)))       = __floats2half2_rn(e0, e1);
                    *(__half2*)(smem + SWZ((uint32_t)((rr + 8) * 128 + cb))) = __floats2half2_rn(e2, e3);
                }
            }
            #pragma unroll
            for (int nt = 0; nt < 8; ++nt) {
                #pragma unroll
                for (int j = 0; j < 2; ++j) {
                    float cc = cs[nt][j];
                    cc += __shfl_xor_sync(0xFFFFFFFFu, cc, 4);
                    cc += __shfl_xor_sync(0xFFFFFFFFu, cc, 8);
                    cc += __shfl_xor_sync(0xFFFFFFFFu, cc, 16);
                    if (lane < 4)
                        atomicAdd(&g_S[bidb * DIM + h * DHEAD + nt * 8 + cq + j], cc);
                }
            }
        } else {
            // v -> vT smem
            #pragma unroll
            for (int mt = 0; mt < 4; ++mt) {
                int rr = wm * 64 + mt * 16 + (lane >> 2);
                #pragma unroll
                for (int nt = 0; nt < 8; ++nt) {
                    int cb = (nt * 8 + cq) * 2;
                    *(__half2*)(smem + 16384 + SWZ((uint32_t)(rr * 128 + cb)))       = __floats2half2_rn(acc[mt][nt][0], acc[mt][nt][1]);
                    *(__half2*)(smem + 16384 + SWZ((uint32_t)((rr + 8) * 128 + cb))) = __floats2half2_rn(acc[mt][nt][2], acc[mt][nt][3]);
                }
            }
        }
        __syncthreads();

        // ctx partial: ekT(128x64)^T @ vT(128x64) -> [64d x 64e], warp wid owns e wid*16..+16
        const int l7 = lane & 7;
        const int row16 = l7 + ((lane & 16) >> 1);
        const int coloff = lane & 8;

        uint32_t aadr[4];
        #pragma unroll
        for (int mt = 0; mt < 4; ++mt)
            aadr[mt] = kTu + SWZ((uint32_t)(row16 * 128 + (mt * 16 + coloff) * 2));
        uint32_t badr = vTu + SWZ((uint32_t)(row16 * 128 + (wid * 16 + coloff) * 2));

        float c2[4][2][4];
        #pragma unroll
        for (int i = 0; i < 4; i++)
            #pragma unroll
            for (int j = 0; j < 2; j++)
                #pragma unroll
                for (int x = 0; x < 4; x++) c2[i][j][x] = 0.f;

        #pragma unroll
        for (int ks = 0; ks < 8; ++ks) {
            const uint32_t koff = (uint32_t)(ks * 2048);
            uint32_t bfr[4];
            LDSM_X4T(bfr[0], bfr[1], bfr[2], bfr[3], badr + koff);
            #pragma unroll
            for (int mt = 0; mt < 4; ++mt) {
                uint32_t afr[4];
                LDSM_X4T(afr[0], afr[1], afr[2], afr[3], aadr[mt] + koff);
                MMA16816(c2[mt][0][0], c2[mt][0][1], c2[mt][0][2], c2[mt][0][3],
                         afr[0], afr[1], afr[2], afr[3], bfr[0], bfr[2]);
                MMA16816(c2[mt][1][0], c2[mt][1][1], c2[mt][1][2], c2[mt][1][3],
                         afr[0], afr[1], afr[2], afr[3], bfr[1], bfr[3]);
            }
        }

        // accumulate directly into g_ctx (RED.F32, spread addresses)
        float* outp = g_ctx + (long)(bidb * HEADS + h) * (DHEAD * DHEAD);
        const int e0 = wid * 16 + cq;
        #pragma unroll
        for (int mt = 0; mt < 4; ++mt) {
            int d0 = mt * 16 + (lane >> 2);
            #pragma unroll
            for (int nt = 0; nt < 2; ++nt) {
                atomicAdd(&outp[(d0)     * DHEAD + e0 + nt * 8],     c2[mt][nt][0]);
                atomicAdd(&outp[(d0)     * DHEAD + e0 + nt * 8 + 1], c2[mt][nt][1]);
                atomicAdd(&outp[(d0 + 8) * DHEAD + e0 + nt * 8],     c2[mt][nt][2]);
                atomicAdd(&outp[(d0 + 8) * DHEAD + e0 + nt * 8 + 1], c2[mt][nt][3]);
            }
        }
    }
}

// ---------------------------------------------------------------------------
// Small kernels
// ---------------------------------------------------------------------------
// fp32 -> fp16 conversion; first 512 blocks also zero g_ctx (131072 floats).
__global__ void f2h_kernel(const float* __restrict__ in)
{
    long i = (long)blockIdx.x * 256 + threadIdx.x;
    if (blockIdx.x < 512)
        g_ctx[blockIdx.x * 256 + threadIdx.x] = 0.f;
    float4 f = ((const float4*)in)[i];
    ((__half2*)g_featsh)[2 * i]     = __floats2half2_rn(f.x, f.y);
    ((__half2*)g_featsh)[2 * i + 1] = __floats2half2_rn(f.z, f.w);
}

// W transpose with head-interleaved permutation + S zeroing.
// Wt row for output column n:
//   n < 1024          -> n                         (q)
//   1024 <= n < 2048  -> 1024 + h*128 + d          (k_h)
//   n >= 2048         -> 1024 + h*128 + 64 + d     (v_h)
__global__ void wtrans_kernel(const float* __restrict__ W)
{
    if (blockIdx.x < 8 && blockIdx.y == 0)
        g_S[blockIdx.x * 256 + threadIdx.x] = 0.f;

    __shared__ float t[32][33];
    const int n0 = blockIdx.x * 32, k0 = blockIdx.y * 32;
    const int tx = threadIdx.x & 31, ty = threadIdx.x >> 5;
    #pragma unroll
    for (int j = 0; j < 4; ++j)
        t[ty + 8 * j][tx] = W[(long)(k0 + ty + 8 * j) * QKV_COLS + n0 + tx];
    __syncthreads();
    #pragma unroll
    for (int j = 0; j < 4; ++j) {
        int n = n0 + ty + 8 * j;
        int row;
        if (n < 1024)       row = n;
        else if (n < 2048)  row = 1024 + ((n - 1024) >> 6) * 128 + ((n - 1024) & 63);
        else                row = 1024 + ((n - 2048) >> 6) * 128 + 64 + ((n - 2048) & 63);
        g_Wt[(long)row * DIM + k0 + tx] = __float2half_rn(t[tx][ty + 8 * j]);
    }
}

// ---------------------------------------------------------------------------
// M_b^T (fp16) = (blockdiag(ctx_b / S) @ W_out)^T
// ---------------------------------------------------------------------------
__global__ __launch_bounds__(256, 4)
void make_M_kernel(const float* __restrict__ W_out)
{
    const int nt = blockIdx.x;
    const int bh = blockIdx.y;
    const int b = bh >> 4;
    const int h = bh & 15;
    const int tid = threadIdx.x;

    __shared__ float cst[DHEAD][DHEAD + 1];
    __shared__ float ws[DHEAD][DHEAD + 4];
    __shared__ float invs[DHEAD];

    if (tid < 64) invs[tid] = 1.f / g_S[b * DIM + h * DHEAD + tid];
    for (int i = tid; i < DHEAD * DHEAD; i += 256) {
        int d = i >> 6, d2 = i & 63;
        cst[d2][d] = g_ctx[bh * (DHEAD*DHEAD) + i];
    }
    for (int i = tid; i < DHEAD * DHEAD; i += 256) {
        int k2 = i >> 6, c = i & 63;
        ws[k2][c] = W_out[(long)(h * DHEAD + k2) * DIM + nt * DHEAD + c];
    }
    __syncthreads();

    const int dd0 = (tid >> 4) * 4;
    const int c0 = (tid & 15) * 4;
    float acc[4][4];
    #pragma unroll
    for (int i = 0; i < 4; i++)
        #pragma unroll
        for (int j = 0; j < 4; j++) acc[i][j] = 0.f;

    #pragma unroll 8
    for (int k2 = 0; k2 < DHEAD; ++k2) {
        float ar[4], br[4];
        ar[0] = cst[k2][dd0 + 0];
        ar[1] = cst[k2][dd0 + 1];
        ar[2] = cst[k2][dd0 + 2];
        ar[3] = cst[k2][dd0 + 3];
        *(float4*)br = *(const float4*)&ws[k2][c0];
        #pragma unroll
        for (int i = 0; i < 4; i++)
            #pragma unroll
            for (int j = 0; j < 4; j++)
                acc[i][j] += ar[i] * br[j];
    }

    #pragma unroll
    for (int j = 0; j < 4; ++j) {
        long rowb = (long)b * DIM * DIM + (long)(nt * 64 + c0 + j) * DIM + h * 64 + dd0;
        *(__half2*)&g_Mh[rowb]     = __floats2half2_rn(acc[0][j] * invs[dd0+0], acc[1][j] * invs[dd0+1]);
        *(__half2*)&g_Mh[rowb + 2] = __floats2half2_rn(acc[2][j] * invs[dd0+2], acc[3][j] * invs[dd0+3]);
    }
}

// ---------------------------------------------------------------------------
// Launch
// ---------------------------------------------------------------------------
extern "C" void kernel_launch(void* const* d_in, const int* in_sizes, int n_in,
                              void* d_out, int out_size)
{
    const float* feats = (const float*)d_in[0];
    const float* W_qkv = (const float*)d_in[1];
    const float* W_out = (const float*)d_in[2];
    float* out = (float*)d_out;

    cudaFuncSetAttribute(hgemm_kernel<0>, cudaFuncAttributeMaxDynamicSharedMemorySize, HG_SMEM);
    cudaFuncSetAttribute(hgemm_kernel<1>, cudaFuncAttributeMaxDynamicSharedMemorySize, HG_SMEM);

    __half* featsh; cudaGetSymbolAddress((void**)&featsh, g_featsh);
    __half* Wt;     cudaGetSymbolAddress((void**)&Wt, g_Wt);
    __half* qh;     cudaGetSymbolAddress((void**)&qh, g_qh);
    __half* Mh;     cudaGetSymbolAddress((void**)&Mh, g_Mh);

    f2h_kernel<<<(M_ROWS * DIM / 4) / 256, 256>>>(feats);
    wtrans_kernel<<<dim3(QKV_COLS / 32, DIM / 32), 256>>>(W_qkv);

    // 1) fused qkv GEMM (q softmax + in-epilogue ctx partials -> atomic g_ctx)
    hgemm_kernel<0><<<dim3(QKV_COLS / HG_BN, M_ROWS / HG_BM, 1), 128, HG_SMEM>>>(
        featsh, Wt, nullptr, DIM, DIM, DIM, 0, 0, 0, 0);

    // 2) M_b^T fp16
    make_M_kernel<<<dim3(16, 32), 256>>>(W_out);

    // 3) out = q' @ M_b
    hgemm_kernel<1><<<dim3(DIM / HG_BN, N_SEQ / HG_BM, B), 128, HG_SMEM>>>(
        qh, Mh, out, DIM, DIM, DIM, DIM,
        (long)N_SEQ * DIM, (long)DIM * DIM, (long)N_SEQ * DIM);
}

// round 12
// speedup vs baseline: 6.8268x; 1.0486x over previous
#include <cuda_runtime.h>
#include <cuda_fp16.h>
#include <cstdint>
#include <math.h>

// Problem constants
#define B 2
#define N_SEQ 4096
#define DIM 1024
#define HEADS 16
#define DHEAD 64
#define M_ROWS (B * N_SEQ)        // 8192
#define QKV_COLS (3 * DIM)        // 3072

// ---------------------------------------------------------------------------
// Scratch (device globals)
// ---------------------------------------------------------------------------
__device__ __half g_featsh[(size_t)M_ROWS * DIM];        // feats fp16
__device__ __half g_Wt[(size_t)QKV_COLS * DIM];          // permuted W_qkv^T fp16
__device__ __half g_WoT[(size_t)DIM * DIM];              // W_out^T fp16 [n][k]
__device__ __half g_qh[(size_t)M_ROWS * DIM];            // q' (softmaxed*scale) fp16
__device__ __half g_Mh[(size_t)B * DIM * DIM];           // M_b^T fp16
__device__ float  g_S[B * DIM];                          // colsum exp(k)
__device__ float  g_ctx[B * HEADS * DHEAD * DHEAD];      // ctx accumulators (atomic)

// ---------------------------------------------------------------------------
// Helpers
// ---------------------------------------------------------------------------
__device__ __forceinline__ uint32_t smem_u32(const void* p) {
    uint32_t a;
    asm("{ .reg .u64 t; cvta.to.shared.u64 t, %1; cvt.u32.u64 %0, t; }" : "=r"(a) : "l"(p));
    return a;
}
#define CP_ASYNC16(smem, g) \
    asm volatile("cp.async.cg.shared.global [%0], [%1], 16;" :: "r"((uint32_t)(smem)), "l"(g) : "memory")
#define CP_COMMIT() asm volatile("cp.async.commit_group;" ::: "memory")
template <int N> __device__ __forceinline__ void cp_wait() {
    asm volatile("cp.async.wait_group %0;" :: "n"(N) : "memory");
}
#define SWZ(x) ((x) ^ (((x) >> 3) & 0x70))

#define LDSM_X4(r0, r1, r2, r3, addr) \
    asm volatile("ldmatrix.sync.aligned.m8n8.x4.shared.b16 {%0,%1,%2,%3}, [%4];" \
                 : "=r"(r0), "=r"(r1), "=r"(r2), "=r"(r3) : "r"(addr))

#define LDSM_X4T(r0, r1, r2, r3, addr) \
    asm volatile("ldmatrix.sync.aligned.m8n8.x4.trans.shared.b16 {%0,%1,%2,%3}, [%4];" \
                 : "=r"(r0), "=r"(r1), "=r"(r2), "=r"(r3) : "r"(addr))

#define MMA16816(c0, c1, c2, c3, a0, a1, a2, a3, b0, b1) \
    asm volatile("mma.sync.aligned.m16n8k16.row.col.f32.f16.f16.f32 " \
                 "{%0,%1,%2,%3}, {%4,%5,%6,%7}, {%8,%9}, {%0,%1,%2,%3};" \
                 : "+f"(c0), "+f"(c1), "+f"(c2), "+f"(c3) \
                 : "r"(a0), "r"(a1), "r"(a2), "r"(a3), "r"(b0), "r"(b1))

// ---------------------------------------------------------------------------
// HMMA fp16 GEMM: 128x128 CTA tile, 4 warps, warp tile 64x64, K-chunk 64,
// 3-stage cp.async (96 KB), 2 CTAs/SM, fragment double-buffering.
// MODE 0 (qkv): W columns permuted as [q | (k_h,v_h) per head].
//   bn <  1024 : q epilogue (softmax*scale -> g_qh fp16)
//   bn >= 1024 : head tile [exp(k_h) | v_h]; in-epilogue ctx partial via HMMA
//                -> atomicAdd into g_ctx, colsums -> g_S.
// MODE 1: plain fp32 C store.
// ---------------------------------------------------------------------------
#define HG_BM 128
#define HG_BN 128
#define STG_A (HG_BM * 128)            // 16 KB
#define STG_B (HG_BN * 128)            // 16 KB
#define STG_BYTES (STG_A + STG_B)      // 32 KB
#define HG_STAGES 3
#define HG_SMEM (HG_STAGES * STG_BYTES)  // 96 KB

template <int MODE>
__global__ __launch_bounds__(128, 2)
void hgemm_kernel(const __half* __restrict__ A, const __half* __restrict__ Bh,
                  float* __restrict__ C, int K, int lda, int ldb, int ldc,
                  long aB, long bB, long cB)
{
    A  += (long)blockIdx.z * aB;
    Bh += (long)blockIdx.z * bB;
    if (MODE == 1) C += (long)blockIdx.z * cB;

    extern __shared__ char smem[];
    const uint32_t sbase = smem_u32(smem);
    const int tid  = threadIdx.x;
    const int wid  = tid >> 5;
    const int lane = tid & 31;
    const int wm = wid >> 1;           // 0..1 (64 rows)
    const int wn = wid & 1;            // 0..1 (64 cols)
    const int bm = blockIdx.y * HG_BM;
    const int bn = blockIdx.x * HG_BN;
    const int NC = K >> 6;

    const int r0   = tid >> 3;          // 0..15
    const int c16  = tid & 7;
    const uint32_t offLd = (uint32_t)(r0 * 128 + ((c16 ^ (r0 & 7)) * 16));
    const __half* apg = A + (long)(bm + r0) * lda + c16 * 8;
    const __half* bpg = Bh + (long)(bn + r0) * ldb + c16 * 8;
    const long strideA = (long)16 * lda;
    const long strideB = (long)16 * ldb;

    auto load_chunk = [&](int kc, int st) {
        const uint32_t sa = sbase + st * STG_BYTES + offLd;
        const uint32_t sb = sa + STG_A;
        const __half* ap = apg + kc * 64;
        const __half* bp = bpg + kc * 64;
        #pragma unroll
        for (int i = 0; i < 8; ++i) { CP_ASYNC16(sa + i * 2048, ap); ap += strideA; }
        #pragma unroll
        for (int i = 0; i < 8; ++i) { CP_ASYNC16(sb + i * 2048, bp); bp += strideB; }
    };

    float acc[4][8][4];
    #pragma unroll
    for (int i = 0; i < 4; i++)
        #pragma unroll
        for (int j = 0; j < 8; j++)
            #pragma unroll
            for (int x = 0; x < 4; x++) acc[i][j][x] = 0.f;

    load_chunk(0, 0); CP_COMMIT();
    load_chunk(1, 1); CP_COMMIT();

    const int lrow = lane & 15;
    const int lsel = lane >> 4;

    uint32_t a_row[4], b_row[4], ksel[4];
    #pragma unroll
    for (int mt = 0; mt < 4; ++mt) a_row[mt] = (uint32_t)(wm * 64 + mt * 16 + lrow) * 128;
    #pragma unroll
    for (int np = 0; np < 4; ++np) b_row[np] = (uint32_t)(wn * 64 + np * 16 + lrow) * 128;
    #pragma unroll
    for (int ks = 0; ks < 4; ++ks) ksel[ks] = (uint32_t)(((2 * ks + lsel) ^ (lrow & 7)) * 16);

    uint32_t af[2][4][4], bf[2][4][4];

    int st = 0, stl = 2;
    for (int c = 0; c < NC; ++c) {
        cp_wait<1>();
        __syncthreads();
        if (c + 2 < NC) load_chunk(c + 2, stl);
        CP_COMMIT();

        const uint32_t sa = sbase + st * STG_BYTES;
        const uint32_t sb = sa + STG_A;

        #pragma unroll
        for (int mt = 0; mt < 4; ++mt)
            LDSM_X4(af[0][mt][0], af[0][mt][1], af[0][mt][2], af[0][mt][3], sa + a_row[mt] + ksel[0]);
        #pragma unroll
        for (int np = 0; np < 4; ++np)
            LDSM_X4(bf[0][np][0], bf[0][np][1], bf[0][np][2], bf[0][np][3], sb + b_row[np] + ksel[0]);

        #pragma unroll
        for (int ks = 0; ks < 4; ++ks) {
            const int cur = ks & 1;
            const int nxt = cur ^ 1;
            if (ks < 3) {
                #pragma unroll
                for (int mt = 0; mt < 4; ++mt)
                    LDSM_X4(af[nxt][mt][0], af[nxt][mt][1], af[nxt][mt][2], af[nxt][mt][3],
                            sa + a_row[mt] + ksel[ks + 1]);
                #pragma unroll
                for (int np = 0; np < 4; ++np)
                    LDSM_X4(bf[nxt][np][0], bf[nxt][np][1], bf[nxt][np][2], bf[nxt][np][3],
                            sb + b_row[np] + ksel[ks + 1]);
            }
            #pragma unroll
            for (int mt = 0; mt < 4; ++mt) {
                #pragma unroll
                for (int np = 0; np < 4; ++np) {
                    MMA16816(acc[mt][2*np][0], acc[mt][2*np][1], acc[mt][2*np][2], acc[mt][2*np][3],
                             af[cur][mt][0], af[cur][mt][1], af[cur][mt][2], af[cur][mt][3],
                             bf[cur][np][0], bf[cur][np][2]);
                    MMA16816(acc[mt][2*np+1][0], acc[mt][2*np+1][1], acc[mt][2*np+1][2], acc[mt][2*np+1][3],
                             af[cur][mt][0], af[cur][mt][1], af[cur][mt][2], af[cur][mt][3],
                             bf[cur][np][1], bf[cur][np][3]);
                }
            }
        }
        if (++st == HG_STAGES) st = 0;
        if (++stl == HG_STAGES) stl = 0;
    }

    // ------------------------- epilogue -------------------------
    const int r_base = bm + wm * 64;
    const int cq = (lane & 3) * 2;

    if (MODE == 1) {
        #pragma unroll
        for (int mt = 0; mt < 4; ++mt) {
            int r0e = r_base + mt * 16 + (lane >> 2);
            #pragma unroll
            for (int nt = 0; nt < 8; ++nt) {
                int col = bn + wn * 64 + nt * 8 + cq;
                *(float2*)&C[(long)r0e * ldc + col]       = make_float2(acc[mt][nt][0], acc[mt][nt][1]);
                *(float2*)&C[(long)(r0e + 8) * ldc + col] = make_float2(acc[mt][nt][2], acc[mt][nt][3]);
            }
        }
    } else if (bn < 1024) {
        // ---- q region: softmax over the warp's 64 cols (= one head) ----
        #pragma unroll
        for (int mt = 0; mt < 4; ++mt) {
            #pragma unroll
            for (int hf = 0; hf < 2; ++hf) {
                int row = r_base + mt * 16 + (lane >> 2) + 8 * hf;
                float mx = -1e30f;
                #pragma unroll
                for (int nt = 0; nt < 8; ++nt)
                    mx = fmaxf(mx, fmaxf(acc[mt][nt][2*hf], acc[mt][nt][2*hf+1]));
                mx = fmaxf(mx, __shfl_xor_sync(0xFFFFFFFFu, mx, 1));
                mx = fmaxf(mx, __shfl_xor_sync(0xFFFFFFFFu, mx, 2));
                float s = 0.f;
                #pragma unroll
                for (int nt = 0; nt < 8; ++nt) {
                    float e0 = __expf(acc[mt][nt][2*hf]   - mx);
                    float e1 = __expf(acc[mt][nt][2*hf+1] - mx);
                    acc[mt][nt][2*hf] = e0; acc[mt][nt][2*hf+1] = e1;
                    s += e0 + e1;
                }
                s += __shfl_xor_sync(0xFFFFFFFFu, s, 1);
                s += __shfl_xor_sync(0xFFFFFFFFu, s, 2);
                float inv = 0.125f / s;
                #pragma unroll
                for (int nt = 0; nt < 8; ++nt) {
                    int col = bn + wn * 64 + nt * 8 + cq;
                    *(__half2*)&g_qh[(long)row * DIM + col] =
                        __floats2half2_rn(acc[mt][nt][2*hf] * inv, acc[mt][nt][2*hf+1] * inv);
                }
            }
        }
    } else {
        // ---- kv region: this CTA holds [exp(k_h) | v_h] for one head ----
        const int h = (bn - 1024) >> 7;
        const int bidb = bm >> 12;
        const uint32_t kTu = sbase;               // 128 x 64 fp16 (128B rows)
        const uint32_t vTu = sbase + 16384;

        __syncthreads();   // all warps done reading stage smem

        if (wn == 0) {
            // exp(k) -> kT smem, colsums -> g_S
            float cs[8][2];
            #pragma unroll
            for (int nt = 0; nt < 8; ++nt) { cs[nt][0] = 0.f; cs[nt][1] = 0.f; }
            #pragma unroll
            for (int mt = 0; mt < 4; ++mt) {
                int rr = wm * 64 + mt * 16 + (lane >> 2);
                #pragma unroll
                for (int nt = 0; nt < 8; ++nt) {
                    float e0 = __expf(acc[mt][nt][0]);
                    float e1 = __expf(acc[mt][nt][1]);
                    float e2 = __expf(acc[mt][nt][2]);
                    float e3 = __expf(acc[mt][nt][3]);
                    cs[nt][0] += e0 + e2;
                    cs[nt][1] += e1 + e3;
                    int cb = (nt * 8 + cq) * 2;     // byte col
                    *(__half2*)(smem + SWZ((uint32_t)(rr * 128 + cb)))       = __floats2half2_rn(e0, e1);
                    *(__half2*)(smem + SWZ((uint32_t)((rr + 8) * 128 + cb))) = __floats2half2_rn(e2, e3);
                }
            }
            #pragma unroll
            for (int nt = 0; nt < 8; ++nt) {
                #pragma unroll
                for (int j = 0; j < 2; ++j) {
                    float cc = cs[nt][j];
                    cc += __shfl_xor_sync(0xFFFFFFFFu, cc, 4);
                    cc += __shfl_xor_sync(0xFFFFFFFFu, cc, 8);
                    cc += __shfl_xor_sync(0xFFFFFFFFu, cc, 16);
                    if (lane < 4)
                        atomicAdd(&g_S[bidb * DIM + h * DHEAD + nt * 8 + cq + j], cc);
                }
            }
        } else {
            // v -> vT smem
            #pragma unroll
            for (int mt = 0; mt < 4; ++mt) {
                int rr = wm * 64 + mt * 16 + (lane >> 2);
                #pragma unroll
                for (int nt = 0; nt < 8; ++nt) {
                    int cb = (nt * 8 + cq) * 2;
                    *(__half2*)(smem + 16384 + SWZ((uint32_t)(rr * 128 + cb)))       = __floats2half2_rn(acc[mt][nt][0], acc[mt][nt][1]);
                    *(__half2*)(smem + 16384 + SWZ((uint32_t)((rr + 8) * 128 + cb))) = __floats2half2_rn(acc[mt][nt][2], acc[mt][nt][3]);
                }
            }
        }
        __syncthreads();

        // ctx partial: ekT(128x64)^T @ vT(128x64) -> [64d x 64e], warp wid owns e wid*16..+16
        const int l7 = lane & 7;
        const int row16 = l7 + ((lane & 16) >> 1);
        const int coloff = lane & 8;

        uint32_t aadr[4];
        #pragma unroll
        for (int mt = 0; mt < 4; ++mt)
            aadr[mt] = kTu + SWZ((uint32_t)(row16 * 128 + (mt * 16 + coloff) * 2));
        uint32_t badr = vTu + SWZ((uint32_t)(row16 * 128 + (wid * 16 + coloff) * 2));

        float c2[4][2][4];
        #pragma unroll
        for (int i = 0; i < 4; i++)
            #pragma unroll
            for (int j = 0; j < 2; j++)
                #pragma unroll
                for (int x = 0; x < 4; x++) c2[i][j][x] = 0.f;

        #pragma unroll
        for (int ks = 0; ks < 8; ++ks) {
            const uint32_t koff = (uint32_t)(ks * 2048);
            uint32_t bfr[4];
            LDSM_X4T(bfr[0], bfr[1], bfr[2], bfr[3], badr + koff);
            #pragma unroll
            for (int mt = 0; mt < 4; ++mt) {
                uint32_t afr[4];
                LDSM_X4T(afr[0], afr[1], afr[2], afr[3], aadr[mt] + koff);
                MMA16816(c2[mt][0][0], c2[mt][0][1], c2[mt][0][2], c2[mt][0][3],
                         afr[0], afr[1], afr[2], afr[3], bfr[0], bfr[2]);
                MMA16816(c2[mt][1][0], c2[mt][1][1], c2[mt][1][2], c2[mt][1][3],
                         afr[0], afr[1], afr[2], afr[3], bfr[1], bfr[3]);
            }
        }

        // accumulate directly into g_ctx (RED.F32, spread addresses)
        float* outp = g_ctx + (long)(bidb * HEADS + h) * (DHEAD * DHEAD);
        const int e0 = wid * 16 + cq;
        #pragma unroll
        for (int mt = 0; mt < 4; ++mt) {
            int d0 = mt * 16 + (lane >> 2);
            #pragma unroll
            for (int nt = 0; nt < 2; ++nt) {
                atomicAdd(&outp[(d0)     * DHEAD + e0 + nt * 8],     c2[mt][nt][0]);
                atomicAdd(&outp[(d0)     * DHEAD + e0 + nt * 8 + 1], c2[mt][nt][1]);
                atomicAdd(&outp[(d0 + 8) * DHEAD + e0 + nt * 8],     c2[mt][nt][2]);
                atomicAdd(&outp[(d0 + 8) * DHEAD + e0 + nt * 8 + 1], c2[mt][nt][3]);
            }
        }
    }
}

// ---------------------------------------------------------------------------
// Small kernels
// ---------------------------------------------------------------------------
// fp32 -> fp16 conversion; first 512 blocks also zero g_ctx (131072 floats).
__global__ void f2h_kernel(const float* __restrict__ in)
{
    long i = (long)blockIdx.x * 256 + threadIdx.x;
    if (blockIdx.x < 512)
        g_ctx[blockIdx.x * 256 + threadIdx.x] = 0.f;
    float4 f = ((const float4*)in)[i];
    ((__half2*)g_featsh)[2 * i]     = __floats2half2_rn(f.x, f.y);
    ((__half2*)g_featsh)[2 * i + 1] = __floats2half2_rn(f.z, f.w);
}

// W_qkv transpose with head-interleaved permutation + S zeroing.
__global__ void wtrans_kernel(const float* __restrict__ W)
{
    if (blockIdx.x < 8 && blockIdx.y == 0)
        g_S[blockIdx.x * 256 + threadIdx.x] = 0.f;

    __shared__ float t[32][33];
    const int n0 = blockIdx.x * 32, k0 = blockIdx.y * 32;
    const int tx = threadIdx.x & 31, ty = threadIdx.x >> 5;
    #pragma unroll
    for (int j = 0; j < 4; ++j)
        t[ty + 8 * j][tx] = W[(long)(k0 + ty + 8 * j) * QKV_COLS + n0 + tx];
    __syncthreads();
    #pragma unroll
    for (int j = 0; j < 4; ++j) {
        int n = n0 + ty + 8 * j;
        int row;
        if (n < 1024)       row = n;
        else if (n < 2048)  row = 1024 + ((n - 1024) >> 6) * 128 + ((n - 1024) & 63);
        else                row = 1024 + ((n - 2048) >> 6) * 128 + 64 + ((n - 2048) & 63);
        g_Wt[(long)row * DIM + k0 + tx] = __float2half_rn(t[tx][ty + 8 * j]);
    }
}

// W_out transpose -> fp16: WoT[n][k] = W_out[k][n]
__global__ void wouttrans_kernel(const float* __restrict__ W)
{
    __shared__ float t[32][33];
    const int n0 = blockIdx.x * 32, k0 = blockIdx.y * 32;
    const int tx = threadIdx.x & 31, ty = threadIdx.x >> 5;
    #pragma unroll
    for (int j = 0; j < 4; ++j)
        t[ty + 8 * j][tx] = W[(long)(k0 + ty + 8 * j) * DIM + n0 + tx];
    __syncthreads();
    #pragma unroll
    for (int j = 0; j < 4; ++j)
        g_WoT[(long)(n0 + ty + 8 * j) * DIM + k0 + tx] = __float2half_rn(t[tx][ty + 8 * j]);
}

// ---------------------------------------------------------------------------
// HMMA make_M: Mh[b][n][h*64+d] = sum_d2 WoT[n][h*64+d2] * ctx[bh][d][d2]/S[d]
// grid (8 n-tiles of 128, 32 bh), 128 threads (4 warps, 32 rows each).
// ---------------------------------------------------------------------------
__global__ __launch_bounds__(128, 4)
void make_M_kernel()
{
    const int ntb = blockIdx.x;        // n-tile (128 rows)
    const int bh = blockIdx.y;
    const int b = bh >> 4;
    const int h = bh & 15;

    __shared__ __align__(16) char sm[16384 + 8192];   // A: 128x128B, B: 64x128B
    const uint32_t sa = smem_u32(sm);
    const uint32_t sb = sa + 16384;

    const int tid = threadIdx.x;
    const int wid = tid >> 5;
    const int lane = tid & 31;

    // ---- A tile: WoT[ntb*128 + r][h*64 ..+64] via cp.async (8 x 16B per thread)
    {
        const int r = tid >> 3;        // 0..15
        const int c = tid & 7;
        const uint32_t off = (uint32_t)(r * 128 + ((c ^ (r & 7)) * 16));
        const __half* ap = g_WoT + (long)(ntb * 128 + r) * DIM + h * 64 + c * 8;
        #pragma unroll
        for (int i = 0; i < 8; ++i) {
            CP_ASYNC16(sa + off + i * 2048, ap);
            ap += (long)16 * DIM;
        }
        CP_COMMIT();
    }

    // ---- B tile: ctx[bh][d][d2]/S[d] -> fp16 (each thread: 32 cols of one row)
    {
        const int d = tid >> 1;
        const int cb = (tid & 1) * 32;
        const float inv = 1.f / g_S[b * DIM + h * DHEAD + d];
        const float* cp = g_ctx + (long)bh * (DHEAD * DHEAD) + d * DHEAD + cb;
        __align__(16) __half hv[32];
        #pragma unroll
        for (int j = 0; j < 8; ++j) {
            float4 f = *(const float4*)(cp + j * 4);
            hv[j*4+0] = __float2half_rn(f.x * inv);
            hv[j*4+1] = __float2half_rn(f.y * inv);
            hv[j*4+2] = __float2half_rn(f.z * inv);
            hv[j*4+3] = __float2half_rn(f.w * inv);
        }
        #pragma unroll
        for (int j = 0; j < 4; ++j)
            *(uint4*)(sm + 16384 + SWZ((uint32_t)(d * 128 + cb * 2 + j * 16))) = ((const uint4*)hv)[j];
    }
    cp_wait<0>();
    __syncthreads();

    // ---- MMA: warp tile 32(m) x 64(n), K=64 ----
    const int lrow = lane & 15;
    const int lsel = lane >> 4;

    uint32_t a_row[2], b_row[4], ksel[4];
    #pragma unroll
    for (int mt = 0; mt < 2; ++mt) a_row[mt] = (uint32_t)(wid * 32 + mt * 16 + lrow) * 128;
    #pragma unroll
    for (int np = 0; np < 4; ++np) b_row[np] = (uint32_t)(np * 16 + lrow) * 128;
    #pragma unroll
    for (int ks = 0; ks < 4; ++ks) ksel[ks] = (uint32_t)(((2 * ks + lsel) ^ (lrow & 7)) * 16);

    float acc[2][8][4];
    #pragma unroll
    for (int i = 0; i < 2; i++)
        #pragma unroll
        for (int j = 0; j < 8; j++)
            #pragma unroll
            for (int x = 0; x < 4; x++) acc[i][j][x] = 0.f;

    #pragma unroll
    for (int ks = 0; ks < 4; ++ks) {
        uint32_t af[2][4], bf[4][4];
        #pragma unroll
        for (int mt = 0; mt < 2; ++mt)
            LDSM_X4(af[mt][0], af[mt][1], af[mt][2], af[mt][3], sa + a_row[mt] + ksel[ks]);
        #pragma unroll
        for (int np = 0; np < 4; ++np)
            LDSM_X4(bf[np][0], bf[np][1], bf[np][2], bf[np][3], sb + b_row[np] + ksel[ks]);
        #pragma unroll
        for (int mt = 0; mt < 2; ++mt) {
            #pragma unroll
            for (int np = 0; np < 4; ++np) {
                MMA16816(acc[mt][2*np][0], acc[mt][2*np][1], acc[mt][2*np][2], acc[mt][2*np][3],
                         af[mt][0], af[mt][1], af[mt][2], af[mt][3],
                         bf[np][0], bf[np][2]);
                MMA16816(acc[mt][2*np+1][0], acc[mt][2*np+1][1], acc[mt][2*np+1][2], acc[mt][2*np+1][3],
                         af[mt][0], af[mt][1], af[mt][2], af[mt][3],
                         bf[np][1], bf[np][3]);
            }
        }
    }

    // ---- store fp16 to g_Mh[b][n][h*64 + d] ----
    const int cq = (lane & 3) * 2;
    __half* mp = g_Mh + (long)b * DIM * DIM;
    #pragma unroll
    for (int mt = 0; mt < 2; ++mt) {
        int row = ntb * 128 + wid * 32 + mt * 16 + (lane >> 2);
        #pragma unroll
        for (int nt = 0; nt < 8; ++nt) {
            int col = h * 64 + nt * 8 + cq;
            *(__half2*)&mp[(long)row * DIM + col]       = __floats2half2_rn(acc[mt][nt][0], acc[mt][nt][1]);
            *(__half2*)&mp[(long)(row + 8) * DIM + col] = __floats2half2_rn(acc[mt][nt][2], acc[mt][nt][3]);
        }
    }
}

// ---------------------------------------------------------------------------
// Launch
// ---------------------------------------------------------------------------
extern "C" void kernel_launch(void* const* d_in, const int* in_sizes, int n_in,
                              void* d_out, int out_size)
{
    const float* feats = (const float*)d_in[0];
    const float* W_qkv = (const float*)d_in[1];
    const float* W_out = (const float*)d_in[2];
    float* out = (float*)d_out;

    cudaFuncSetAttribute(hgemm_kernel<0>, cudaFuncAttributeMaxDynamicSharedMemorySize, HG_SMEM);
    cudaFuncSetAttribute(hgemm_kernel<1>, cudaFuncAttributeMaxDynamicSharedMemorySize, HG_SMEM);

    __half* featsh; cudaGetSymbolAddress((void**)&featsh, g_featsh);
    __half* Wt;     cudaGetSymbolAddress((void**)&Wt, g_Wt);
    __half* qh;     cudaGetSymbolAddress((void**)&qh, g_qh);
    __half* Mh;     cudaGetSymbolAddress((void**)&Mh, g_Mh);

    f2h_kernel<<<(M_ROWS * DIM / 4) / 256, 256>>>(feats);
    wtrans_kernel<<<dim3(QKV_COLS / 32, DIM / 32), 256>>>(W_qkv);
    wouttrans_kernel<<<dim3(DIM / 32, DIM / 32), 256>>>(W_out);

    // 1) fused qkv GEMM (q softmax + in-epilogue ctx partials -> atomic g_ctx)
    hgemm_kernel<0><<<dim3(QKV_COLS / HG_BN, M_ROWS / HG_BM, 1), 128, HG_SMEM>>>(
        featsh, Wt, nullptr, DIM, DIM, DIM, 0, 0, 0, 0);

    // 2) M_b^T fp16 (HMMA)
    make_M_kernel<<<dim3(8, 32), 128>>>();

    // 3) out = q' @ M_b
    hgemm_kernel<1><<<dim3(DIM / HG_BN, N_SEQ / HG_BM, B), 128, HG_SMEM>>>(
        qh, Mh, out, DIM, DIM, DIM, DIM,
        (long)N_SEQ * DIM, (long)DIM * DIM, (long)N_SEQ * DIM);
}

// round 15
// speedup vs baseline: 6.8748x; 1.0070x over previous
#include <cuda_runtime.h>
#include <cuda_fp16.h>
#include <cstdint>
#include <math.h>

// Problem constants
#define B 2
#define N_SEQ 4096
#define DIM 1024
#define HEADS 16
#define DHEAD 64
#define M_ROWS (B * N_SEQ)        // 8192
#define QKV_COLS (3 * DIM)        // 3072

// ---------------------------------------------------------------------------
// Scratch (device globals)
// ---------------------------------------------------------------------------
__device__ __half g_featsh[(size_t)M_ROWS * DIM];        // feats fp16
__device__ __half g_Wt[(size_t)QKV_COLS * DIM];          // permuted W_qkv^T fp16
__device__ __half g_WoT[(size_t)DIM * DIM];              // W_out^T fp16 [n][k]
__device__ __half g_qh[(size_t)M_ROWS * DIM];            // q' (softmaxed*scale) fp16
__device__ __half g_Mh[(size_t)B * DIM * DIM];           // M_b^T fp16
__device__ float  g_S[B * DIM];                          // colsum exp(k)
__device__ float  g_ctx[B * HEADS * DHEAD * DHEAD];      // ctx accumulators (atomic)

// ---------------------------------------------------------------------------
// Helpers
// ---------------------------------------------------------------------------
__device__ __forceinline__ uint32_t smem_u32(const void* p) {
    uint32_t a;
    asm("{ .reg .u64 t; cvta.to.shared.u64 t, %1; cvt.u32.u64 %0, t; }" : "=r"(a) : "l"(p));
    return a;
}
#define CP_ASYNC16(smem, g) \
    asm volatile("cp.async.cg.shared.global [%0], [%1], 16;" :: "r"((uint32_t)(smem)), "l"(g) : "memory")
#define CP_COMMIT() asm volatile("cp.async.commit_group;" ::: "memory")
template <int N> __device__ __forceinline__ void cp_wait() {
    asm volatile("cp.async.wait_group %0;" :: "n"(N) : "memory");
}
#define SWZ(x) ((x) ^ (((x) >> 3) & 0x70))

#define LDSM_X4(r0, r1, r2, r3, addr) \
    asm volatile("ldmatrix.sync.aligned.m8n8.x4.shared.b16 {%0,%1,%2,%3}, [%4];" \
                 : "=r"(r0), "=r"(r1), "=r"(r2), "=r"(r3) : "r"(addr))

#define LDSM_X4T(r0, r1, r2, r3, addr) \
    asm volatile("ldmatrix.sync.aligned.m8n8.x4.trans.shared.b16 {%0,%1,%2,%3}, [%4];" \
                 : "=r"(r0), "=r"(r1), "=r"(r2), "=r"(r3) : "r"(addr))

#define MMA16816(c0, c1, c2, c3, a0, a1, a2, a3, b0, b1) \
    asm volatile("mma.sync.aligned.m16n8k16.row.col.f32.f16.f16.f32 " \
                 "{%0,%1,%2,%3}, {%4,%5,%6,%7}, {%8,%9}, {%0,%1,%2,%3};" \
                 : "+f"(c0), "+f"(c1), "+f"(c2), "+f"(c3) \
                 : "r"(a0), "r"(a1), "r"(a2), "r"(a3), "r"(b0), "r"(b1))

// ---------------------------------------------------------------------------
// HMMA fp16 GEMM: 128x128 CTA tile, 4 warps, warp tile 64x64, K-chunk 64,
// 3-stage cp.async (96 KB), 2 CTAs/SM, fragment double-buffering.
// MODE 0 (qkv): W columns permuted as [q | (k_h,v_h) per head].
//   bn <  1024 : q epilogue (softmax*scale -> g_qh fp16)
//   bn >= 1024 : head tile [exp(k_h) | v_h]; in-epilogue ctx partial via HMMA
//                -> atomicAdd into g_ctx, colsums -> g_S.
// MODE 1: plain fp32 C store.
// ---------------------------------------------------------------------------
#define HG_BM 128
#define HG_BN 128
#define STG_A (HG_BM * 128)            // 16 KB
#define STG_B (HG_BN * 128)            // 16 KB
#define STG_BYTES (STG_A + STG_B)      // 32 KB
#define HG_STAGES 3
#define HG_SMEM (HG_STAGES * STG_BYTES)  // 96 KB

template <int MODE>
__global__ __launch_bounds__(128, 2)
void hgemm_kernel(const __half* __restrict__ A, const __half* __restrict__ Bh,
                  float* __restrict__ C, int K, int lda, int ldb, int ldc,
                  long aB, long bB, long cB)
{
    A  += (long)blockIdx.z * aB;
    Bh += (long)blockIdx.z * bB;
    if (MODE == 1) C += (long)blockIdx.z * cB;

    extern __shared__ char smem[];
    const uint32_t sbase = smem_u32(smem);
    const int tid  = threadIdx.x;
    const int wid  = tid >> 5;
    const int lane = tid & 31;
    const int wm = wid >> 1;           // 0..1 (64 rows)
    const int wn = wid & 1;            // 0..1 (64 cols)
    const int bm = blockIdx.y * HG_BM;
    const int bn = blockIdx.x * HG_BN;
    const int NC = K >> 6;

    const int r0   = tid >> 3;          // 0..15
    const int c16  = tid & 7;
    const uint32_t offLd = (uint32_t)(r0 * 128 + ((c16 ^ (r0 & 7)) * 16));
    const __half* apg = A + (long)(bm + r0) * lda + c16 * 8;
    const __half* bpg = Bh + (long)(bn + r0) * ldb + c16 * 8;
    const long strideA = (long)16 * lda;
    const long strideB = (long)16 * ldb;

    auto load_chunk = [&](int kc, int st) {
        const uint32_t sa = sbase + st * STG_BYTES + offLd;
        const uint32_t sb = sa + STG_A;
        const __half* ap = apg + kc * 64;
        const __half* bp = bpg + kc * 64;
        #pragma unroll
        for (int i = 0; i < 8; ++i) { CP_ASYNC16(sa + i * 2048, ap); ap += strideA; }
        #pragma unroll
        for (int i = 0; i < 8; ++i) { CP_ASYNC16(sb + i * 2048, bp); bp += strideB; }
    };

    float acc[4][8][4];
    #pragma unroll
    for (int i = 0; i < 4; i++)
        #pragma unroll
        for (int j = 0; j < 8; j++)
            #pragma unroll
            for (int x = 0; x < 4; x++) acc[i][j][x] = 0.f;

    load_chunk(0, 0); CP_COMMIT();
    load_chunk(1, 1); CP_COMMIT();

    const int lrow = lane & 15;
    const int lsel = lane >> 4;

    uint32_t a_row[4], b_row[4], ksel[4];
    #pragma unroll
    for (int mt = 0; mt < 4; ++mt) a_row[mt] = (uint32_t)(wm * 64 + mt * 16 + lrow) * 128;
    #pragma unroll
    for (int np = 0; np < 4; ++np) b_row[np] = (uint32_t)(wn * 64 + np * 16 + lrow) * 128;
    #pragma unroll
    for (int ks = 0; ks < 4; ++ks) ksel[ks] = (uint32_t)(((2 * ks + lsel) ^ (lrow & 7)) * 16);

    uint32_t af[2][4][4], bf[2][4][4];

    int st = 0, stl = 2;
    for (int c = 0; c < NC; ++c) {
        cp_wait<1>();
        __syncthreads();
        if (c + 2 < NC) load_chunk(c + 2, stl);
        CP_COMMIT();

        const uint32_t sa = sbase + st * STG_BYTES;
        const uint32_t sb = sa + STG_A;

        #pragma unroll
        for (int mt = 0; mt < 4; ++mt)
            LDSM_X4(af[0][mt][0], af[0][mt][1], af[0][mt][2], af[0][mt][3], sa + a_row[mt] + ksel[0]);
        #pragma unroll
        for (int np = 0; np < 4; ++np)
            LDSM_X4(bf[0][np][0], bf[0][np][1], bf[0][np][2], bf[0][np][3], sb + b_row[np] + ksel[0]);

        #pragma unroll
        for (int ks = 0; ks < 4; ++ks) {
            const int cur = ks & 1;
            const int nxt = cur ^ 1;
            if (ks < 3) {
                #pragma unroll
                for (int mt = 0; mt < 4; ++mt)
                    LDSM_X4(af[nxt][mt][0], af[nxt][mt][1], af[nxt][mt][2], af[nxt][mt][3],
                            sa + a_row[mt] + ksel[ks + 1]);
                #pragma unroll
                for (int np = 0; np < 4; ++np)
                    LDSM_X4(bf[nxt][np][0], bf[nxt][np][1], bf[nxt][np][2], bf[nxt][np][3],
                            sb + b_row[np] + ksel[ks + 1]);
            }
            #pragma unroll
            for (int mt = 0; mt < 4; ++mt) {
                #pragma unroll
                for (int np = 0; np < 4; ++np) {
                    MMA16816(acc[mt][2*np][0], acc[mt][2*np][1], acc[mt][2*np][2], acc[mt][2*np][3],
                             af[cur][mt][0], af[cur][mt][1], af[cur][mt][2], af[cur][mt][3],
                             bf[cur][np][0], bf[cur][np][2]);
                    MMA16816(acc[mt][2*np+1][0], acc[mt][2*np+1][1], acc[mt][2*np+1][2], acc[mt][2*np+1][3],
                             af[cur][mt][0], af[cur][mt][1], af[cur][mt][2], af[cur][mt][3],
                             bf[cur][np][1], bf[cur][np][3]);
                }
            }
        }
        if (++st == HG_STAGES) st = 0;
        if (++stl == HG_STAGES) stl = 0;
    }

    // ------------------------- epilogue -------------------------
    const int r_base = bm + wm * 64;
    const int cq = (lane & 3) * 2;

    if (MODE == 1) {
        #pragma unroll
        for (int mt = 0; mt < 4; ++mt) {
            int r0e = r_base + mt * 16 + (lane >> 2);
            #pragma unroll
            for (int nt = 0; nt < 8; ++nt) {
                int col = bn + wn * 64 + nt * 8 + cq;
                *(float2*)&C[(long)r0e * ldc + col]       = make_float2(acc[mt][nt][0], acc[mt][nt][1]);
                *(float2*)&C[(long)(r0e + 8) * ldc + col] = make_float2(acc[mt][nt][2], acc[mt][nt][3]);
            }
        }
    } else if (bn < 1024) {
        // ---- q region: softmax over the warp's 64 cols (= one head) ----
        #pragma unroll
        for (int mt = 0; mt < 4; ++mt) {
            #pragma unroll
            for (int hf = 0; hf < 2; ++hf) {
                int row = r_base + mt * 16 + (lane >> 2) + 8 * hf;
                float mx = -1e30f;
                #pragma unroll
                for (int nt = 0; nt < 8; ++nt)
                    mx = fmaxf(mx, fmaxf(acc[mt][nt][2*hf], acc[mt][nt][2*hf+1]));
                mx = fmaxf(mx, __shfl_xor_sync(0xFFFFFFFFu, mx, 1));
                mx = fmaxf(mx, __shfl_xor_sync(0xFFFFFFFFu, mx, 2));
                float s = 0.f;
                #pragma unroll
                for (int nt = 0; nt < 8; ++nt) {
                    float e0 = __expf(acc[mt][nt][2*hf]   - mx);
                    float e1 = __expf(acc[mt][nt][2*hf+1] - mx);
                    acc[mt][nt][2*hf] = e0; acc[mt][nt][2*hf+1] = e1;
                    s += e0 + e1;
                }
                s += __shfl_xor_sync(0xFFFFFFFFu, s, 1);
                s += __shfl_xor_sync(0xFFFFFFFFu, s, 2);
                float inv = 0.125f / s;
                #pragma unroll
                for (int nt = 0; nt < 8; ++nt) {
                    int col = bn + wn * 64 + nt * 8 + cq;
                    *(__half2*)&g_qh[(long)row * DIM + col] =
                        __floats2half2_rn(acc[mt][nt][2*hf] * inv, acc[mt][nt][2*hf+1] * inv);
                }
            }
        }
    } else {
        // ---- kv region: this CTA holds [exp(k_h) | v_h] for one head ----
        const int h = (bn - 1024) >> 7;
        const int bidb = bm >> 12;
        const uint32_t kTu = sbase;               // 128 x 64 fp16 (128B rows)
        const uint32_t vTu = sbase + 16384;

        __syncthreads();   // all warps done reading stage smem

        if (wn == 0) {
            // exp(k) -> kT smem, colsums -> g_S
            float cs[8][2];
            #pragma unroll
            for (int nt = 0; nt < 8; ++nt) { cs[nt][0] = 0.f; cs[nt][1] = 0.f; }
            #pragma unroll
            for (int mt = 0; mt < 4; ++mt) {
                int rr = wm * 64 + mt * 16 + (lane >> 2);
                #pragma unroll
                for (int nt = 0; nt < 8; ++nt) {
                    float e0 = __expf(acc[mt][nt][0]);
                    float e1 = __expf(acc[mt][nt][1]);
                    float e2 = __expf(acc[mt][nt][2]);
                    float e3 = __expf(acc[mt][nt][3]);
                    cs[nt][0] += e0 + e2;
                    cs[nt][1] += e1 + e3;
                    int cb = (nt * 8 + cq) * 2;     // byte col
                    *(__half2*)(smem + SWZ((uint32_t)(rr * 128 + cb)))       = __floats2half2_rn(e0, e1);
                    *(__half2*)(smem + SWZ((uint32_t)((rr + 8) * 128 + cb))) = __floats2half2_rn(e2, e3);
                }
            }
            #pragma unroll
            for (int nt = 0; nt < 8; ++nt) {
                #pragma unroll
                for (int j = 0; j < 2; ++j) {
                    float cc = cs[nt][j];
                    cc += __shfl_xor_sync(0xFFFFFFFFu, cc, 4);
                    cc += __shfl_xor_sync(0xFFFFFFFFu, cc, 8);
                    cc += __shfl_xor_sync(0xFFFFFFFFu, cc, 16);
                    if (lane < 4)
                        atomicAdd(&g_S[bidb * DIM + h * DHEAD + nt * 8 + cq + j], cc);
                }
            }
        } else {
            // v -> vT smem
            #pragma unroll
            for (int mt = 0; mt < 4; ++mt) {
                int rr = wm * 64 + mt * 16 + (lane >> 2);
                #pragma unroll
                for (int nt = 0; nt < 8; ++nt) {
                    int cb = (nt * 8 + cq) * 2;
                    *(__half2*)(smem + 16384 + SWZ((uint32_t)(rr * 128 + cb)))       = __floats2half2_rn(acc[mt][nt][0], acc[mt][nt][1]);
                    *(__half2*)(smem + 16384 + SWZ((uint32_t)((rr + 8) * 128 + cb))) = __floats2half2_rn(acc[mt][nt][2], acc[mt][nt][3]);
                }
            }
        }
        __syncthreads();

        // ctx partial: ekT(128x64)^T @ vT(128x64) -> [64d x 64e], warp wid owns e wid*16..+16
        const int l7 = lane & 7;
        const int row16 = l7 + ((lane & 16) >> 1);
        const int coloff = lane & 8;

        uint32_t aadr[4];
        #pragma unroll
        for (int mt = 0; mt < 4; ++mt)
            aadr[mt] = kTu + SWZ((uint32_t)(row16 * 128 + (mt * 16 + coloff) * 2));
        uint32_t badr = vTu + SWZ((uint32_t)(row16 * 128 + (wid * 16 + coloff) * 2));

        float c2[4][2][4];
        #pragma unroll
        for (int i = 0; i < 4; i++)
            #pragma unroll
            for (int j = 0; j < 2; j++)
                #pragma unroll
                for (int x = 0; x < 4; x++) c2[i][j][x] = 0.f;

        #pragma unroll
        for (int ks = 0; ks < 8; ++ks) {
            const uint32_t koff = (uint32_t)(ks * 2048);
            uint32_t bfr[4];
            LDSM_X4T(bfr[0], bfr[1], bfr[2], bfr[3], badr + koff);
            #pragma unroll
            for (int mt = 0; mt < 4; ++mt) {
                uint32_t afr[4];
                LDSM_X4T(afr[0], afr[1], afr[2], afr[3], aadr[mt] + koff);
                MMA16816(c2[mt][0][0], c2[mt][0][1], c2[mt][0][2], c2[mt][0][3],
                         afr[0], afr[1], afr[2], afr[3], bfr[0], bfr[2]);
                MMA16816(c2[mt][1][0], c2[mt][1][1], c2[mt][1][2], c2[mt][1][3],
                         afr[0], afr[1], afr[2], afr[3], bfr[1], bfr[3]);
            }
        }

        // accumulate directly into g_ctx (RED.F32, spread addresses)
        float* outp = g_ctx + (long)(bidb * HEADS + h) * (DHEAD * DHEAD);
        const int e0 = wid * 16 + cq;
        #pragma unroll
        for (int mt = 0; mt < 4; ++mt) {
            int d0 = mt * 16 + (lane >> 2);
            #pragma unroll
            for (int nt = 0; nt < 2; ++nt) {
                atomicAdd(&outp[(d0)     * DHEAD + e0 + nt * 8],     c2[mt][nt][0]);
                atomicAdd(&outp[(d0)     * DHEAD + e0 + nt * 8 + 1], c2[mt][nt][1]);
                atomicAdd(&outp[(d0 + 8) * DHEAD + e0 + nt * 8],     c2[mt][nt][2]);
                atomicAdd(&outp[(d0 + 8) * DHEAD + e0 + nt * 8 + 1], c2[mt][nt][3]);
            }
        }
    }
}

// ---------------------------------------------------------------------------
// Small kernels
// ---------------------------------------------------------------------------
// fp32 -> fp16 conversion; first 512 blocks also zero g_ctx (131072 floats).
__global__ void f2h_kernel(const float* __restrict__ in)
{
    long i = (long)blockIdx.x * 256 + threadIdx.x;
    if (blockIdx.x < 512)
        g_ctx[blockIdx.x * 256 + threadIdx.x] = 0.f;
    float4 f = ((const float4*)in)[i];
    ((__half2*)g_featsh)[2 * i]     = __floats2half2_rn(f.x, f.y);
    ((__half2*)g_featsh)[2 * i + 1] = __floats2half2_rn(f.z, f.w);
}

// W_qkv transpose with head-interleaved permutation + S zeroing.
__global__ void wtrans_kernel(const float* __restrict__ W)
{
    if (blockIdx.x < 8 && blockIdx.y == 0)
        g_S[blockIdx.x * 256 + threadIdx.x] = 0.f;

    __shared__ float t[32][33];
    const int n0 = blockIdx.x * 32, k0 = blockIdx.y * 32;
    const int tx = threadIdx.x & 31, ty = threadIdx.x >> 5;
    #pragma unroll
    for (int j = 0; j < 4; ++j)
        t[ty + 8 * j][tx] = W[(long)(k0 + ty + 8 * j) * QKV_COLS + n0 + tx];
    __syncthreads();
    #pragma unroll
    for (int j = 0; j < 4; ++j) {
        int n = n0 + ty + 8 * j;
        int row;
        if (n < 1024)       row = n;
        else if (n < 2048)  row = 1024 + ((n - 1024) >> 6) * 128 + ((n - 1024) & 63);
        else                row = 1024 + ((n - 2048) >> 6) * 128 + 64 + ((n - 2048) & 63);
        g_Wt[(long)row * DIM + k0 + tx] = __float2half_rn(t[tx][ty + 8 * j]);
    }
}

// W_out transpose -> fp16: WoT[n][k] = W_out[k][n]
__global__ void wouttrans_kernel(const float* __restrict__ W)
{
    __shared__ float t[32][33];
    const int n0 = blockIdx.x * 32, k0 = blockIdx.y * 32;
    const int tx = threadIdx.x & 31, ty = threadIdx.x >> 5;
    #pragma unroll
    for (int j = 0; j < 4; ++j)
        t[ty + 8 * j][tx] = W[(long)(k0 + ty + 8 * j) * DIM + n0 + tx];
    __syncthreads();
    #pragma unroll
    for (int j = 0; j < 4; ++j)
        g_WoT[(long)(n0 + ty + 8 * j) * DIM + k0 + tx] = __float2half_rn(t[tx][ty + 8 * j]);
}

// ---------------------------------------------------------------------------
// HMMA make_M: Mh[b][n][h*64+d] = sum_d2 WoT[n][h*64+d2] * ctx[bh][d][d2]/S[d]
// grid (8 n-tiles of 128, 32 bh), 128 threads (4 warps, 32 rows each).
// ---------------------------------------------------------------------------
__global__ __launch_bounds__(128, 4)
void make_M_kernel()
{
    const int ntb = blockIdx.x;        // n-tile (128 rows)
    const int bh = blockIdx.y;
    const int b = bh >> 4;
    const int h = bh & 15;

    __shared__ __align__(16) char sm[16384 + 8192];   // A: 128x128B, B: 64x128B
    const uint32_t sa = smem_u32(sm);
    const uint32_t sb = sa + 16384;

    const int tid = threadIdx.x;
    const int wid = tid >> 5;
    const int lane = tid & 31;

    // ---- A tile: WoT[ntb*128 + r][h*64 ..+64] via cp.async (8 x 16B per thread)
    {
        const int r = tid >> 3;        // 0..15
        const int c = tid & 7;
        const uint32_t off = (uint32_t)(r * 128 + ((c ^ (r & 7)) * 16));
        const __half* ap = g_WoT + (long)(ntb * 128 + r) * DIM + h * 64 + c * 8;
        #pragma unroll
        for (int i = 0; i < 8; ++i) {
            CP_ASYNC16(sa + off + i * 2048, ap);
            ap += (long)16 * DIM;
        }
        CP_COMMIT();
    }

    // ---- B tile: ctx[bh][d][d2]/S[d] -> fp16 (each thread: 32 cols of one row)
    {
        const int d = tid >> 1;
        const int cb = (tid & 1) * 32;
        const float inv = 1.f / g_S[b * DIM + h * DHEAD + d];
        const float* cp = g_ctx + (long)bh * (DHEAD * DHEAD) + d * DHEAD + cb;
        __align__(16) __half hv[32];
        #pragma unroll
        for (int j = 0; j < 8; ++j) {
            float4 f = *(const float4*)(cp + j * 4);
            hv[j*4+0] = __float2half_rn(f.x * inv);
            hv[j*4+1] = __float2half_rn(f.y * inv);
            hv[j*4+2] = __float2half_rn(f.z * inv);
            hv[j*4+3] = __float2half_rn(f.w * inv);
        }
        #pragma unroll
        for (int j = 0; j < 4; ++j)
            *(uint4*)(sm + 16384 + SWZ((uint32_t)(d * 128 + cb * 2 + j * 16))) = ((const uint4*)hv)[j];
    }
    cp_wait<0>();
    __syncthreads();

    // ---- MMA: warp tile 32(m) x 64(n), K=64 ----
    const int lrow = lane & 15;
    const int lsel = lane >> 4;

    uint32_t a_row[2], b_row[4], ksel[4];
    #pragma unroll
    for (int mt = 0; mt < 2; ++mt) a_row[mt] = (uint32_t)(wid * 32 + mt * 16 + lrow) * 128;
    #pragma unroll
    for (int np = 0; np < 4; ++np) b_row[np] = (uint32_t)(np * 16 + lrow) * 128;
    #pragma unroll
    for (int ks = 0; ks < 4; ++ks) ksel[ks] = (uint32_t)(((2 * ks + lsel) ^ (lrow & 7)) * 16);

    float acc[2][8][4];
    #pragma unroll
    for (int i = 0; i < 2; i++)
        #pragma unroll
        for (int j = 0; j < 8; j++)
            #pragma unroll
            for (int x = 0; x < 4; x++) acc[i][j][x] = 0.f;

    #pragma unroll
    for (int ks = 0; ks < 4; ++ks) {
        uint32_t af[2][4], bf[4][4];
        #pragma unroll
        for (int mt = 0; mt < 2; ++mt)
            LDSM_X4(af[mt][0], af[mt][1], af[mt][2], af[mt][3], sa + a_row[mt] + ksel[ks]);
        #pragma unroll
        for (int np = 0; np < 4; ++np)
            LDSM_X4(bf[np][0], bf[np][1], bf[np][2], bf[np][3], sb + b_row[np] + ksel[ks]);
        #pragma unroll
        for (int mt = 0; mt < 2; ++mt) {
            #pragma unroll
            for (int np = 0; np < 4; ++np) {
                MMA16816(acc[mt][2*np][0], acc[mt][2*np][1], acc[mt][2*np][2], acc[mt][2*np][3],
                         af[mt][0], af[mt][1], af[mt][2], af[mt][3],
                         bf[np][0], bf[np][2]);
                MMA16816(acc[mt][2*np+1][0], acc[mt][2*np+1][1], acc[mt][2*np+1][2], acc[mt][2*np+1][3],
                         af[mt][0], af[mt][1], af[mt][2], af[mt][3],
                         bf[np][1], bf[np][3]);
            }
        }
    }

    // ---- store fp16 to g_Mh[b][n][h*64 + d] ----
    const int cq = (lane & 3) * 2;
    __half* mp = g_Mh + (long)b * DIM * DIM;
    #pragma unroll
    for (int mt = 0; mt < 2; ++mt) {
        int row = ntb * 128 + wid * 32 + mt * 16 + (lane >> 2);
        #pragma unroll
        for (int nt = 0; nt < 8; ++nt) {
            int col = h * 64 + nt * 8 + cq;
            *(__half2*)&mp[(long)row * DIM + col]       = __floats2half2_rn(acc[mt][nt][0], acc[mt][nt][1]);
            *(__half2*)&mp[(long)(row + 8) * DIM + col] = __floats2half2_rn(acc[mt][nt][2], acc[mt][nt][3]);
        }
    }
}

// ---------------------------------------------------------------------------
// Launch
// ---------------------------------------------------------------------------
extern "C" void kernel_launch(void* const* d_in, const int* in_sizes, int n_in,
                              void* d_out, int out_size)
{
    const float* feats = (const float*)d_in[0];
    const float* W_qkv = (const float*)d_in[1];
    const float* W_out = (const float*)d_in[2];
    float* out = (float*)d_out;

    cudaFuncSetAttribute(hgemm_kernel<0>, cudaFuncAttributeMaxDynamicSharedMemorySize, HG_SMEM);
    cudaFuncSetAttribute(hgemm_kernel<1>, cudaFuncAttributeMaxDynamicSharedMemorySize, HG_SMEM);

    __half* featsh; cudaGetSymbolAddress((void**)&featsh, g_featsh);
    __half* Wt;     cudaGetSymbolAddress((void**)&Wt, g_Wt);
    __half* qh;     cudaGetSymbolAddress((void**)&qh, g_qh);
    __half* Mh;     cudaGetSymbolAddress((void**)&Mh, g_Mh);

    f2h_kernel<<<(M_ROWS * DIM / 4) / 256, 256>>>(feats);
    wtrans_kernel<<<dim3(QKV_COLS / 32, DIM / 32), 256>>>(W_qkv);
    wouttrans_kernel<<<dim3(DIM / 32, DIM / 32), 256>>>(W_out);

    // 1) fused qkv GEMM (q softmax + in-epilogue ctx partials -> atomic g_ctx)
    hgemm_kernel<0><<<dim3(QKV_COLS / HG_BN, M_ROWS / HG_BM, 1), 128, HG_SMEM>>>(
        featsh, Wt, nullptr, DIM, DIM, DIM, 0, 0, 0, 0);

    // 2) M_b^T fp16 (HMMA)
    make_M_kernel<<<dim3(8, 32), 128>>>();

    // 3) out = q' @ M_b
    hgemm_kernel<1><<<dim3(DIM / HG_BN, N_SEQ / HG_BM, B), 128, HG_SMEM>>>(
        qh, Mh, out, DIM, DIM, DIM, DIM,
        (long)N_SEQ * DIM, (long)DIM * DIM, (long)N_SEQ * DIM);
}

// round 16
// speedup vs baseline: 7.0580x; 1.0267x over previous
#include <cuda_runtime.h>
#include <cuda_fp16.h>
#include <cstdint>
#include <math.h>

// Problem constants
#define B 2
#define N_SEQ 4096
#define DIM 1024
#define HEADS 16
#define DHEAD 64
#define M_ROWS (B * N_SEQ)        // 8192
#define QKV_COLS (3 * DIM)        // 3072

// ---------------------------------------------------------------------------
// Scratch (device globals)
// ---------------------------------------------------------------------------
__device__ __half g_featsh[(size_t)M_ROWS * DIM];        // feats fp16
__device__ __half g_Wt[(size_t)QKV_COLS * DIM];          // permuted W_qkv^T fp16
__device__ __half g_WoT[(size_t)DIM * DIM];              // W_out^T fp16 [n][k]
__device__ __half g_qh[(size_t)M_ROWS * DIM];            // q' (softmaxed*scale) fp16
__device__ __half g_Mh[(size_t)B * DIM * DIM];           // M_b^T fp16
__device__ float  g_S[B * DIM];                          // colsum exp(k)
__device__ float  g_ctx[B * HEADS * DHEAD * DHEAD];      // ctx accumulators (atomic)

// ---------------------------------------------------------------------------
// Helpers
// ---------------------------------------------------------------------------
__device__ __forceinline__ uint32_t smem_u32(const void* p) {
    uint32_t a;
    asm("{ .reg .u64 t; cvta.to.shared.u64 t, %1; cvt.u32.u64 %0, t; }" : "=r"(a) : "l"(p));
    return a;
}
#define CP_ASYNC16(smem, g) \
    asm volatile("cp.async.cg.shared.global [%0], [%1], 16;" :: "r"((uint32_t)(smem)), "l"(g) : "memory")
#define CP_COMMIT() asm volatile("cp.async.commit_group;" ::: "memory")
template <int N> __device__ __forceinline__ void cp_wait() {
    asm volatile("cp.async.wait_group %0;" :: "n"(N) : "memory");
}
#define SWZ(x) ((x) ^ (((x) >> 3) & 0x70))

#define LDSM_X4(r0, r1, r2, r3, addr) \
    asm volatile("ldmatrix.sync.aligned.m8n8.x4.shared.b16 {%0,%1,%2,%3}, [%4];" \
                 : "=r"(r0), "=r"(r1), "=r"(r2), "=r"(r3) : "r"(addr))

#define LDSM_X4T(r0, r1, r2, r3, addr) \
    asm volatile("ldmatrix.sync.aligned.m8n8.x4.trans.shared.b16 {%0,%1,%2,%3}, [%4];" \
                 : "=r"(r0), "=r"(r1), "=r"(r2), "=r"(r3) : "r"(addr))

#define MMA16816(c0, c1, c2, c3, a0, a1, a2, a3, b0, b1) \
    asm volatile("mma.sync.aligned.m16n8k16.row.col.f32.f16.f16.f32 " \
                 "{%0,%1,%2,%3}, {%4,%5,%6,%7}, {%8,%9}, {%0,%1,%2,%3};" \
                 : "+f"(c0), "+f"(c1), "+f"(c2), "+f"(c3) \
                 : "r"(a0), "r"(a1), "r"(a2), "r"(a3), "r"(b0), "r"(b1))

// ---------------------------------------------------------------------------
// HMMA fp16 GEMM: 128x128 CTA tile, 4 warps, warp tile 64x64, K-chunk 64,
// 3-stage cp.async (96 KB), 2 CTAs/SM, fragment double-buffering.
// MODE 0 (qkv): W columns permuted as [q | (k_h,v_h) per head].
//   bn <  1024 : q epilogue (softmax*scale -> g_qh fp16)
//   bn >= 1024 : head tile [exp(k_h) | v_h]; in-epilogue ctx partial via HMMA
//                -> atomicAdd into g_ctx, colsums -> g_S.
// MODE 1: plain fp32 C store.
// ---------------------------------------------------------------------------
#define HG_BM 128
#define HG_BN 128
#define STG_A (HG_BM * 128)            // 16 KB
#define STG_B (HG_BN * 128)            // 16 KB
#define STG_BYTES (STG_A + STG_B)      // 32 KB
#define HG_STAGES 3
#define HG_SMEM (HG_STAGES * STG_BYTES)  // 96 KB

template <int MODE>
__global__ __launch_bounds__(128, 2)
void hgemm_kernel(const __half* __restrict__ A, const __half* __restrict__ Bh,
                  float* __restrict__ C, int K, int lda, int ldb, int ldc,
                  long aB, long bB, long cB)
{
    A  += (long)blockIdx.z * aB;
    Bh += (long)blockIdx.z * bB;
    if (MODE == 1) C += (long)blockIdx.z * cB;

    extern __shared__ char smem[];
    const uint32_t sbase = smem_u32(smem);
    const int tid  = threadIdx.x;
    const int wid  = tid >> 5;
    const int lane = tid & 31;
    const int wm = wid >> 1;           // 0..1 (64 rows)
    const int wn = wid & 1;            // 0..1 (64 cols)
    const int bm = blockIdx.y * HG_BM;
    const int bn = blockIdx.x * HG_BN;
    const int NC = K >> 6;

    const int r0   = tid >> 3;          // 0..15
    const int c16  = tid & 7;
    const uint32_t offLd = (uint32_t)(r0 * 128 + ((c16 ^ (r0 & 7)) * 16));
    const __half* apg = A + (long)(bm + r0) * lda + c16 * 8;
    const __half* bpg = Bh + (long)(bn + r0) * ldb + c16 * 8;
    const long strideA = (long)16 * lda;
    const long strideB = (long)16 * ldb;

    auto load_chunk = [&](int kc, int st) {
        const uint32_t sa = sbase + st * STG_BYTES + offLd;
        const uint32_t sb = sa + STG_A;
        const __half* ap = apg + kc * 64;
        const __half* bp = bpg + kc * 64;
        #pragma unroll
        for (int i = 0; i < 8; ++i) { CP_ASYNC16(sa + i * 2048, ap); ap += strideA; }
        #pragma unroll
        for (int i = 0; i < 8; ++i) { CP_ASYNC16(sb + i * 2048, bp); bp += strideB; }
    };

    float acc[4][8][4];
    #pragma unroll
    for (int i = 0; i < 4; i++)
        #pragma unroll
        for (int j = 0; j < 8; j++)
            #pragma unroll
            for (int x = 0; x < 4; x++) acc[i][j][x] = 0.f;

    load_chunk(0, 0); CP_COMMIT();
    load_chunk(1, 1); CP_COMMIT();

    const int lrow = lane & 15;
    const int lsel = lane >> 4;

    uint32_t a_row[4], b_row[4], ksel[4];
    #pragma unroll
    for (int mt = 0; mt < 4; ++mt) a_row[mt] = (uint32_t)(wm * 64 + mt * 16 + lrow) * 128;
    #pragma unroll
    for (int np = 0; np < 4; ++np) b_row[np] = (uint32_t)(wn * 64 + np * 16 + lrow) * 128;
    #pragma unroll
    for (int ks = 0; ks < 4; ++ks) ksel[ks] = (uint32_t)(((2 * ks + lsel) ^ (lrow & 7)) * 16);

    uint32_t af[2][4][4], bf[2][4][4];

    int st = 0, stl = 2;
    for (int c = 0; c < NC; ++c) {
        cp_wait<1>();
        __syncthreads();
        if (c + 2 < NC) load_chunk(c + 2, stl);
        CP_COMMIT();

        const uint32_t sa = sbase + st * STG_BYTES;
        const uint32_t sb = sa + STG_A;

        #pragma unroll
        for (int mt = 0; mt < 4; ++mt)
            LDSM_X4(af[0][mt][0], af[0][mt][1], af[0][mt][2], af[0][mt][3], sa + a_row[mt] + ksel[0]);
        #pragma unroll
        for (int np = 0; np < 4; ++np)
            LDSM_X4(bf[0][np][0], bf[0][np][1], bf[0][np][2], bf[0][np][3], sb + b_row[np] + ksel[0]);

        #pragma unroll
        for (int ks = 0; ks < 4; ++ks) {
            const int cur = ks & 1;
            const int nxt = cur ^ 1;
            if (ks < 3) {
                #pragma unroll
                for (int mt = 0; mt < 4; ++mt)
                    LDSM_X4(af[nxt][mt][0], af[nxt][mt][1], af[nxt][mt][2], af[nxt][mt][3],
                            sa + a_row[mt] + ksel[ks + 1]);
                #pragma unroll
                for (int np = 0; np < 4; ++np)
                    LDSM_X4(bf[nxt][np][0], bf[nxt][np][1], bf[nxt][np][2], bf[nxt][np][3],
                            sb + b_row[np] + ksel[ks + 1]);
            }
            #pragma unroll
            for (int mt = 0; mt < 4; ++mt) {
                #pragma unroll
                for (int np = 0; np < 4; ++np) {
                    MMA16816(acc[mt][2*np][0], acc[mt][2*np][1], acc[mt][2*np][2], acc[mt][2*np][3],
                             af[cur][mt][0], af[cur][mt][1], af[cur][mt][2], af[cur][mt][3],
                             bf[cur][np][0], bf[cur][np][2]);
                    MMA16816(acc[mt][2*np+1][0], acc[mt][2*np+1][1], acc[mt][2*np+1][2], acc[mt][2*np+1][3],
                             af[cur][mt][0], af[cur][mt][1], af[cur][mt][2], af[cur][mt][3],
                             bf[cur][np][1], bf[cur][np][3]);
                }
            }
        }
        if (++st == HG_STAGES) st = 0;
        if (++stl == HG_STAGES) stl = 0;
    }

    // ------------------------- epilogue -------------------------
    const int r_base = bm + wm * 64;
    const int cq = (lane & 3) * 2;

    if (MODE == 1) {
        #pragma unroll
        for (int mt = 0; mt < 4; ++mt) {
            int r0e = r_base + mt * 16 + (lane >> 2);
            #pragma unroll
            for (int nt = 0; nt < 8; ++nt) {
                int col = bn + wn * 64 + nt * 8 + cq;
                *(float2*)&C[(long)r0e * ldc + col]       = make_float2(acc[mt][nt][0], acc[mt][nt][1]);
                *(float2*)&C[(long)(r0e + 8) * ldc + col] = make_float2(acc[mt][nt][2], acc[mt][nt][3]);
            }
        }
    } else if (bn < 1024) {
        // ---- q region: softmax over the warp's 64 cols (= one head) ----
        #pragma unroll
        for (int mt = 0; mt < 4; ++mt) {
            #pragma unroll
            for (int hf = 0; hf < 2; ++hf) {
                int row = r_base + mt * 16 + (lane >> 2) + 8 * hf;
                float mx = -1e30f;
                #pragma unroll
                for (int nt = 0; nt < 8; ++nt)
                    mx = fmaxf(mx, fmaxf(acc[mt][nt][2*hf], acc[mt][nt][2*hf+1]));
                mx = fmaxf(mx, __shfl_xor_sync(0xFFFFFFFFu, mx, 1));
                mx = fmaxf(mx, __shfl_xor_sync(0xFFFFFFFFu, mx, 2));
                float s = 0.f;
                #pragma unroll
                for (int nt = 0; nt < 8; ++nt) {
                    float e0 = __expf(acc[mt][nt][2*hf]   - mx);
                    float e1 = __expf(acc[mt][nt][2*hf+1] - mx);
                    acc[mt][nt][2*hf] = e0; acc[mt][nt][2*hf+1] = e1;
                    s += e0 + e1;
                }
                s += __shfl_xor_sync(0xFFFFFFFFu, s, 1);
                s += __shfl_xor_sync(0xFFFFFFFFu, s, 2);
                float inv = 0.125f / s;
                #pragma unroll
                for (int nt = 0; nt < 8; ++nt) {
                    int col = bn + wn * 64 + nt * 8 + cq;
                    *(__half2*)&g_qh[(long)row * DIM + col] =
                        __floats2half2_rn(acc[mt][nt][2*hf] * inv, acc[mt][nt][2*hf+1] * inv);
                }
            }
        }
    } else {
        // ---- kv region: this CTA holds [exp(k_h) | v_h] for one head ----
        const int h = (bn - 1024) >> 7;
        const int bidb = bm >> 12;
        const uint32_t kTu = sbase;               // 128 x 64 fp16 (128B rows)
        const uint32_t vTu = sbase + 16384;

        __syncthreads();   // all warps done reading stage smem

        if (wn == 0) {
            // exp(k) -> kT smem, colsums -> g_S
            float cs[8][2];
            #pragma unroll
            for (int nt = 0; nt < 8; ++nt) { cs[nt][0] = 0.f; cs[nt][1] = 0.f; }
            #pragma unroll
            for (int mt = 0; mt < 4; ++mt) {
                int rr = wm * 64 + mt * 16 + (lane >> 2);
                #pragma unroll
                for (int nt = 0; nt < 8; ++nt) {
                    float e0 = __expf(acc[mt][nt][0]);
                    float e1 = __expf(acc[mt][nt][1]);
                    float e2 = __expf(acc[mt][nt][2]);
                    float e3 = __expf(acc[mt][nt][3]);
                    cs[nt][0] += e0 + e2;
                    cs[nt][1] += e1 + e3;
                    int cb = (nt * 8 + cq) * 2;     // byte col
                    *(__half2*)(smem + SWZ((uint32_t)(rr * 128 + cb)))       = __floats2half2_rn(e0, e1);
                    *(__half2*)(smem + SWZ((uint32_t)((rr + 8) * 128 + cb))) = __floats2half2_rn(e2, e3);
                }
            }
            #pragma unroll
            for (int nt = 0; nt < 8; ++nt) {
                #pragma unroll
                for (int j = 0; j < 2; ++j) {
                    float cc = cs[nt][j];
                    cc += __shfl_xor_sync(0xFFFFFFFFu, cc, 4);
                    cc += __shfl_xor_sync(0xFFFFFFFFu, cc, 8);
                    cc += __shfl_xor_sync(0xFFFFFFFFu, cc, 16);
                    if (lane < 4)
                        atomicAdd(&g_S[bidb * DIM + h * DHEAD + nt * 8 + cq + j], cc);
                }
            }
        } else {
            // v -> vT smem
            #pragma unroll
            for (int mt = 0; mt < 4; ++mt) {
                int rr = wm * 64 + mt * 16 + (lane >> 2);
                #pragma unroll
                for (int nt = 0; nt < 8; ++nt) {
                    int cb = (nt * 8 + cq) * 2;
                    *(__half2*)(smem + 16384 + SWZ((uint32_t)(rr * 128 + cb)))       = __floats2half2_rn(acc[mt][nt][0], acc[mt][nt][1]);
                    *(__half2*)(smem + 16384 + SWZ((uint32_t)((rr + 8) * 128 + cb))) = __floats2half2_rn(acc[mt][nt][2], acc[mt][nt][3]);
                }
            }
        }
        __syncthreads();

        // ctx partial: ekT(128x64)^T @ vT(128x64) -> [64d x 64e], warp wid owns e wid*16..+16
        const int l7 = lane & 7;
        const int row16 = l7 + ((lane & 16) >> 1);
        const int coloff = lane & 8;

        uint32_t aadr[4];
        #pragma unroll
        for (int mt = 0; mt < 4; ++mt)
            aadr[mt] = kTu + SWZ((uint32_t)(row16 * 128 + (mt * 16 + coloff) * 2));
        uint32_t badr = vTu + SWZ((uint32_t)(row16 * 128 + (wid * 16 + coloff) * 2));

        float c2[4][2][4];
        #pragma unroll
        for (int i = 0; i < 4; i++)
            #pragma unroll
            for (int j = 0; j < 2; j++)
                #pragma unroll
                for (int x = 0; x < 4; x++) c2[i][j][x] = 0.f;

        #pragma unroll
        for (int ks = 0; ks < 8; ++ks) {
            const uint32_t koff = (uint32_t)(ks * 2048);
            uint32_t bfr[4];
            LDSM_X4T(bfr[0], bfr[1], bfr[2], bfr[3], badr + koff);
            #pragma unroll
            for (int mt = 0; mt < 4; ++mt) {
                uint32_t afr[4];
                LDSM_X4T(afr[0], afr[1], afr[2], afr[3], aadr[mt] + koff);
                MMA16816(c2[mt][0][0], c2[mt][0][1], c2[mt][0][2], c2[mt][0][3],
                         afr[0], afr[1], afr[2], afr[3], bfr[0], bfr[2]);
                MMA16816(c2[mt][1][0], c2[mt][1][1], c2[mt][1][2], c2[mt][1][3],
                         afr[0], afr[1], afr[2], afr[3], bfr[1], bfr[3]);
            }
        }

        // accumulate directly into g_ctx (RED.F32, spread addresses)
        float* outp = g_ctx + (long)(bidb * HEADS + h) * (DHEAD * DHEAD);
        const int e0 = wid * 16 + cq;
        #pragma unroll
        for (int mt = 0; mt < 4; ++mt) {
            int d0 = mt * 16 + (lane >> 2);
            #pragma unroll
            for (int nt = 0; nt < 2; ++nt) {
                atomicAdd(&outp[(d0)     * DHEAD + e0 + nt * 8],     c2[mt][nt][0]);
                atomicAdd(&outp[(d0)     * DHEAD + e0 + nt * 8 + 1], c2[mt][nt][1]);
                atomicAdd(&outp[(d0 + 8) * DHEAD + e0 + nt * 8],     c2[mt][nt][2]);
                atomicAdd(&outp[(d0 + 8) * DHEAD + e0 + nt * 8 + 1], c2[mt][nt][3]);
            }
        }
    }
}

// ---------------------------------------------------------------------------
// Fused prep kernel: one launch does all independent preprocessing.
//   bid <  1024          : feats fp32->fp16 (8 float4/thread) + zero g_ctx/g_S
//   1024 <= bid < 4096   : W_qkv transpose tile (head-interleaved permutation)
//   bid >= 4096          : W_out transpose tile
// 256 threads everywhere.
// ---------------------------------------------------------------------------
__global__ __launch_bounds__(256)
void prep_kernel(const float* __restrict__ feats,
                 const float* __restrict__ Wqkv,
                 const float* __restrict__ Wout)
{
    const int bid = blockIdx.x;
    const int tid = threadIdx.x;

    if (bid < 1024) {
        // ---- feats conversion: 8 float4 per thread ----
        if (bid < 512)
            g_ctx[bid * 256 + tid] = 0.f;
        if (bid >= 512 && bid < 520)
            g_S[(bid - 512) * 256 + tid] = 0.f;
        long base = (long)bid * 2048 + tid;     // float4 index, stride 256
        #pragma unroll
        for (int j = 0; j < 8; ++j) {
            long i = base + j * 256;
            float4 f = ((const float4*)feats)[i];
            ((__half2*)g_featsh)[2 * i]     = __floats2half2_rn(f.x, f.y);
            ((__half2*)g_featsh)[2 * i + 1] = __floats2half2_rn(f.z, f.w);
        }
    } else if (bid < 4096) {
        // ---- W_qkv transpose tile (32x32) with permutation ----
        const int t = bid - 1024;               // 0..3071
        const int n0 = (t % 96) * 32;
        const int k0 = (t / 96) * 32;
        __shared__ float tt[32][33];
        const int tx = tid & 31, ty = tid >> 5;
        #pragma unroll
        for (int j = 0; j < 4; ++j)
            tt[ty + 8 * j][tx] = Wqkv[(long)(k0 + ty + 8 * j) * QKV_COLS + n0 + tx];
        __syncthreads();
        #pragma unroll
        for (int j = 0; j < 4; ++j) {
            int n = n0 + ty + 8 * j;
            int row;
            if (n < 1024)       row = n;
            else if (n < 2048)  row = 1024 + ((n - 1024) >> 6) * 128 + ((n - 1024) & 63);
            else                row = 1024 + ((n - 2048) >> 6) * 128 + 64 + ((n - 2048) & 63);
            g_Wt[(long)row * DIM + k0 + tx] = __float2half_rn(tt[tx][ty + 8 * j]);
        }
    } else {
        // ---- W_out transpose tile (32x32) ----
        const int t = bid - 4096;               // 0..1023
        const int n0 = (t % 32) * 32;
        const int k0 = (t / 32) * 32;
        __shared__ float tt[32][33];
        const int tx = tid & 31, ty = tid >> 5;
        #pragma unroll
        for (int j = 0; j < 4; ++j)
            tt[ty + 8 * j][tx] = Wout[(long)(k0 + ty + 8 * j) * DIM + n0 + tx];
        __syncthreads();
        #pragma unroll
        for (int j = 0; j < 4; ++j)
            g_WoT[(long)(n0 + ty + 8 * j) * DIM + k0 + tx] = __float2half_rn(tt[tx][ty + 8 * j]);
    }
}

// ---------------------------------------------------------------------------
// HMMA make_M: Mh[b][n][h*64+d] = sum_d2 WoT[n][h*64+d2] * ctx[bh][d][d2]/S[d]
// grid (8 n-tiles of 128, 32 bh), 128 threads (4 warps, 32 rows each).
// ---------------------------------------------------------------------------
__global__ __launch_bounds__(128, 4)
void make_M_kernel()
{
    const int ntb = blockIdx.x;        // n-tile (128 rows)
    const int bh = blockIdx.y;
    const int b = bh >> 4;
    const int h = bh & 15;

    __shared__ __align__(16) char sm[16384 + 8192];   // A: 128x128B, B: 64x128B
    const uint32_t sa = smem_u32(sm);
    const uint32_t sb = sa + 16384;

    const int tid = threadIdx.x;
    const int wid = tid >> 5;
    const int lane = tid & 31;

    // ---- A tile: WoT[ntb*128 + r][h*64 ..+64] via cp.async (8 x 16B per thread)
    {
        const int r = tid >> 3;        // 0..15
        const int c = tid & 7;
        const uint32_t off = (uint32_t)(r * 128 + ((c ^ (r & 7)) * 16));
        const __half* ap = g_WoT + (long)(ntb * 128 + r) * DIM + h * 64 + c * 8;
        #pragma unroll
        for (int i = 0; i < 8; ++i) {
            CP_ASYNC16(sa + off + i * 2048, ap);
            ap += (long)16 * DIM;
        }
        CP_COMMIT();
    }

    // ---- B tile: ctx[bh][d][d2]/S[d] -> fp16 (each thread: 32 cols of one row)
    {
        const int d = tid >> 1;
        const int cb = (tid & 1) * 32;
        const float inv = 1.f / g_S[b * DIM + h * DHEAD + d];
        const float* cp = g_ctx + (long)bh * (DHEAD * DHEAD) + d * DHEAD + cb;
        __align__(16) __half hv[32];
        #pragma unroll
        for (int j = 0; j < 8; ++j) {
            float4 f = *(const float4*)(cp + j * 4);
            hv[j*4+0] = __float2half_rn(f.x * inv);
            hv[j*4+1] = __float2half_rn(f.y * inv);
            hv[j*4+2] = __float2half_rn(f.z * inv);
            hv[j*4+3] = __float2half_rn(f.w * inv);
        }
        #pragma unroll
        for (int j = 0; j < 4; ++j)
            *(uint4*)(sm + 16384 + SWZ((uint32_t)(d * 128 + cb * 2 + j * 16))) = ((const uint4*)hv)[j];
    }
    cp_wait<0>();
    __syncthreads();

    // ---- MMA: warp tile 32(m) x 64(n), K=64 ----
    const int lrow = lane & 15;
    const int lsel = lane >> 4;

    uint32_t a_row[2], b_row[4], ksel[4];
    #pragma unroll
    for (int mt = 0; mt < 2; ++mt) a_row[mt] = (uint32_t)(wid * 32 + mt * 16 + lrow) * 128;
    #pragma unroll
    for (int np = 0; np < 4; ++np) b_row[np] = (uint32_t)(np * 16 + lrow) * 128;
    #pragma unroll
    for (int ks = 0; ks < 4; ++ks) ksel[ks] = (uint32_t)(((2 * ks + lsel) ^ (lrow & 7)) * 16);

    float acc[2][8][4];
    #pragma unroll
    for (int i = 0; i < 2; i++)
        #pragma unroll
        for (int j = 0; j < 8; j++)
            #pragma unroll
            for (int x = 0; x < 4; x++) acc[i][j][x] = 0.f;

    #pragma unroll
    for (int ks = 0; ks < 4; ++ks) {
        uint32_t af[2][4], bf[4][4];
        #pragma unroll
        for (int mt = 0; mt < 2; ++mt)
            LDSM_X4(af[mt][0], af[mt][1], af[mt][2], af[mt][3], sa + a_row[mt] + ksel[ks]);
        #pragma unroll
        for (int np = 0; np < 4; ++np)
            LDSM_X4(bf[np][0], bf[np][1], bf[np][2], bf[np][3], sb + b_row[np] + ksel[ks]);
        #pragma unroll
        for (int mt = 0; mt < 2; ++mt) {
            #pragma unroll
            for (int np = 0; np < 4; ++np) {
                MMA16816(acc[mt][2*np][0], acc[mt][2*np][1], acc[mt][2*np][2], acc[mt][2*np][3],
                         af[mt][0], af[mt][1], af[mt][2], af[mt][3],
                         bf[np][0], bf[np][2]);
                MMA16816(acc[mt][2*np+1][0], acc[mt][2*np+1][1], acc[mt][2*np+1][2], acc[mt][2*np+1][3],
                         af[mt][0], af[mt][1], af[mt][2], af[mt][3],
                         bf[np][1], bf[np][3]);
            }
        }
    }

    // ---- store fp16 to g_Mh[b][n][h*64 + d] ----
    const int cq = (lane & 3) * 2;
    __half* mp = g_Mh + (long)b * DIM * DIM;
    #pragma unroll
    for (int mt = 0; mt < 2; ++mt) {
        int row = ntb * 128 + wid * 32 + mt * 16 + (lane >> 2);
        #pragma unroll
        for (int nt = 0; nt < 8; ++nt) {
            int col = h * 64 + nt * 8 + cq;
            *(__half2*)&mp[(long)row * DIM + col]       = __floats2half2_rn(acc[mt][nt][0], acc[mt][nt][1]);
            *(__half2*)&mp[(long)(row + 8) * DIM + col] = __floats2half2_rn(acc[mt][nt][2], acc[mt][nt][3]);
        }
    }
}

// ---------------------------------------------------------------------------
// Launch
// ---------------------------------------------------------------------------
extern "C" void kernel_launch(void* const* d_in, const int* in_sizes, int n_in,
                              void* d_out, int out_size)
{
    const float* feats = (const float*)d_in[0];
    const float* W_qkv = (const float*)d_in[1];
    const float* W_out = (const float*)d_in[2];
    float* out = (float*)d_out;

    cudaFuncSetAttribute(hgemm_kernel<0>, cudaFuncAttributeMaxDynamicSharedMemorySize, HG_SMEM);
    cudaFuncSetAttribute(hgemm_kernel<1>, cudaFuncAttributeMaxDynamicSharedMemorySize, HG_SMEM);

    __half* featsh; cudaGetSymbolAddress((void**)&featsh, g_featsh);
    __half* Wt;     cudaGetSymbolAddress((void**)&Wt, g_Wt);
    __half* qh;     cudaGetSymbolAddress((void**)&qh, g_qh);
    __half* Mh;     cudaGetSymbolAddress((void**)&Mh, g_Mh);

    // 0) fused prep: f2h + both weight transposes + buffer zeroing
    prep_kernel<<<5120, 256>>>(feats, W_qkv, W_out);

    // 1) fused qkv GEMM (q softmax + in-epilogue ctx partials -> atomic g_ctx)
    hgemm_kernel<0><<<dim3(QKV_COLS / HG_BN, M_ROWS / HG_BM, 1), 128, HG_SMEM>>>(
        featsh, Wt, nullptr, DIM, DIM, DIM, 0, 0, 0, 0);

    // 2) M_b^T fp16 (HMMA)
    make_M_kernel<<<dim3(8, 32), 128>>>();

    // 3) out = q' @ M_b
    hgemm_kernel<1><<<dim3(DIM / HG_BN, N_SEQ / HG_BM, B), 128, HG_SMEM>>>(
        qh, Mh, out, DIM, DIM, DIM, DIM,
        (long)N_SEQ * DIM, (long)DIM * DIM, (long)N_SEQ * DIM);
}

// round 17
// speedup vs baseline: 7.2896x; 1.0328x over previous
#include <cuda_runtime.h>
#include <cuda_fp16.h>
#include <cstdint>
#include <math.h>

// Problem constants
#define B 2
#define N_SEQ 4096
#define DIM 1024
#define HEADS 16
#define DHEAD 64
#define M_ROWS (B * N_SEQ)        // 8192
#define QKV_COLS (3 * DIM)        // 3072

// ---------------------------------------------------------------------------
// Scratch (device globals)
// ---------------------------------------------------------------------------
__device__ __half g_featsh[(size_t)M_ROWS * DIM];        // feats fp16
__device__ __half g_Wt[(size_t)QKV_COLS * DIM];          // permuted W_qkv^T fp16
__device__ __half g_WoT[(size_t)DIM * DIM];              // W_out^T fp16 [n][k]
__device__ __half g_qh[(size_t)M_ROWS * DIM];            // q' (softmaxed*scale) fp16
__device__ __half g_Mh[(size_t)B * DIM * DIM];           // M_b^T fp16
__device__ float  g_S[B * DIM];                          // colsum exp(k)
__device__ float  g_ctx[B * HEADS * DHEAD * DHEAD];      // ctx accumulators (atomic)

// ---------------------------------------------------------------------------
// Helpers
// ---------------------------------------------------------------------------
__device__ __forceinline__ uint32_t smem_u32(const void* p) {
    uint32_t a;
    asm("{ .reg .u64 t; cvta.to.shared.u64 t, %1; cvt.u32.u64 %0, t; }" : "=r"(a) : "l"(p));
    return a;
}
#define CP_ASYNC16(smem, g) \
    asm volatile("cp.async.cg.shared.global [%0], [%1], 16;" :: "r"((uint32_t)(smem)), "l"(g) : "memory")
#define CP_COMMIT() asm volatile("cp.async.commit_group;" ::: "memory")
template <int N> __device__ __forceinline__ void cp_wait() {
    asm volatile("cp.async.wait_group %0;" :: "n"(N) : "memory");
}
#define SWZ(x) ((x) ^ (((x) >> 3) & 0x70))

#define LDSM_X4(r0, r1, r2, r3, addr) \
    asm volatile("ldmatrix.sync.aligned.m8n8.x4.shared.b16 {%0,%1,%2,%3}, [%4];" \
                 : "=r"(r0), "=r"(r1), "=r"(r2), "=r"(r3) : "r"(addr))

#define LDSM_X4T(r0, r1, r2, r3, addr) \
    asm volatile("ldmatrix.sync.aligned.m8n8.x4.trans.shared.b16 {%0,%1,%2,%3}, [%4];" \
                 : "=r"(r0), "=r"(r1), "=r"(r2), "=r"(r3) : "r"(addr))

#define MMA16816(c0, c1, c2, c3, a0, a1, a2, a3, b0, b1) \
    asm volatile("mma.sync.aligned.m16n8k16.row.col.f32.f16.f16.f32 " \
                 "{%0,%1,%2,%3}, {%4,%5,%6,%7}, {%8,%9}, {%0,%1,%2,%3};" \
                 : "+f"(c0), "+f"(c1), "+f"(c2), "+f"(c3) \
                 : "r"(a0), "r"(a1), "r"(a2), "r"(a3), "r"(b0), "r"(b1))

// ---------------------------------------------------------------------------
// HMMA fp16 GEMM (qkv): 128x128 CTA tile, 4 warps, warp tile 64x64, K-chunk 64,
// 3-stage cp.async (96 KB), 2 CTAs/SM, fragment double-buffering.
// W columns permuted as [q | (k_h,v_h) per head]:
//   bn <  1024 : q epilogue (softmax*scale -> g_qh fp16)
//   bn >= 1024 : head tile [exp(k_h) | v_h]; in-epilogue ctx partial via HMMA
//                -> atomicAdd into g_ctx, colsums -> g_S.
// ---------------------------------------------------------------------------
#define HG_BM 128
#define HG_BN 128
#define STG_A (HG_BM * 128)            // 16 KB
#define STG_B (HG_BN * 128)            // 16 KB
#define STG_BYTES (STG_A + STG_B)      // 32 KB
#define HG_STAGES 3
#define HG_SMEM (HG_STAGES * STG_BYTES)  // 96 KB

__global__ __launch_bounds__(128, 2)
void hgemm_qkv_kernel(const __half* __restrict__ A, const __half* __restrict__ Bh,
                      int K, int lda, int ldb)
{
    extern __shared__ char smem[];
    const uint32_t sbase = smem_u32(smem);
    const int tid  = threadIdx.x;
    const int wid  = tid >> 5;
    const int lane = tid & 31;
    const int wm = wid >> 1;           // 0..1 (64 rows)
    const int wn = wid & 1;            // 0..1 (64 cols)
    const int bm = blockIdx.y * HG_BM;
    const int bn = blockIdx.x * HG_BN;
    const int NC = K >> 6;

    const int r0   = tid >> 3;          // 0..15
    const int c16  = tid & 7;
    const uint32_t offLd = (uint32_t)(r0 * 128 + ((c16 ^ (r0 & 7)) * 16));
    const __half* apg = A + (long)(bm + r0) * lda + c16 * 8;
    const __half* bpg = Bh + (long)(bn + r0) * ldb + c16 * 8;
    const long strideA = (long)16 * lda;
    const long strideB = (long)16 * ldb;

    auto load_chunk = [&](int kc, int st) {
        const uint32_t sa = sbase + st * STG_BYTES + offLd;
        const uint32_t sb = sa + STG_A;
        const __half* ap = apg + kc * 64;
        const __half* bp = bpg + kc * 64;
        #pragma unroll
        for (int i = 0; i < 8; ++i) { CP_ASYNC16(sa + i * 2048, ap); ap += strideA; }
        #pragma unroll
        for (int i = 0; i < 8; ++i) { CP_ASYNC16(sb + i * 2048, bp); bp += strideB; }
    };

    float acc[4][8][4];
    #pragma unroll
    for (int i = 0; i < 4; i++)
        #pragma unroll
        for (int j = 0; j < 8; j++)
            #pragma unroll
            for (int x = 0; x < 4; x++) acc[i][j][x] = 0.f;

    load_chunk(0, 0); CP_COMMIT();
    load_chunk(1, 1); CP_COMMIT();

    const int lrow = lane & 15;
    const int lsel = lane >> 4;

    uint32_t a_row[4], b_row[4], ksel[4];
    #pragma unroll
    for (int mt = 0; mt < 4; ++mt) a_row[mt] = (uint32_t)(wm * 64 + mt * 16 + lrow) * 128;
    #pragma unroll
    for (int np = 0; np < 4; ++np) b_row[np] = (uint32_t)(wn * 64 + np * 16 + lrow) * 128;
    #pragma unroll
    for (int ks = 0; ks < 4; ++ks) ksel[ks] = (uint32_t)(((2 * ks + lsel) ^ (lrow & 7)) * 16);

    uint32_t af[2][4][4], bf[2][4][4];

    int st = 0, stl = 2;
    for (int c = 0; c < NC; ++c) {
        cp_wait<1>();
        __syncthreads();
        if (c + 2 < NC) load_chunk(c + 2, stl);
        CP_COMMIT();

        const uint32_t sa = sbase + st * STG_BYTES;
        const uint32_t sb = sa + STG_A;

        #pragma unroll
        for (int mt = 0; mt < 4; ++mt)
            LDSM_X4(af[0][mt][0], af[0][mt][1], af[0][mt][2], af[0][mt][3], sa + a_row[mt] + ksel[0]);
        #pragma unroll
        for (int np = 0; np < 4; ++np)
            LDSM_X4(bf[0][np][0], bf[0][np][1], bf[0][np][2], bf[0][np][3], sb + b_row[np] + ksel[0]);

        #pragma unroll
        for (int ks = 0; ks < 4; ++ks) {
            const int cur = ks & 1;
            const int nxt = cur ^ 1;
            if (ks < 3) {
                #pragma unroll
                for (int mt = 0; mt < 4; ++mt)
                    LDSM_X4(af[nxt][mt][0], af[nxt][mt][1], af[nxt][mt][2], af[nxt][mt][3],
                            sa + a_row[mt] + ksel[ks + 1]);
                #pragma unroll
                for (int np = 0; np < 4; ++np)
                    LDSM_X4(bf[nxt][np][0], bf[nxt][np][1], bf[nxt][np][2], bf[nxt][np][3],
                            sb + b_row[np] + ksel[ks + 1]);
            }
            #pragma unroll
            for (int mt = 0; mt < 4; ++mt) {
                #pragma unroll
                for (int np = 0; np < 4; ++np) {
                    MMA16816(acc[mt][2*np][0], acc[mt][2*np][1], acc[mt][2*np][2], acc[mt][2*np][3],
                             af[cur][mt][0], af[cur][mt][1], af[cur][mt][2], af[cur][mt][3],
                             bf[cur][np][0], bf[cur][np][2]);
                    MMA16816(acc[mt][2*np+1][0], acc[mt][2*np+1][1], acc[mt][2*np+1][2], acc[mt][2*np+1][3],
                             af[cur][mt][0], af[cur][mt][1], af[cur][mt][2], af[cur][mt][3],
                             bf[cur][np][1], bf[cur][np][3]);
                }
            }
        }
        if (++st == HG_STAGES) st = 0;
        if (++stl == HG_STAGES) stl = 0;
    }

    // ------------------------- epilogue -------------------------
    const int r_base = bm + wm * 64;
    const int cq = (lane & 3) * 2;

    if (bn < 1024) {
        // ---- q region: softmax over the warp's 64 cols (= one head) ----
        #pragma unroll
        for (int mt = 0; mt < 4; ++mt) {
            #pragma unroll
            for (int hf = 0; hf < 2; ++hf) {
                int row = r_base + mt * 16 + (lane >> 2) + 8 * hf;
                float mx = -1e30f;
                #pragma unroll
                for (int nt = 0; nt < 8; ++nt)
                    mx = fmaxf(mx, fmaxf(acc[mt][nt][2*hf], acc[mt][nt][2*hf+1]));
                mx = fmaxf(mx, __shfl_xor_sync(0xFFFFFFFFu, mx, 1));
                mx = fmaxf(mx, __shfl_xor_sync(0xFFFFFFFFu, mx, 2));
                float s = 0.f;
                #pragma unroll
                for (int nt = 0; nt < 8; ++nt) {
                    float e0 = __expf(acc[mt][nt][2*hf]   - mx);
                    float e1 = __expf(acc[mt][nt][2*hf+1] - mx);
                    acc[mt][nt][2*hf] = e0; acc[mt][nt][2*hf+1] = e1;
                    s += e0 + e1;
                }
                s += __shfl_xor_sync(0xFFFFFFFFu, s, 1);
                s += __shfl_xor_sync(0xFFFFFFFFu, s, 2);
                float inv = 0.125f / s;
                #pragma unroll
                for (int nt = 0; nt < 8; ++nt) {
                    int col = bn + wn * 64 + nt * 8 + cq;
                    *(__half2*)&g_qh[(long)row * DIM + col] =
                        __floats2half2_rn(acc[mt][nt][2*hf] * inv, acc[mt][nt][2*hf+1] * inv);
                }
            }
        }
    } else {
        // ---- kv region: this CTA holds [exp(k_h) | v_h] for one head ----
        const int h = (bn - 1024) >> 7;
        const int bidb = bm >> 12;
        const uint32_t kTu = sbase;               // 128 x 64 fp16 (128B rows)
        const uint32_t vTu = sbase + 16384;

        __syncthreads();   // all warps done reading stage smem

        if (wn == 0) {
            // exp(k) -> kT smem, colsums -> g_S
            float cs[8][2];
            #pragma unroll
            for (int nt = 0; nt < 8; ++nt) { cs[nt][0] = 0.f; cs[nt][1] = 0.f; }
            #pragma unroll
            for (int mt = 0; mt < 4; ++mt) {
                int rr = wm * 64 + mt * 16 + (lane >> 2);
                #pragma unroll
                for (int nt = 0; nt < 8; ++nt) {
                    float e0 = __expf(acc[mt][nt][0]);
                    float e1 = __expf(acc[mt][nt][1]);
                    float e2 = __expf(acc[mt][nt][2]);
                    float e3 = __expf(acc[mt][nt][3]);
                    cs[nt][0] += e0 + e2;
                    cs[nt][1] += e1 + e3;
                    int cb = (nt * 8 + cq) * 2;     // byte col
                    *(__half2*)(smem + SWZ((uint32_t)(rr * 128 + cb)))       = __floats2half2_rn(e0, e1);
                    *(__half2*)(smem + SWZ((uint32_t)((rr + 8) * 128 + cb))) = __floats2half2_rn(e2, e3);
                }
            }
            #pragma unroll
            for (int nt = 0; nt < 8; ++nt) {
                #pragma unroll
                for (int j = 0; j < 2; ++j) {
                    float cc = cs[nt][j];
                    cc += __shfl_xor_sync(0xFFFFFFFFu, cc, 4);
                    cc += __shfl_xor_sync(0xFFFFFFFFu, cc, 8);
                    cc += __shfl_xor_sync(0xFFFFFFFFu, cc, 16);
                    if (lane < 4)
                        atomicAdd(&g_S[bidb * DIM + h * DHEAD + nt * 8 + cq + j], cc);
                }
            }
        } else {
            // v -> vT smem
            #pragma unroll
            for (int mt = 0; mt < 4; ++mt) {
                int rr = wm * 64 + mt * 16 + (lane >> 2);
                #pragma unroll
                for (int nt = 0; nt < 8; ++nt) {
                    int cb = (nt * 8 + cq) * 2;
                    *(__half2*)(smem + 16384 + SWZ((uint32_t)(rr * 128 + cb)))       = __floats2half2_rn(acc[mt][nt][0], acc[mt][nt][1]);
                    *(__half2*)(smem + 16384 + SWZ((uint32_t)((rr + 8) * 128 + cb))) = __floats2half2_rn(acc[mt][nt][2], acc[mt][nt][3]);
                }
            }
        }
        __syncthreads();

        // ctx partial: ekT(128x64)^T @ vT(128x64) -> [64d x 64e]
        const int l7 = lane & 7;
        const int row16 = l7 + ((lane & 16) >> 1);
        const int coloff = lane & 8;

        uint32_t aadr[4];
        #pragma unroll
        for (int mt = 0; mt < 4; ++mt)
            aadr[mt] = kTu + SWZ((uint32_t)(row16 * 128 + (mt * 16 + coloff) * 2));
        uint32_t badr = vTu + SWZ((uint32_t)(row16 * 128 + (wid * 16 + coloff) * 2));

        float c2[4][2][4];
        #pragma unroll
        for (int i = 0; i < 4; i++)
            #pragma unroll
            for (int j = 0; j < 2; j++)
                #pragma unroll
                for (int x = 0; x < 4; x++) c2[i][j][x] = 0.f;

        #pragma unroll
        for (int ks = 0; ks < 8; ++ks) {
            const uint32_t koff = (uint32_t)(ks * 2048);
            uint32_t bfr[4];
            LDSM_X4T(bfr[0], bfr[1], bfr[2], bfr[3], badr + koff);
            #pragma unroll
            for (int mt = 0; mt < 4; ++mt) {
                uint32_t afr[4];
                LDSM_X4T(afr[0], afr[1], afr[2], afr[3], aadr[mt] + koff);
                MMA16816(c2[mt][0][0], c2[mt][0][1], c2[mt][0][2], c2[mt][0][3],
                         afr[0], afr[1], afr[2], afr[3], bfr[0], bfr[2]);
                MMA16816(c2[mt][1][0], c2[mt][1][1], c2[mt][1][2], c2[mt][1][3],
                         afr[0], afr[1], afr[2], afr[3], bfr[1], bfr[3]);
            }
        }

        float* outp = g_ctx + (long)(bidb * HEADS + h) * (DHEAD * DHEAD);
        const int e0 = wid * 16 + cq;
        #pragma unroll
        for (int mt = 0; mt < 4; ++mt) {
            int d0 = mt * 16 + (lane >> 2);
            #pragma unroll
            for (int nt = 0; nt < 2; ++nt) {
                atomicAdd(&outp[(d0)     * DHEAD + e0 + nt * 8],     c2[mt][nt][0]);
                atomicAdd(&outp[(d0)     * DHEAD + e0 + nt * 8 + 1], c2[mt][nt][1]);
                atomicAdd(&outp[(d0 + 8) * DHEAD + e0 + nt * 8],     c2[mt][nt][2]);
                atomicAdd(&outp[(d0 + 8) * DHEAD + e0 + nt * 8 + 1], c2[mt][nt][3]);
            }
        }
    }
}

// ---------------------------------------------------------------------------
// HMMA fp16 GEMM2 (out = q' @ M): 64x128 CTA tile, 4 warps, warp tile 32x64,
// K-chunk 64, 3-stage cp.async (72 KB), 3 CTAs/SM. fp32 C store.
// ---------------------------------------------------------------------------
#define G2_BM 64
#define G2_BN 128
#define G2_STG_A (G2_BM * 128)          // 8 KB
#define G2_STG_B (G2_BN * 128)          // 16 KB
#define G2_STG_BYTES (G2_STG_A + G2_STG_B)  // 24 KB
#define G2_SMEM (HG_STAGES * G2_STG_BYTES)  // 72 KB

__global__ __launch_bounds__(128, 3)
void hgemm2_kernel(const __half* __restrict__ A, const __half* __restrict__ Bh,
                   float* __restrict__ C, int K, int lda, int ldb, int ldc,
                   long aB, long bB, long cB)
{
    A  += (long)blockIdx.z * aB;
    Bh += (long)blockIdx.z * bB;
    C  += (long)blockIdx.z * cB;

    extern __shared__ char smem[];
    const uint32_t sbase = smem_u32(smem);
    const int tid  = threadIdx.x;
    const int wid  = tid >> 5;
    const int lane = tid & 31;
    const int wm = wid >> 1;           // 0..1 (32 rows each)
    const int wn = wid & 1;            // 0..1 (64 cols each)
    const int bm = blockIdx.y * G2_BM;
    const int bn = blockIdx.x * G2_BN;
    const int NC = K >> 6;

    const int r0   = tid >> 3;          // 0..15
    const int c16  = tid & 7;
    const uint32_t offLd = (uint32_t)(r0 * 128 + ((c16 ^ (r0 & 7)) * 16));
    const __half* apg = A + (long)(bm + r0) * lda + c16 * 8;
    const __half* bpg = Bh + (long)(bn + r0) * ldb + c16 * 8;
    const long strideA = (long)16 * lda;
    const long strideB = (long)16 * ldb;

    auto load_chunk = [&](int kc, int st) {
        const uint32_t sa = sbase + st * G2_STG_BYTES + offLd;
        const uint32_t sb = sa + G2_STG_A;
        const __half* ap = apg + kc * 64;
        const __half* bp = bpg + kc * 64;
        #pragma unroll
        for (int i = 0; i < 4; ++i) { CP_ASYNC16(sa + i * 2048, ap); ap += strideA; }  // A: 64 rows
        #pragma unroll
        for (int i = 0; i < 8; ++i) { CP_ASYNC16(sb + i * 2048, bp); bp += strideB; }  // B: 128 rows
    };

    float acc[2][8][4];
    #pragma unroll
    for (int i = 0; i < 2; i++)
        #pragma unroll
        for (int j = 0; j < 8; j++)
            #pragma unroll
            for (int x = 0; x < 4; x++) acc[i][j][x] = 0.f;

    load_chunk(0, 0); CP_COMMIT();
    load_chunk(1, 1); CP_COMMIT();

    const int lrow = lane & 15;
    const int lsel = lane >> 4;

    uint32_t a_row[2], b_row[4], ksel[4];
    #pragma unroll
    for (int mt = 0; mt < 2; ++mt) a_row[mt] = (uint32_t)(wm * 32 + mt * 16 + lrow) * 128;
    #pragma unroll
    for (int np = 0; np < 4; ++np) b_row[np] = (uint32_t)(wn * 64 + np * 16 + lrow) * 128;
    #pragma unroll
    for (int ks = 0; ks < 4; ++ks) ksel[ks] = (uint32_t)(((2 * ks + lsel) ^ (lrow & 7)) * 16);

    uint32_t af[2][2][4], bf[2][4][4];

    int st = 0, stl = 2;
    for (int c = 0; c < NC; ++c) {
        cp_wait<1>();
        __syncthreads();
        if (c + 2 < NC) load_chunk(c + 2, stl);
        CP_COMMIT();

        const uint32_t sa = sbase + st * G2_STG_BYTES;
        const uint32_t sb = sa + G2_STG_A;

        #pragma unroll
        for (int mt = 0; mt < 2; ++mt)
            LDSM_X4(af[0][mt][0], af[0][mt][1], af[0][mt][2], af[0][mt][3], sa + a_row[mt] + ksel[0]);
        #pragma unroll
        for (int np = 0; np < 4; ++np)
            LDSM_X4(bf[0][np][0], bf[0][np][1], bf[0][np][2], bf[0][np][3], sb + b_row[np] + ksel[0]);

        #pragma unroll
        for (int ks = 0; ks < 4; ++ks) {
            const int cur = ks & 1;
            const int nxt = cur ^ 1;
            if (ks < 3) {
                #pragma unroll
                for (int mt = 0; mt < 2; ++mt)
                    LDSM_X4(af[nxt][mt][0], af[nxt][mt][1], af[nxt][mt][2], af[nxt][mt][3],
                            sa + a_row[mt] + ksel[ks + 1]);
                #pragma unroll
                for (int np = 0; np < 4; ++np)
                    LDSM_X4(bf[nxt][np][0], bf[nxt][np][1], bf[nxt][np][2], bf[nxt][np][3],
                            sb + b_row[np] + ksel[ks + 1]);
            }
            #pragma unroll
            for (int mt = 0; mt < 2; ++mt) {
                #pragma unroll
                for (int np = 0; np < 4; ++np) {
                    MMA16816(acc[mt][2*np][0], acc[mt][2*np][1], acc[mt][2*np][2], acc[mt][2*np][3],
                             af[cur][mt][0], af[cur][mt][1], af[cur][mt][2], af[cur][mt][3],
                             bf[cur][np][0], bf[cur][np][2]);
                    MMA16816(acc[mt][2*np+1][0], acc[mt][2*np+1][1], acc[mt][2*np+1][2], acc[mt][2*np+1][3],
                             af[cur][mt][0], af[cur][mt][1], af[cur][mt][2], af[cur][mt][3],
                             bf[cur][np][1], bf[cur][np][3]);
                }
            }
        }
        if (++st == HG_STAGES) st = 0;
        if (++stl == HG_STAGES) stl = 0;
    }

    const int cq = (lane & 3) * 2;
    #pragma unroll
    for (int mt = 0; mt < 2; ++mt) {
        int r0e = bm + wm * 32 + mt * 16 + (lane >> 2);
        #pragma unroll
        for (int nt = 0; nt < 8; ++nt) {
            int col = bn + wn * 64 + nt * 8 + cq;
            *(float2*)&C[(long)r0e * ldc + col]       = make_float2(acc[mt][nt][0], acc[mt][nt][1]);
            *(float2*)&C[(long)(r0e + 8) * ldc + col] = make_float2(acc[mt][nt][2], acc[mt][nt][3]);
        }
    }
}

// ---------------------------------------------------------------------------
// Fused prep kernel (validated R16): f2h + W transposes + zeroing, one launch.
// ---------------------------------------------------------------------------
__global__ __launch_bounds__(256)
void prep_kernel(const float* __restrict__ feats,
                 const float* __restrict__ Wqkv,
                 const float* __restrict__ Wout)
{
    const int bid = blockIdx.x;
    const int tid = threadIdx.x;

    if (bid < 1024) {
        if (bid < 512)
            g_ctx[bid * 256 + tid] = 0.f;
        if (bid >= 512 && bid < 520)
            g_S[(bid - 512) * 256 + tid] = 0.f;
        long base = (long)bid * 2048 + tid;
        #pragma unroll
        for (int j = 0; j < 8; ++j) {
            long i = base + j * 256;
            float4 f = ((const float4*)feats)[i];
            ((__half2*)g_featsh)[2 * i]     = __floats2half2_rn(f.x, f.y);
            ((__half2*)g_featsh)[2 * i + 1] = __floats2half2_rn(f.z, f.w);
        }
    } else if (bid < 4096) {
        const int t = bid - 1024;
        const int n0 = (t % 96) * 32;
        const int k0 = (t / 96) * 32;
        __shared__ float tt[32][33];
        const int tx = tid & 31, ty = tid >> 5;
        #pragma unroll
        for (int j = 0; j < 4; ++j)
            tt[ty + 8 * j][tx] = Wqkv[(long)(k0 + ty + 8 * j) * QKV_COLS + n0 + tx];
        __syncthreads();
        #pragma unroll
        for (int j = 0; j < 4; ++j) {
            int n = n0 + ty + 8 * j;
            int row;
            if (n < 1024)       row = n;
            else if (n < 2048)  row = 1024 + ((n - 1024) >> 6) * 128 + ((n - 1024) & 63);
            else                row = 1024 + ((n - 2048) >> 6) * 128 + 64 + ((n - 2048) & 63);
            g_Wt[(long)row * DIM + k0 + tx] = __float2half_rn(tt[tx][ty + 8 * j]);
        }
    } else {
        const int t = bid - 4096;
        const int n0 = (t % 32) * 32;
        const int k0 = (t / 32) * 32;
        __shared__ float tt[32][33];
        const int tx = tid & 31, ty = tid >> 5;
        #pragma unroll
        for (int j = 0; j < 4; ++j)
            tt[ty + 8 * j][tx] = Wout[(long)(k0 + ty + 8 * j) * DIM + n0 + tx];
        __syncthreads();
        #pragma unroll
        for (int j = 0; j < 4; ++j)
            g_WoT[(long)(n0 + ty + 8 * j) * DIM + k0 + tx] = __float2half_rn(tt[tx][ty + 8 * j]);
    }
}

// ---------------------------------------------------------------------------
// HMMA make_M: Mh[b][n][h*64+d] = sum_d2 WoT[n][h*64+d2] * ctx[bh][d][d2]/S[d]
// grid (8 n-tiles of 128, 32 bh), 128 threads.
// ---------------------------------------------------------------------------
__global__ __launch_bounds__(128, 4)
void make_M_kernel()
{
    const int ntb = blockIdx.x;
    const int bh = blockIdx.y;
    const int b = bh >> 4;
    const int h = bh & 15;

    __shared__ __align__(16) char sm[16384 + 8192];
    const uint32_t sa = smem_u32(sm);
    const uint32_t sb = sa + 16384;

    const int tid = threadIdx.x;
    const int wid = tid >> 5;
    const int lane = tid & 31;

    {
        const int r = tid >> 3;
        const int c = tid & 7;
        const uint32_t off = (uint32_t)(r * 128 + ((c ^ (r & 7)) * 16));
        const __half* ap = g_WoT + (long)(ntb * 128 + r) * DIM + h * 64 + c * 8;
        #pragma unroll
        for (int i = 0; i < 8; ++i) {
            CP_ASYNC16(sa + off + i * 2048, ap);
            ap += (long)16 * DIM;
        }
        CP_COMMIT();
    }

    {
        const int d = tid >> 1;
        const int cb = (tid & 1) * 32;
        const float inv = 1.f / g_S[b * DIM + h * DHEAD + d];
        const float* cp = g_ctx + (long)bh * (DHEAD * DHEAD) + d * DHEAD + cb;
        __align__(16) __half hv[32];
        #pragma unroll
        for (int j = 0; j < 8; ++j) {
            float4 f = *(const float4*)(cp + j * 4);
            hv[j*4+0] = __float2half_rn(f.x * inv);
            hv[j*4+1] = __float2half_rn(f.y * inv);
            hv[j*4+2] = __float2half_rn(f.z * inv);
            hv[j*4+3] = __float2half_rn(f.w * inv);
        }
        #pragma unroll
        for (int j = 0; j < 4; ++j)
            *(uint4*)(sm + 16384 + SWZ((uint32_t)(d * 128 + cb * 2 + j * 16))) = ((const uint4*)hv)[j];
    }
    cp_wait<0>();
    __syncthreads();

    const int lrow = lane & 15;
    const int lsel = lane >> 4;

    uint32_t a_row[2], b_row[4], ksel[4];
    #pragma unroll
    for (int mt = 0; mt < 2; ++mt) a_row[mt] = (uint32_t)(wid * 32 + mt * 16 + lrow) * 128;
    #pragma unroll
    for (int np = 0; np < 4; ++np) b_row[np] = (uint32_t)(np * 16 + lrow) * 128;
    #pragma unroll
    for (int ks = 0; ks < 4; ++ks) ksel[ks] = (uint32_t)(((2 * ks + lsel) ^ (lrow & 7)) * 16);

    float acc[2][8][4];
    #pragma unroll
    for (int i = 0; i < 2; i++)
        #pragma unroll
        for (int j = 0; j < 8; j++)
            #pragma unroll
            for (int x = 0; x < 4; x++) acc[i][j][x] = 0.f;

    #pragma unroll
    for (int ks = 0; ks < 4; ++ks) {
        uint32_t af[2][4], bf[4][4];
        #pragma unroll
        for (int mt = 0; mt < 2; ++mt)
            LDSM_X4(af[mt][0], af[mt][1], af[mt][2], af[mt][3], sa + a_row[mt] + ksel[ks]);
        #pragma unroll
        for (int np = 0; np < 4; ++np)
            LDSM_X4(bf[np][0], bf[np][1], bf[np][2], bf[np][3], sb + b_row[np] + ksel[ks]);
        #pragma unroll
        for (int mt = 0; mt < 2; ++mt) {
            #pragma unroll
            for (int np = 0; np < 4; ++np) {
                MMA16816(acc[mt][2*np][0], acc[mt][2*np][1], acc[mt][2*np][2], acc[mt][2*np][3],
                         af[mt][0], af[mt][1], af[mt][2], af[mt][3],
                         bf[np][0], bf[np][2]);
                MMA16816(acc[mt][2*np+1][0], acc[mt][2*np+1][1], acc[mt][2*np+1][2], acc[mt][2*np+1][3],
                         af[mt][0], af[mt][1], af[mt][2], af[mt][3],
                         bf[np][1], bf[np][3]);
            }
        }
    }

    const int cq = (lane & 3) * 2;
    __half* mp = g_Mh + (long)b * DIM * DIM;
    #pragma unroll
    for (int mt = 0; mt < 2; ++mt) {
        int row = ntb * 128 + wid * 32 + mt * 16 + (lane >> 2);
        #pragma unroll
        for (int nt = 0; nt < 8; ++nt) {
            int col = h * 64 + nt * 8 + cq;
            *(__half2*)&mp[(long)row * DIM + col]       = __floats2half2_rn(acc[mt][nt][0], acc[mt][nt][1]);
            *(__half2*)&mp[(long)(row + 8) * DIM + col] = __floats2half2_rn(acc[mt][nt][2], acc[mt][nt][3]);
        }
    }
}

// ---------------------------------------------------------------------------
// Launch
// ---------------------------------------------------------------------------
extern "C" void kernel_launch(void* const* d_in, const int* in_sizes, int n_in,
                              void* d_out, int out_size)
{
    const float* feats = (const float*)d_in[0];
    const float* W_qkv = (const float*)d_in[1];
    const float* W_out = (const float*)d_in[2];
    float* out = (float*)d_out;

    cudaFuncSetAttribute(hgemm_qkv_kernel, cudaFuncAttributeMaxDynamicSharedMemorySize, HG_SMEM);
    cudaFuncSetAttribute(hgemm2_kernel, cudaFuncAttributeMaxDynamicSharedMemorySize, G2_SMEM);

    __half* featsh; cudaGetSymbolAddress((void**)&featsh, g_featsh);
    __half* Wt;     cudaGetSymbolAddress((void**)&Wt, g_Wt);
    __half* qh;     cudaGetSymbolAddress((void**)&qh, g_qh);
    __half* Mh;     cudaGetSymbolAddress((void**)&Mh, g_Mh);

    // 0) fused prep
    prep_kernel<<<5120, 256>>>(feats, W_qkv, W_out);

    // 1) fused qkv GEMM (q softmax + in-epilogue ctx partials -> atomic g_ctx)
    hgemm_qkv_kernel<<<dim3(QKV_COLS / HG_BN, M_ROWS / HG_BM, 1), 128, HG_SMEM>>>(
        featsh, Wt, DIM, DIM, DIM);

    // 2) M_b^T fp16 (HMMA)
    make_M_kernel<<<dim3(8, 32), 128>>>();

    // 3) out = q' @ M_b  (64x128 tiles, 3 CTAs/SM)
    hgemm2_kernel<<<dim3(DIM / G2_BN, N_SEQ / G2_BM, B), 128, G2_SMEM>>>(
        qh, Mh, out, DIM, DIM, DIM, DIM,
        (long)N_SEQ * DIM, (long)DIM * DIM, (long)N_SEQ * DIM);
}